// round 1
// baseline (speedup 1.0000x reference)
#include <cuda_runtime.h>
#include <cuda_bf16.h>
#include <math.h>

// ---------------- problem constants ----------------
#define NN 50000
#define EE 600000
#define HID 128
#define HEADS 4
#define HD 32
#define NEG_SLOPE 0.2f
#define LN_EPS 1e-5f

// ---------------- scratch (static device arrays; no allocation) ----------------
__device__ float g_fs[NN * HID];      // h @ W_src + b_src
__device__ float g_fd[NN * HID];      // h @ W_dst + b_dst
__device__ float g_a[EE * HEADS];     // exp(logit) per edge/head
__device__ float g_denom[NN * HEADS]; // segment sum of exp(logit)
__device__ float g_rst[NN * HID];     // aggregated messages
__device__ float g_h1[NN * HID];      // LN1 output
__device__ float g_t[NN * 2 * HID];   // gelu(h1@W1+bf1)
__device__ float g_z[NN * HID];       // t@W2 + bf2

// ---------------- helpers ----------------
__global__ void zero_kernel(float* __restrict__ p, int n) {
    int i = blockIdx.x * blockDim.x + threadIdx.x;
    if (i < n) p[i] = 0.0f;
}

// ---------------- GEMM core: BM=64, BN=128, 256 threads, 4x8 per-thread tile ----
// A: [n_rows, K] row-major. B: column tile (128 wide) with row stride ldb.
// C: row stride ldc, column offset ccol0. Bias for this column tile.
template <int K, bool GELU>
__device__ __forceinline__ void gemm_core(
    const float* __restrict__ A, const float* __restrict__ B, int ldb,
    const float* __restrict__ bias, float* __restrict__ C, int ldc, int ccol0)
{
    extern __shared__ float smem[];
    float* Bs = smem;                 // K * 128 floats
    float* As = smem + K * 128;       // K * 68 floats (transposed, padded)

    const int tid = threadIdx.x;
    const int tm = tid & 15;          // 16 thread rows * 4 = 64 tile rows
    const int tn = tid >> 4;          // 16 thread cols * 8 = 128 tile cols
    const int m0 = blockIdx.x * 64;

    // load B tile (K x 128), float4 vectorized
    #pragma unroll 4
    for (int i = tid; i < K * 32; i += 256) {
        int k = i >> 5, c4 = i & 31;
        float4 v = *reinterpret_cast<const float4*>(B + (size_t)k * ldb + c4 * 4);
        reinterpret_cast<float4*>(Bs + k * 128)[c4] = v;
    }
    // load A tile transposed: As[k][r] = A[m0+r][k]
    constexpr int KQ = K / 4;
    #pragma unroll 4
    for (int i = tid; i < 64 * KQ; i += 256) {
        int r = i / KQ, kq = i % KQ;
        int row = m0 + r;
        float4 v = make_float4(0.f, 0.f, 0.f, 0.f);
        if (row < NN) v = *reinterpret_cast<const float4*>(A + (size_t)row * K + kq * 4);
        int k = kq * 4;
        As[(k + 0) * 68 + r] = v.x;
        As[(k + 1) * 68 + r] = v.y;
        As[(k + 2) * 68 + r] = v.z;
        As[(k + 3) * 68 + r] = v.w;
    }
    __syncthreads();

    float acc[4][8];
    #pragma unroll
    for (int i = 0; i < 4; i++)
        #pragma unroll
        for (int j = 0; j < 8; j++) acc[i][j] = 0.0f;

    #pragma unroll 8
    for (int k = 0; k < K; k++) {
        float4 a4 = *reinterpret_cast<const float4*>(As + k * 68 + tm * 4);
        float4 b0 = *reinterpret_cast<const float4*>(Bs + k * 128 + tn * 8);
        float4 b1 = *reinterpret_cast<const float4*>(Bs + k * 128 + tn * 8 + 4);
        float av[4] = {a4.x, a4.y, a4.z, a4.w};
        float bv[8] = {b0.x, b0.y, b0.z, b0.w, b1.x, b1.y, b1.z, b1.w};
        #pragma unroll
        for (int i = 0; i < 4; i++)
            #pragma unroll
            for (int j = 0; j < 8; j++)
                acc[i][j] += av[i] * bv[j];
    }

    float4 ba = *reinterpret_cast<const float4*>(bias + tn * 8);
    float4 bb = *reinterpret_cast<const float4*>(bias + tn * 8 + 4);
    float bs[8] = {ba.x, ba.y, ba.z, ba.w, bb.x, bb.y, bb.z, bb.w};

    #pragma unroll
    for (int i = 0; i < 4; i++) {
        int row = m0 + tm * 4 + i;
        if (row >= NN) continue;
        float o[8];
        #pragma unroll
        for (int j = 0; j < 8; j++) {
            float c = acc[i][j] + bs[j];
            if (GELU) c = 0.5f * c * (1.0f + erff(c * 0.70710678118654752f));
            o[j] = c;
        }
        float* cp = C + (size_t)row * ldc + ccol0 + tn * 8;
        *reinterpret_cast<float4*>(cp)     = make_float4(o[0], o[1], o[2], o[3]);
        *reinterpret_cast<float4*>(cp + 4) = make_float4(o[4], o[5], o[6], o[7]);
    }
}

__global__ __launch_bounds__(256) void gemm_srcdst(
    const float* __restrict__ h,
    const float* __restrict__ Wsrc, const float* __restrict__ bsrc,
    const float* __restrict__ Wdst, const float* __restrict__ bdst,
    float* __restrict__ fs, float* __restrict__ fd)
{
    if (blockIdx.y == 0) gemm_core<128, false>(h, Wsrc, 128, bsrc, fs, 128, 0);
    else                 gemm_core<128, false>(h, Wdst, 128, bdst, fd, 128, 0);
}

__global__ __launch_bounds__(256) void gemm_ffn1(
    const float* __restrict__ h1, const float* __restrict__ W1,
    const float* __restrict__ bf1, float* __restrict__ t)
{
    int y = blockIdx.y;  // 0 or 1: which 128-col slice of the 256 outputs
    gemm_core<128, true>(h1, W1 + y * 128, 256, bf1 + y * 128, t, 256, y * 128);
}

__global__ __launch_bounds__(256) void gemm_ffn2(
    const float* __restrict__ t, const float* __restrict__ W2,
    const float* __restrict__ bf2, float* __restrict__ z)
{
    gemm_core<256, false>(t, W2, 128, bf2, z, 128, 0);
}

// ---------------- edge pass 1: logits -> exp -> denom ----------------
// One warp per edge. Lane l owns float4 chunk l (head = l>>3).
// No max-subtraction: |logit| is O(1) by construction (attn scaled 1/sqrt(128)),
// and softmax is shift-invariant, so result matches the reference.
__global__ __launch_bounds__(256) void edge_p1(
    const float* __restrict__ fs, const float* __restrict__ fd,
    const int* __restrict__ src, const int* __restrict__ dst,
    const float* __restrict__ attn,
    float* __restrict__ a_out, float* __restrict__ denom)
{
    int e = blockIdx.x * 8 + (threadIdx.x >> 5);
    if (e >= EE) return;
    int lane = threadIdx.x & 31;
    int s = src[e], d = dst[e];

    float4 vs = reinterpret_cast<const float4*>(fs)[(size_t)s * 32 + lane];
    float4 vd = reinterpret_cast<const float4*>(fd)[(size_t)d * 32 + lane];
    float4 va = reinterpret_cast<const float4*>(attn)[lane];

    float x, sum = 0.0f;
    x = vs.x + vd.x; x = (x > 0.f) ? x : NEG_SLOPE * x; sum += x * va.x;
    x = vs.y + vd.y; x = (x > 0.f) ? x : NEG_SLOPE * x; sum += x * va.y;
    x = vs.z + vd.z; x = (x > 0.f) ? x : NEG_SLOPE * x; sum += x * va.z;
    x = vs.w + vd.w; x = (x > 0.f) ? x : NEG_SLOPE * x; sum += x * va.w;

    // reduce within each 8-lane (per-head) group
    sum += __shfl_xor_sync(0xffffffffu, sum, 4);
    sum += __shfl_xor_sync(0xffffffffu, sum, 2);
    sum += __shfl_xor_sync(0xffffffffu, sum, 1);

    if ((lane & 7) == 0) {
        int hh = lane >> 3;
        float a = expf(sum);
        a_out[(size_t)e * 4 + hh] = a;
        atomicAdd(&denom[(size_t)d * 4 + hh], a);
    }
}

// ---------------- edge pass 2: alpha-weighted aggregation ----------------
__global__ __launch_bounds__(256) void edge_p2(
    const float* __restrict__ fs,
    const int* __restrict__ src, const int* __restrict__ dst,
    const float* __restrict__ a_in, const float* __restrict__ denom,
    float* __restrict__ rst)
{
    int e = blockIdx.x * 8 + (threadIdx.x >> 5);
    if (e >= EE) return;
    int lane = threadIdx.x & 31;
    int s = src[e], d = dst[e];
    int hh = lane >> 3;

    float alpha = a_in[(size_t)e * 4 + hh] / denom[(size_t)d * 4 + hh];
    float4 f = reinterpret_cast<const float4*>(fs)[(size_t)s * 32 + lane];
    f.x *= alpha; f.y *= alpha; f.z *= alpha; f.w *= alpha;

    float* p = rst + (size_t)d * HID + lane * 4;
    asm volatile("red.global.add.v4.f32 [%0], {%1,%2,%3,%4};"
                 :: "l"(p), "f"(f.x), "f"(f.y), "f"(f.z), "f"(f.w)
                 : "memory");
}

// ---------------- LayerNorm(x + resid): one warp per row ----------------
__global__ __launch_bounds__(256) void ln_kernel(
    const float* __restrict__ x, const float* __restrict__ resid,
    const float* __restrict__ g, const float* __restrict__ b,
    float* __restrict__ out)
{
    int row = blockIdx.x * 8 + (threadIdx.x >> 5);
    if (row >= NN) return;
    int lane = threadIdx.x & 31;

    float4 v = reinterpret_cast<const float4*>(x)[(size_t)row * 32 + lane];
    float4 r = reinterpret_cast<const float4*>(resid)[(size_t)row * 32 + lane];
    v.x += r.x; v.y += r.y; v.z += r.z; v.w += r.w;

    float s1 = v.x + v.y + v.z + v.w;
    float s2 = v.x * v.x + v.y * v.y + v.z * v.z + v.w * v.w;
    #pragma unroll
    for (int off = 16; off > 0; off >>= 1) {
        s1 += __shfl_xor_sync(0xffffffffu, s1, off);
        s2 += __shfl_xor_sync(0xffffffffu, s2, off);
    }
    float mu = s1 * (1.0f / HID);
    float var = s2 * (1.0f / HID) - mu * mu;
    float rstd = rsqrtf(var + LN_EPS);

    float4 gg = reinterpret_cast<const float4*>(g)[lane];
    float4 bb = reinterpret_cast<const float4*>(b)[lane];
    float4 o;
    o.x = (v.x - mu) * rstd * gg.x + bb.x;
    o.y = (v.y - mu) * rstd * gg.y + bb.y;
    o.z = (v.z - mu) * rstd * gg.z + bb.z;
    o.w = (v.w - mu) * rstd * gg.w + bb.w;
    reinterpret_cast<float4*>(out)[(size_t)row * 32 + lane] = o;
}

// ---------------- launcher ----------------
extern "C" void kernel_launch(void* const* d_in, const int* in_sizes, int n_in,
                              void* d_out, int out_size)
{
    const float* h    = (const float*)d_in[0];
    const int*   src  = (const int*)  d_in[1];
    const int*   dst  = (const int*)  d_in[2];
    const float* Wsrc = (const float*)d_in[3];
    const float* bsrc = (const float*)d_in[4];
    const float* Wdst = (const float*)d_in[5];
    const float* bdst = (const float*)d_in[6];
    const float* attn = (const float*)d_in[7];
    const float* W1   = (const float*)d_in[8];
    const float* bf1  = (const float*)d_in[9];
    const float* W2   = (const float*)d_in[10];
    const float* bf2  = (const float*)d_in[11];
    const float* g1   = (const float*)d_in[12];
    const float* be1  = (const float*)d_in[13];
    const float* g2   = (const float*)d_in[14];
    const float* be2  = (const float*)d_in[15];
    float* out = (float*)d_out;

    float *fs, *fd, *aexp, *denom, *rst, *h1, *t, *z;
    cudaGetSymbolAddress((void**)&fs,    g_fs);
    cudaGetSymbolAddress((void**)&fd,    g_fd);
    cudaGetSymbolAddress((void**)&aexp,  g_a);
    cudaGetSymbolAddress((void**)&denom, g_denom);
    cudaGetSymbolAddress((void**)&rst,   g_rst);
    cudaGetSymbolAddress((void**)&h1,    g_h1);
    cudaGetSymbolAddress((void**)&t,     g_t);
    cudaGetSymbolAddress((void**)&z,     g_z);

    const int SMEM_K128 = (128 * 128 + 128 * 68) * 4;  // 100352
    const int SMEM_K256 = (256 * 128 + 256 * 68) * 4;  // 200704
    cudaFuncSetAttribute(gemm_srcdst, cudaFuncAttributeMaxDynamicSharedMemorySize, SMEM_K128);
    cudaFuncSetAttribute(gemm_ffn1,   cudaFuncAttributeMaxDynamicSharedMemorySize, SMEM_K128);
    cudaFuncSetAttribute(gemm_ffn2,   cudaFuncAttributeMaxDynamicSharedMemorySize, SMEM_K256);

    zero_kernel<<<(NN * HEADS + 255) / 256, 256>>>(denom, NN * HEADS);
    zero_kernel<<<(NN * HID + 255) / 256, 256>>>(rst, NN * HID);

    dim3 gdual((NN + 63) / 64, 2);
    gemm_srcdst<<<gdual, 256, SMEM_K128>>>(h, Wsrc, bsrc, Wdst, bdst, fs, fd);

    int eblocks = (EE + 7) / 8;
    edge_p1<<<eblocks, 256>>>(fs, fd, src, dst, attn, aexp, denom);
    edge_p2<<<eblocks, 256>>>(fs, src, dst, aexp, denom, rst);

    int lblocks = (NN + 7) / 8;
    ln_kernel<<<lblocks, 256>>>(rst, h, g1, be1, h1);

    gemm_ffn1<<<gdual, 256, SMEM_K128>>>(h1, W1, bf1, t);

    dim3 gffn2((NN + 63) / 64, 1);
    gemm_ffn2<<<gffn2, 256, SMEM_K256>>>(t, W2, bf2, z);

    ln_kernel<<<lblocks, 256>>>(z, h1, g2, be2, out);
}

// round 3
// speedup vs baseline: 1.2342x; 1.2342x over previous
#include <cuda_runtime.h>
#include <cuda_bf16.h>
#include <math.h>

// ---------------- problem constants ----------------
#define NN 50000
#define EE 600000
#define HID 128
#define HEADS 4
#define NEG_SLOPE 0.2f
#define LN_EPS 1e-5f

typedef unsigned long long u64;

// ---------------- scratch ----------------
__device__ float g_fs[NN * HID];      // h @ W_src + b_src
__device__ float g_fd[NN * HID];      // h @ W_dst + b_dst
__device__ float g_denom[NN * HEADS]; // segment sum of exp(logit)
__device__ float g_rst[NN * HID];     // unnormalized aggregated messages
__device__ float g_h1[NN * HID];      // LN1 output
__device__ float g_t[NN * 2 * HID];   // gelu(h1@W1+bf1)
__device__ float g_z[NN * HID];       // t@W2 + bf2

// ---------------- packed f32x2 helpers ----------------
__device__ __forceinline__ u64 pack2_dup(float x) {
    unsigned int b = __float_as_uint(x);
    u64 r;
    asm("mov.b64 %0, {%1, %1};" : "=l"(r) : "r"(b));
    return r;
}
__device__ __forceinline__ u64 ffma2(u64 a, u64 b, u64 c) {
    u64 d;
    asm("fma.rn.f32x2 %0, %1, %2, %3;" : "=l"(d) : "l"(a), "l"(b), "l"(c));
    return d;
}
__device__ __forceinline__ void unpack2(u64 v, float& lo, float& hi) {
    unsigned int l, h;
    asm("mov.b64 {%0, %1}, %2;" : "=r"(l), "=r"(h) : "l"(v));
    lo = __uint_as_float(l);
    hi = __uint_as_float(h);
}

// ---------------- GEMM core: BM=64, BN=128, 256 threads, 4x8 tile, FFMA2 ----
// A: [n_rows, K] row-major. B: 128-wide column tile, row stride ldb.
template <int K, bool GELU>
__device__ __forceinline__ void gemm_core(
    const float* __restrict__ A, const float* __restrict__ B, int ldb,
    const float* __restrict__ bias, float* __restrict__ C, int ldc, int ccol0)
{
    extern __shared__ float smem[];
    float* Bs = smem;                 // K * 128
    float* As = smem + K * 128;       // K * 68 (transposed, padded)

    const int tid = threadIdx.x;
    const int tm = tid & 15;          // 16 x 4 = 64 rows
    const int tn = tid >> 4;          // 16 x 8 = 128 cols
    const int m0 = blockIdx.x * 64;

    #pragma unroll 4
    for (int i = tid; i < K * 32; i += 256) {
        int k = i >> 5, c4 = i & 31;
        float4 v = *reinterpret_cast<const float4*>(B + (size_t)k * ldb + c4 * 4);
        reinterpret_cast<float4*>(Bs + k * 128)[c4] = v;
    }
    constexpr int KQ = K / 4;
    #pragma unroll 4
    for (int i = tid; i < 64 * KQ; i += 256) {
        int r = i / KQ, kq = i % KQ;
        int row = m0 + r;
        float4 v = make_float4(0.f, 0.f, 0.f, 0.f);
        if (row < NN) v = *reinterpret_cast<const float4*>(A + (size_t)row * K + kq * 4);
        int k = kq * 4;
        As[(k + 0) * 68 + r] = v.x;
        As[(k + 1) * 68 + r] = v.y;
        As[(k + 2) * 68 + r] = v.z;
        As[(k + 3) * 68 + r] = v.w;
    }
    __syncthreads();

    // packed accumulators: acc[i][j] covers cols (2j, 2j+1)
    u64 acc[4][4];
    #pragma unroll
    for (int i = 0; i < 4; i++)
        #pragma unroll
        for (int j = 0; j < 4; j++) acc[i][j] = 0ull;  // (0.0f, 0.0f)

    #pragma unroll 8
    for (int k = 0; k < K; k++) {
        float4 a4 = *reinterpret_cast<const float4*>(As + k * 68 + tm * 4);
        const ulonglong2* bp = reinterpret_cast<const ulonglong2*>(Bs + k * 128 + tn * 8);
        ulonglong2 bq0 = bp[0];
        ulonglong2 bq1 = bp[1];
        u64 bv[4] = {bq0.x, bq0.y, bq1.x, bq1.y};
        u64 aa[4] = {pack2_dup(a4.x), pack2_dup(a4.y), pack2_dup(a4.z), pack2_dup(a4.w)};
        #pragma unroll
        for (int i = 0; i < 4; i++)
            #pragma unroll
            for (int j = 0; j < 4; j++)
                acc[i][j] = ffma2(aa[i], bv[j], acc[i][j]);
    }

    float4 ba = *reinterpret_cast<const float4*>(bias + tn * 8);
    float4 bb = *reinterpret_cast<const float4*>(bias + tn * 8 + 4);
    float bs[8] = {ba.x, ba.y, ba.z, ba.w, bb.x, bb.y, bb.z, bb.w};

    #pragma unroll
    for (int i = 0; i < 4; i++) {
        int row = m0 + tm * 4 + i;
        if (row >= NN) continue;
        float o[8];
        #pragma unroll
        for (int j = 0; j < 4; j++) {
            float c0, c1;
            unpack2(acc[i][j], c0, c1);
            o[2 * j]     = c0 + bs[2 * j];
            o[2 * j + 1] = c1 + bs[2 * j + 1];
        }
        if (GELU) {
            #pragma unroll
            for (int j = 0; j < 8; j++)
                o[j] = 0.5f * o[j] * (1.0f + erff(o[j] * 0.70710678118654752f));
        }
        float* cp = C + (size_t)row * ldc + ccol0 + tn * 8;
        *reinterpret_cast<float4*>(cp)     = make_float4(o[0], o[1], o[2], o[3]);
        *reinterpret_cast<float4*>(cp + 4) = make_float4(o[4], o[5], o[6], o[7]);
    }
}

__global__ __launch_bounds__(256) void gemm_srcdst(
    const float* __restrict__ h,
    const float* __restrict__ Wsrc, const float* __restrict__ bsrc,
    const float* __restrict__ Wdst, const float* __restrict__ bdst,
    float* __restrict__ fs, float* __restrict__ fd)
{
    if (blockIdx.y == 0) gemm_core<128, false>(h, Wsrc, 128, bsrc, fs, 128, 0);
    else                 gemm_core<128, false>(h, Wdst, 128, bdst, fd, 128, 0);
}

__global__ __launch_bounds__(256) void gemm_ffn1(
    const float* __restrict__ h1, const float* __restrict__ W1,
    const float* __restrict__ bf1, float* __restrict__ t)
{
    int y = blockIdx.y;
    gemm_core<128, true>(h1, W1 + y * 128, 256, bf1 + y * 128, t, 256, y * 128);
}

__global__ __launch_bounds__(256) void gemm_ffn2(
    const float* __restrict__ t, const float* __restrict__ W2,
    const float* __restrict__ bf2, float* __restrict__ z)
{
    gemm_core<256, false>(t, W2, 128, bf2, z, 128, 0);
}

// ---------------- fused edge pass ----------------
// One warp per edge. Accumulates UNNORMALIZED numerator (a * fs[src]) into rst
// and a into denom; normalization happens per-node in ln1_kernel. Softmax max-
// subtraction dropped: logits are O(1) by construction and softmax is shift-
// invariant, so results match the reference.
__global__ __launch_bounds__(256) void edge_fused(
    const float* __restrict__ fs, const float* __restrict__ fd,
    const int* __restrict__ src, const int* __restrict__ dst,
    const float* __restrict__ attn,
    float* __restrict__ denom, float* __restrict__ rst)
{
    int e = blockIdx.x * 8 + (threadIdx.x >> 5);
    if (e >= EE) return;
    int lane = threadIdx.x & 31;

    float4 va = reinterpret_cast<const float4*>(attn)[lane];  // L1-resident
    int s = __ldg(src + e), d = __ldg(dst + e);

    float4 vs = reinterpret_cast<const float4*>(fs)[(size_t)s * 32 + lane];
    float4 vd = reinterpret_cast<const float4*>(fd)[(size_t)d * 32 + lane];

    float x, sum = 0.0f;
    x = vs.x + vd.x; x = (x > 0.f) ? x : NEG_SLOPE * x; sum += x * va.x;
    x = vs.y + vd.y; x = (x > 0.f) ? x : NEG_SLOPE * x; sum += x * va.y;
    x = vs.z + vd.z; x = (x > 0.f) ? x : NEG_SLOPE * x; sum += x * va.z;
    x = vs.w + vd.w; x = (x > 0.f) ? x : NEG_SLOPE * x; sum += x * va.w;

    // butterfly reduce within each 8-lane head group -> all 8 lanes hold the sum
    sum += __shfl_xor_sync(0xffffffffu, sum, 4);
    sum += __shfl_xor_sync(0xffffffffu, sum, 2);
    sum += __shfl_xor_sync(0xffffffffu, sum, 1);

    float a = expf(sum);

    if ((lane & 7) == 0)
        atomicAdd(&denom[(size_t)d * 4 + (lane >> 3)], a);

    float4 m;
    m.x = vs.x * a; m.y = vs.y * a; m.z = vs.z * a; m.w = vs.w * a;
    float* p = rst + (size_t)d * HID + lane * 4;
    asm volatile("red.global.add.v4.f32 [%0], {%1,%2,%3,%4};"
                 :: "l"(p), "f"(m.x), "f"(m.y), "f"(m.z), "f"(m.w)
                 : "memory");
}

// ---------------- LN1: normalize rst by denom, add residual, LayerNorm ----
__global__ __launch_bounds__(256) void ln1_kernel(
    const float* __restrict__ rst, const float* __restrict__ denom,
    const float* __restrict__ resid,
    const float* __restrict__ g, const float* __restrict__ b,
    float* __restrict__ out)
{
    int row = blockIdx.x * 8 + (threadIdx.x >> 5);
    if (row >= NN) return;
    int lane = threadIdx.x & 31;

    float den = denom[(size_t)row * 4 + (lane >> 3)];
    den = (den == 0.0f) ? 1.0f : den;
    float inv = 1.0f / den;

    float4 v = reinterpret_cast<const float4*>(rst)[(size_t)row * 32 + lane];
    float4 r = reinterpret_cast<const float4*>(resid)[(size_t)row * 32 + lane];
    v.x = v.x * inv + r.x; v.y = v.y * inv + r.y;
    v.z = v.z * inv + r.z; v.w = v.w * inv + r.w;

    float s1 = v.x + v.y + v.z + v.w;
    float s2 = v.x * v.x + v.y * v.y + v.z * v.z + v.w * v.w;
    #pragma unroll
    for (int off = 16; off > 0; off >>= 1) {
        s1 += __shfl_xor_sync(0xffffffffu, s1, off);
        s2 += __shfl_xor_sync(0xffffffffu, s2, off);
    }
    float mu = s1 * (1.0f / HID);
    float var = s2 * (1.0f / HID) - mu * mu;
    float rstd = rsqrtf(var + LN_EPS);

    float4 gg = reinterpret_cast<const float4*>(g)[lane];
    float4 bb = reinterpret_cast<const float4*>(b)[lane];
    float4 o;
    o.x = (v.x - mu) * rstd * gg.x + bb.x;
    o.y = (v.y - mu) * rstd * gg.y + bb.y;
    o.z = (v.z - mu) * rstd * gg.z + bb.z;
    o.w = (v.w - mu) * rstd * gg.w + bb.w;
    reinterpret_cast<float4*>(out)[(size_t)row * 32 + lane] = o;
}

// ---------------- LN2: plain residual LayerNorm ----------------
__global__ __launch_bounds__(256) void ln2_kernel(
    const float* __restrict__ x, const float* __restrict__ resid,
    const float* __restrict__ g, const float* __restrict__ b,
    float* __restrict__ out)
{
    int row = blockIdx.x * 8 + (threadIdx.x >> 5);
    if (row >= NN) return;
    int lane = threadIdx.x & 31;

    float4 v = reinterpret_cast<const float4*>(x)[(size_t)row * 32 + lane];
    float4 r = reinterpret_cast<const float4*>(resid)[(size_t)row * 32 + lane];
    v.x += r.x; v.y += r.y; v.z += r.z; v.w += r.w;

    float s1 = v.x + v.y + v.z + v.w;
    float s2 = v.x * v.x + v.y * v.y + v.z * v.z + v.w * v.w;
    #pragma unroll
    for (int off = 16; off > 0; off >>= 1) {
        s1 += __shfl_xor_sync(0xffffffffu, s1, off);
        s2 += __shfl_xor_sync(0xffffffffu, s2, off);
    }
    float mu = s1 * (1.0f / HID);
    float var = s2 * (1.0f / HID) - mu * mu;
    float rstd = rsqrtf(var + LN_EPS);

    float4 gg = reinterpret_cast<const float4*>(g)[lane];
    float4 bb = reinterpret_cast<const float4*>(b)[lane];
    float4 o;
    o.x = (v.x - mu) * rstd * gg.x + bb.x;
    o.y = (v.y - mu) * rstd * gg.y + bb.y;
    o.z = (v.z - mu) * rstd * gg.z + bb.z;
    o.w = (v.w - mu) * rstd * gg.w + bb.w;
    reinterpret_cast<float4*>(out)[(size_t)row * 32 + lane] = o;
}

// ---------------- launcher ----------------
extern "C" void kernel_launch(void* const* d_in, const int* in_sizes, int n_in,
                              void* d_out, int out_size)
{
    const float* h    = (const float*)d_in[0];
    const int*   src  = (const int*)  d_in[1];
    const int*   dst  = (const int*)  d_in[2];
    const float* Wsrc = (const float*)d_in[3];
    const float* bsrc = (const float*)d_in[4];
    const float* Wdst = (const float*)d_in[5];
    const float* bdst = (const float*)d_in[6];
    const float* attn = (const float*)d_in[7];
    const float* W1   = (const float*)d_in[8];
    const float* bf1  = (const float*)d_in[9];
    const float* W2   = (const float*)d_in[10];
    const float* bf2  = (const float*)d_in[11];
    const float* g1   = (const float*)d_in[12];
    const float* be1  = (const float*)d_in[13];
    const float* g2   = (const float*)d_in[14];
    const float* be2  = (const float*)d_in[15];
    float* out = (float*)d_out;

    float *fs, *fd, *denom, *rst, *h1, *t, *z;
    cudaGetSymbolAddress((void**)&fs,    g_fs);
    cudaGetSymbolAddress((void**)&fd,    g_fd);
    cudaGetSymbolAddress((void**)&denom, g_denom);
    cudaGetSymbolAddress((void**)&rst,   g_rst);
    cudaGetSymbolAddress((void**)&h1,    g_h1);
    cudaGetSymbolAddress((void**)&t,     g_t);
    cudaGetSymbolAddress((void**)&z,     g_z);

    const int SMEM_K128 = (128 * 128 + 128 * 68) * 4;  // 100352
    const int SMEM_K256 = (256 * 128 + 256 * 68) * 4;  // 200704
    cudaFuncSetAttribute(gemm_srcdst, cudaFuncAttributeMaxDynamicSharedMemorySize, SMEM_K128);
    cudaFuncSetAttribute(gemm_ffn1,   cudaFuncAttributeMaxDynamicSharedMemorySize, SMEM_K128);
    cudaFuncSetAttribute(gemm_ffn2,   cudaFuncAttributeMaxDynamicSharedMemorySize, SMEM_K256);

    cudaMemsetAsync(denom, 0, NN * HEADS * sizeof(float));
    cudaMemsetAsync(rst,   0, NN * HID * sizeof(float));

    dim3 gdual((NN + 63) / 64, 2);
    gemm_srcdst<<<gdual, 256, SMEM_K128>>>(h, Wsrc, bsrc, Wdst, bdst, fs, fd);

    int eblocks = (EE + 7) / 8;
    edge_fused<<<eblocks, 256>>>(fs, fd, src, dst, attn, denom, rst);

    int lblocks = (NN + 7) / 8;
    ln1_kernel<<<lblocks, 256>>>(rst, denom, h, g1, be1, h1);

    gemm_ffn1<<<gdual, 256, SMEM_K128>>>(h1, W1, bf1, t);

    dim3 gffn2((NN + 63) / 64, 1);
    gemm_ffn2<<<gffn2, 256, SMEM_K256>>>(t, W2, bf2, z);

    ln2_kernel<<<lblocks, 256>>>(z, h1, g2, be2, out);
}

// round 4
// speedup vs baseline: 1.3633x; 1.1046x over previous
#include <cuda_runtime.h>
#include <cuda_bf16.h>
#include <mma.h>
#include <math.h>

using namespace nvcuda;

// ---------------- problem constants ----------------
#define NN 50000
#define NPAD 50048            // 782 * 64 — GEMM tiles may write garbage rows < NPAD
#define EE 600000
#define HID 128
#define HEADS 4
#define NEG_SLOPE 0.2f
#define LN_EPS 1e-5f

// smem tile geometry (bf16 elements)
#define LDA_SM 144            // 128 + 16 pad
#define LDB_SM 80             // 64 + 16 pad
#define A_ELEMS (64 * LDA_SM)     // 9216
#define B_ELEMS (128 * LDB_SM)    // 10240
#define SM_BYTES (2 * (A_ELEMS + B_ELEMS) * 2 + 16 * 64 * 4)  // 81920

// ---------------- scratch (padded where GEMM writes) ----------------
__device__ float g_fs[NPAD * HID];
__device__ float g_fd[NPAD * HID];
__device__ float g_denom[NN * HEADS];
__device__ float g_rst[NN * HID];
__device__ float g_h1[NPAD * HID];
__device__ float g_t[NPAD * 2 * HID];
__device__ float g_z[NPAD * HID];

// ---------------- split-bf16 pack helper ----------------
__device__ __forceinline__ void split4(float4 v, unsigned int* hi2, unsigned int* lo2) {
    __nv_bfloat16 h0 = __float2bfloat16(v.x);
    __nv_bfloat16 h1 = __float2bfloat16(v.y);
    __nv_bfloat16 h2 = __float2bfloat16(v.z);
    __nv_bfloat16 h3 = __float2bfloat16(v.w);
    __nv_bfloat16 l0 = __float2bfloat16(v.x - __bfloat162float(h0));
    __nv_bfloat16 l1 = __float2bfloat16(v.y - __bfloat162float(h1));
    __nv_bfloat16 l2 = __float2bfloat16(v.z - __bfloat162float(h2));
    __nv_bfloat16 l3 = __float2bfloat16(v.w - __bfloat162float(h3));
    hi2[0] = (unsigned int)__bfloat16_as_ushort(h0) | ((unsigned int)__bfloat16_as_ushort(h1) << 16);
    hi2[1] = (unsigned int)__bfloat16_as_ushort(h2) | ((unsigned int)__bfloat16_as_ushort(h3) << 16);
    lo2[0] = (unsigned int)__bfloat16_as_ushort(l0) | ((unsigned int)__bfloat16_as_ushort(l1) << 16);
    lo2[1] = (unsigned int)__bfloat16_as_ushort(l2) | ((unsigned int)__bfloat16_as_ushort(l3) << 16);
}

// ---------------- WMMA split-bf16 GEMM core ----------------
// C[64x64 tile at (m0, ccol0)] = A[m0:m0+64, :KTOT] @ B[:, ccol0:ccol0+64] + bias
// A row-major lda, B row-major ldb. fp32 in/out; split-bf16 internally:
// A ~ Ah+Al, B ~ Bh+Bl; C = AhBh + AhBl + AlBh (AlBl ~ 2^-18, dropped).
template <int KTOT, bool GELU>
__device__ __forceinline__ void gemm_core(
    const float* __restrict__ A, int lda,
    const float* __restrict__ B, int ldb,
    const float* __restrict__ bias,
    float* __restrict__ C, int ldc, int ccol0, int m0)
{
    extern __shared__ __nv_bfloat16 sm[];
    __nv_bfloat16* Ah = sm;
    __nv_bfloat16* Al = sm + A_ELEMS;
    __nv_bfloat16* Bh = sm + 2 * A_ELEMS;
    __nv_bfloat16* Bl = sm + 2 * A_ELEMS + B_ELEMS;
    float* bias_sm = (float*)(sm + 2 * (A_ELEMS + B_ELEMS));  // [16][64]

    const int tid = threadIdx.x;
    const int wid = tid >> 5;
    const int warp_m = wid >> 2;      // 0..1 -> 32 rows each
    const int warp_n = wid & 3;       // 0..3 -> 16 cols each

    // bias tile: 16 identical rows of bias[ccol0 .. ccol0+63]
    for (int i = tid; i < 16 * 64; i += 256)
        bias_sm[i] = bias[ccol0 + (i & 63)];
    __syncthreads();

    wmma::fragment<wmma::accumulator, 16, 16, 16, float> acc[2];
    wmma::load_matrix_sync(acc[0], bias_sm + warp_n * 16, 64, wmma::mem_row_major);
    wmma::load_matrix_sync(acc[1], bias_sm + warp_n * 16, 64, wmma::mem_row_major);

    constexpr int KCHUNKS = KTOT / 128;
    for (int kc = 0; kc < KCHUNKS; kc++) {
        __syncthreads();
        // load + split A chunk: 64 rows x 128 cols
        #pragma unroll
        for (int i = tid; i < 64 * 32; i += 256) {
            int r = i >> 5, c4 = i & 31;
            int row = m0 + r;
            float4 v = make_float4(0.f, 0.f, 0.f, 0.f);
            if (row < NN) v = *reinterpret_cast<const float4*>(A + (size_t)row * lda + kc * 128 + c4 * 4);
            unsigned int hi2[2], lo2[2];
            split4(v, hi2, lo2);
            int off = r * LDA_SM + c4 * 4;
            *reinterpret_cast<uint2*>(Ah + off) = make_uint2(hi2[0], hi2[1]);
            *reinterpret_cast<uint2*>(Al + off) = make_uint2(lo2[0], lo2[1]);
        }
        // load + split B chunk: 128 rows (k) x 64 cols
        #pragma unroll
        for (int i = tid; i < 128 * 16; i += 256) {
            int r = i >> 4, c4 = i & 15;
            float4 v = *reinterpret_cast<const float4*>(B + (size_t)(kc * 128 + r) * ldb + ccol0 + c4 * 4);
            unsigned int hi2[2], lo2[2];
            split4(v, hi2, lo2);
            int off = r * LDB_SM + c4 * 4;
            *reinterpret_cast<uint2*>(Bh + off) = make_uint2(hi2[0], hi2[1]);
            *reinterpret_cast<uint2*>(Bl + off) = make_uint2(lo2[0], lo2[1]);
        }
        __syncthreads();

        #pragma unroll
        for (int kk = 0; kk < 8; kk++) {
            wmma::fragment<wmma::matrix_a, 16, 16, 16, __nv_bfloat16, wmma::row_major> ah0, ah1, al0, al1;
            wmma::fragment<wmma::matrix_b, 16, 16, 16, __nv_bfloat16, wmma::row_major> bh, bl;
            const __nv_bfloat16* ap = Ah + (warp_m * 32) * LDA_SM + kk * 16;
            const __nv_bfloat16* alp = Al + (warp_m * 32) * LDA_SM + kk * 16;
            wmma::load_matrix_sync(ah0, ap, LDA_SM);
            wmma::load_matrix_sync(ah1, ap + 16 * LDA_SM, LDA_SM);
            wmma::load_matrix_sync(al0, alp, LDA_SM);
            wmma::load_matrix_sync(al1, alp + 16 * LDA_SM, LDA_SM);
            wmma::load_matrix_sync(bh, Bh + (kk * 16) * LDB_SM + warp_n * 16, LDB_SM);
            wmma::load_matrix_sync(bl, Bl + (kk * 16) * LDB_SM + warp_n * 16, LDB_SM);

            wmma::mma_sync(acc[0], ah0, bh, acc[0]);
            wmma::mma_sync(acc[1], ah1, bh, acc[1]);
            wmma::mma_sync(acc[0], ah0, bl, acc[0]);
            wmma::mma_sync(acc[1], ah1, bl, acc[1]);
            wmma::mma_sync(acc[0], al0, bh, acc[0]);
            wmma::mma_sync(acc[1], al1, bh, acc[1]);
        }
    }

    if (GELU) {
        #pragma unroll
        for (int f = 0; f < 2; f++)
            #pragma unroll
            for (int i = 0; i < acc[f].num_elements; i++) {
                float x = acc[f].x[i];
                acc[f].x[i] = 0.5f * x * (1.0f + erff(x * 0.70710678118654752f));
            }
    }

    // rows beyond NN land in padded scratch (all GEMM outputs are padded)
    #pragma unroll
    for (int f = 0; f < 2; f++) {
        float* cp = C + (size_t)(m0 + warp_m * 32 + f * 16) * ldc + ccol0 + warp_n * 16;
        wmma::store_matrix_sync(cp, acc[f], ldc, wmma::mem_row_major);
    }
}

__global__ __launch_bounds__(256) void gemm_srcdst(
    const float* __restrict__ h,
    const float* __restrict__ Wsrc, const float* __restrict__ bsrc,
    const float* __restrict__ Wdst, const float* __restrict__ bdst,
    float* __restrict__ fs, float* __restrict__ fd)
{
    int m0 = blockIdx.x * 64;
    int y = blockIdx.y;              // 0,1 -> fs cols 0/64 ; 2,3 -> fd cols 0/64
    int col0 = (y & 1) * 64;
    if (y < 2) gemm_core<128, false>(h, 128, Wsrc, 128, bsrc, fs, 128, col0, m0);
    else       gemm_core<128, false>(h, 128, Wdst, 128, bdst, fd, 128, col0, m0);
}

__global__ __launch_bounds__(256) void gemm_ffn1(
    const float* __restrict__ h1, const float* __restrict__ W1,
    const float* __restrict__ bf1, float* __restrict__ t)
{
    gemm_core<128, true>(h1, 128, W1, 256, bf1, t, 256, blockIdx.y * 64, blockIdx.x * 64);
}

__global__ __launch_bounds__(256) void gemm_ffn2(
    const float* __restrict__ t, const float* __restrict__ W2,
    const float* __restrict__ bf2, float* __restrict__ z)
{
    gemm_core<256, false>(t, 256, W2, 128, bf2, z, 128, blockIdx.y * 64, blockIdx.x * 64);
}

// ---------------- fused edge pass ----------------
// One warp per edge; unnormalized numerator + denom in one sweep.
// Softmax max-subtraction dropped: logits O(1) by construction; shift-invariant.
__global__ __launch_bounds__(256) void edge_fused(
    const float* __restrict__ fs, const float* __restrict__ fd,
    const int* __restrict__ src, const int* __restrict__ dst,
    const float* __restrict__ attn,
    float* __restrict__ denom, float* __restrict__ rst)
{
    int e = blockIdx.x * 8 + (threadIdx.x >> 5);
    if (e >= EE) return;
    int lane = threadIdx.x & 31;

    float4 va = reinterpret_cast<const float4*>(attn)[lane];
    int s = __ldg(src + e), d = __ldg(dst + e);

    float4 vs = reinterpret_cast<const float4*>(fs)[(size_t)s * 32 + lane];
    float4 vd = reinterpret_cast<const float4*>(fd)[(size_t)d * 32 + lane];

    float x, sum = 0.0f;
    x = vs.x + vd.x; x = (x > 0.f) ? x : NEG_SLOPE * x; sum += x * va.x;
    x = vs.y + vd.y; x = (x > 0.f) ? x : NEG_SLOPE * x; sum += x * va.y;
    x = vs.z + vd.z; x = (x > 0.f) ? x : NEG_SLOPE * x; sum += x * va.z;
    x = vs.w + vd.w; x = (x > 0.f) ? x : NEG_SLOPE * x; sum += x * va.w;

    sum += __shfl_xor_sync(0xffffffffu, sum, 4);
    sum += __shfl_xor_sync(0xffffffffu, sum, 2);
    sum += __shfl_xor_sync(0xffffffffu, sum, 1);

    float a = expf(sum);

    if ((lane & 7) == 0)
        atomicAdd(&denom[(size_t)d * 4 + (lane >> 3)], a);

    float4 m;
    m.x = vs.x * a; m.y = vs.y * a; m.z = vs.z * a; m.w = vs.w * a;
    float* p = rst + (size_t)d * HID + lane * 4;
    asm volatile("red.global.add.v4.f32 [%0], {%1,%2,%3,%4};"
                 :: "l"(p), "f"(m.x), "f"(m.y), "f"(m.z), "f"(m.w)
                 : "memory");
}

// ---------------- LN1: normalize by denom, residual, LayerNorm ----------------
__global__ __launch_bounds__(256) void ln1_kernel(
    const float* __restrict__ rst, const float* __restrict__ denom,
    const float* __restrict__ resid,
    const float* __restrict__ g, const float* __restrict__ b,
    float* __restrict__ out)
{
    int row = blockIdx.x * 8 + (threadIdx.x >> 5);
    if (row >= NN) return;
    int lane = threadIdx.x & 31;

    float den = denom[(size_t)row * 4 + (lane >> 3)];
    den = (den == 0.0f) ? 1.0f : den;
    float inv = 1.0f / den;

    float4 v = reinterpret_cast<const float4*>(rst)[(size_t)row * 32 + lane];
    float4 r = reinterpret_cast<const float4*>(resid)[(size_t)row * 32 + lane];
    v.x = v.x * inv + r.x; v.y = v.y * inv + r.y;
    v.z = v.z * inv + r.z; v.w = v.w * inv + r.w;

    float s1 = v.x + v.y + v.z + v.w;
    float s2 = v.x * v.x + v.y * v.y + v.z * v.z + v.w * v.w;
    #pragma unroll
    for (int off = 16; off > 0; off >>= 1) {
        s1 += __shfl_xor_sync(0xffffffffu, s1, off);
        s2 += __shfl_xor_sync(0xffffffffu, s2, off);
    }
    float mu = s1 * (1.0f / HID);
    float var = s2 * (1.0f / HID) - mu * mu;
    float rstd = rsqrtf(var + LN_EPS);

    float4 gg = reinterpret_cast<const float4*>(g)[lane];
    float4 bb = reinterpret_cast<const float4*>(b)[lane];
    float4 o;
    o.x = (v.x - mu) * rstd * gg.x + bb.x;
    o.y = (v.y - mu) * rstd * gg.y + bb.y;
    o.z = (v.z - mu) * rstd * gg.z + bb.z;
    o.w = (v.w - mu) * rstd * gg.w + bb.w;
    reinterpret_cast<float4*>(out)[(size_t)row * 32 + lane] = o;
}

// ---------------- LN2: residual LayerNorm ----------------
__global__ __launch_bounds__(256) void ln2_kernel(
    const float* __restrict__ x, const float* __restrict__ resid,
    const float* __restrict__ g, const float* __restrict__ b,
    float* __restrict__ out)
{
    int row = blockIdx.x * 8 + (threadIdx.x >> 5);
    if (row >= NN) return;
    int lane = threadIdx.x & 31;

    float4 v = reinterpret_cast<const float4*>(x)[(size_t)row * 32 + lane];
    float4 r = reinterpret_cast<const float4*>(resid)[(size_t)row * 32 + lane];
    v.x += r.x; v.y += r.y; v.z += r.z; v.w += r.w;

    float s1 = v.x + v.y + v.z + v.w;
    float s2 = v.x * v.x + v.y * v.y + v.z * v.z + v.w * v.w;
    #pragma unroll
    for (int off = 16; off > 0; off >>= 1) {
        s1 += __shfl_xor_sync(0xffffffffu, s1, off);
        s2 += __shfl_xor_sync(0xffffffffu, s2, off);
    }
    float mu = s1 * (1.0f / HID);
    float var = s2 * (1.0f / HID) - mu * mu;
    float rstd = rsqrtf(var + LN_EPS);

    float4 gg = reinterpret_cast<const float4*>(g)[lane];
    float4 bb = reinterpret_cast<const float4*>(b)[lane];
    float4 o;
    o.x = (v.x - mu) * rstd * gg.x + bb.x;
    o.y = (v.y - mu) * rstd * gg.y + bb.y;
    o.z = (v.z - mu) * rstd * gg.z + bb.z;
    o.w = (v.w - mu) * rstd * gg.w + bb.w;
    reinterpret_cast<float4*>(out)[(size_t)row * 32 + lane] = o;
}

// ---------------- launcher ----------------
extern "C" void kernel_launch(void* const* d_in, const int* in_sizes, int n_in,
                              void* d_out, int out_size)
{
    const float* h    = (const float*)d_in[0];
    const int*   src  = (const int*)  d_in[1];
    const int*   dst  = (const int*)  d_in[2];
    const float* Wsrc = (const float*)d_in[3];
    const float* bsrc = (const float*)d_in[4];
    const float* Wdst = (const float*)d_in[5];
    const float* bdst = (const float*)d_in[6];
    const float* attn = (const float*)d_in[7];
    const float* W1   = (const float*)d_in[8];
    const float* bf1  = (const float*)d_in[9];
    const float* W2   = (const float*)d_in[10];
    const float* bf2  = (const float*)d_in[11];
    const float* g1   = (const float*)d_in[12];
    const float* be1  = (const float*)d_in[13];
    const float* g2   = (const float*)d_in[14];
    const float* be2  = (const float*)d_in[15];
    float* out = (float*)d_out;

    float *fs, *fd, *denom, *rst, *h1, *t, *z;
    cudaGetSymbolAddress((void**)&fs,    g_fs);
    cudaGetSymbolAddress((void**)&fd,    g_fd);
    cudaGetSymbolAddress((void**)&denom, g_denom);
    cudaGetSymbolAddress((void**)&rst,   g_rst);
    cudaGetSymbolAddress((void**)&h1,    g_h1);
    cudaGetSymbolAddress((void**)&t,     g_t);
    cudaGetSymbolAddress((void**)&z,     g_z);

    cudaFuncSetAttribute(gemm_srcdst, cudaFuncAttributeMaxDynamicSharedMemorySize, SM_BYTES);
    cudaFuncSetAttribute(gemm_ffn1,   cudaFuncAttributeMaxDynamicSharedMemorySize, SM_BYTES);
    cudaFuncSetAttribute(gemm_ffn2,   cudaFuncAttributeMaxDynamicSharedMemorySize, SM_BYTES);

    cudaMemsetAsync(denom, 0, NN * HEADS * sizeof(float));
    cudaMemsetAsync(rst,   0, NN * HID * sizeof(float));

    const int GX = (NN + 63) / 64;   // 782 (NPAD = 782*64)

    gemm_srcdst<<<dim3(GX, 4), 256, SM_BYTES>>>(h, Wsrc, bsrc, Wdst, bdst, fs, fd);

    int eblocks = (EE + 7) / 8;
    edge_fused<<<eblocks, 256>>>(fs, fd, src, dst, attn, denom, rst);

    int lblocks = (NN + 7) / 8;
    ln1_kernel<<<lblocks, 256>>>(rst, denom, h, g1, be1, h1);

    gemm_ffn1<<<dim3(GX, 4), 256, SM_BYTES>>>(h1, W1, bf1, t);
    gemm_ffn2<<<dim3(GX, 2), 256, SM_BYTES>>>(t, W2, bf2, z);

    ln2_kernel<<<lblocks, 256>>>(z, h1, g2, be2, out);
}

// round 5
// speedup vs baseline: 1.8083x; 1.3264x over previous
#include <cuda_runtime.h>
#include <cuda_bf16.h>
#include <mma.h>
#include <math.h>

using namespace nvcuda;
typedef __nv_bfloat16 bf16;

// ---------------- problem constants ----------------
#define NN 50000
#define NPAD 50048            // 391 * 128
#define EE 600000
#define HID 128
#define HEADS 4
#define NEG_SLOPE 0.2f
#define LN_EPS 1e-5f

// GEMM tile geometry
#define BM 128
#define BN 64
#define BK 64
#define LDA_SM 72             // 64 + 8 pad (bf16 elems)
#define LDB_SM 72
#define A_SM 9216             // 128 * 72
#define B_SM 4608             // 64 * 72
// smem: Ah, Al, Bh, Bl (bf16) + bias tile 16x64 fp32
#define SM_BYTES ((2 * A_SM + 2 * B_SM) * 2 + 16 * 64 * 4)   // 59392

// ---------------- scratch ----------------
__device__ float g_fs[NPAD * HID];
__device__ float g_fd[NPAD * HID];
__device__ float g_denom[NN * HEADS];
__device__ float g_rst[NN * HID];
__device__ float g_h1[NPAD * HID];
__device__ float g_z[NPAD * HID];
// bf16 hi/lo planes
__device__ bf16 g_h_hi[NPAD * HID];
__device__ bf16 g_h_lo[NPAD * HID];
__device__ bf16 g_h1_hi[NPAD * HID];
__device__ bf16 g_h1_lo[NPAD * HID];
__device__ bf16 g_t_hi[NPAD * 2 * HID];
__device__ bf16 g_t_lo[NPAD * 2 * HID];
__device__ bf16 g_Wsrc_hi[HID * HID];
__device__ bf16 g_Wsrc_lo[HID * HID];
__device__ bf16 g_Wdst_hi[HID * HID];
__device__ bf16 g_Wdst_lo[HID * HID];
__device__ bf16 g_W1_hi[HID * 2 * HID];
__device__ bf16 g_W1_lo[HID * 2 * HID];
__device__ bf16 g_W2_hi[2 * HID * HID];
__device__ bf16 g_W2_lo[2 * HID * HID];

// ---------------- split helper: fp32x4 -> (hi bf16x4, lo bf16x4) ----------------
__device__ __forceinline__ void split4(float4 v, uint2& hi, uint2& lo) {
    bf16 h0 = __float2bfloat16(v.x), h1 = __float2bfloat16(v.y);
    bf16 h2 = __float2bfloat16(v.z), h3 = __float2bfloat16(v.w);
    bf16 l0 = __float2bfloat16(v.x - __bfloat162float(h0));
    bf16 l1 = __float2bfloat16(v.y - __bfloat162float(h1));
    bf16 l2 = __float2bfloat16(v.z - __bfloat162float(h2));
    bf16 l3 = __float2bfloat16(v.w - __bfloat162float(h3));
    hi.x = (unsigned)__bfloat16_as_ushort(h0) | ((unsigned)__bfloat16_as_ushort(h1) << 16);
    hi.y = (unsigned)__bfloat16_as_ushort(h2) | ((unsigned)__bfloat16_as_ushort(h3) << 16);
    lo.x = (unsigned)__bfloat16_as_ushort(l0) | ((unsigned)__bfloat16_as_ushort(l1) << 16);
    lo.y = (unsigned)__bfloat16_as_ushort(l2) | ((unsigned)__bfloat16_as_ushort(l3) << 16);
}

// ---------------- split kernels ----------------
__global__ void split_mat(const float* __restrict__ src, bf16* __restrict__ hi,
                          bf16* __restrict__ lo, int n4) {
    int i = blockIdx.x * blockDim.x + threadIdx.x;
    if (i >= n4) return;
    float4 v = reinterpret_cast<const float4*>(src)[i];
    uint2 h, l;
    split4(v, h, l);
    reinterpret_cast<uint2*>(hi)[i] = h;
    reinterpret_cast<uint2*>(lo)[i] = l;
}

// h: guard rows >= NN with zeros, pad to NPAD
__global__ void split_h(const float* __restrict__ src, bf16* __restrict__ hi,
                        bf16* __restrict__ lo) {
    int i = blockIdx.x * blockDim.x + threadIdx.x;   // over NPAD*32
    if (i >= NPAD * 32) return;
    int row = i >> 5;
    float4 v = make_float4(0.f, 0.f, 0.f, 0.f);
    if (row < NN) v = reinterpret_cast<const float4*>(src)[i];
    uint2 h, l;
    split4(v, h, l);
    reinterpret_cast<uint2*>(hi)[i] = h;
    reinterpret_cast<uint2*>(lo)[i] = l;
}

// ---------------- WMMA split-bf16 GEMM core ----------------
// C(128x64 tile) = A@B + bias over pre-split bf16 planes.
// 8 warps: 4(m) x 2(n); warp tile 32x32; K chunked at 64.
template <int KTOT, bool GELU, bool SPLIT_OUT>
__device__ __forceinline__ void gemm_core(
    const bf16* __restrict__ Ah_g, const bf16* __restrict__ Al_g, int lda,
    const bf16* __restrict__ Bh_g, const bf16* __restrict__ Bl_g, int ldb,
    const float* __restrict__ bias,
    float* __restrict__ C, bf16* __restrict__ Chi, bf16* __restrict__ Clo,
    int ldc, int ccol0, int m0)
{
    extern __shared__ bf16 sm[];
    bf16* Ah = sm;
    bf16* Al = sm + A_SM;
    bf16* Bh = sm + 2 * A_SM;
    bf16* Bl = sm + 2 * A_SM + B_SM;
    float* bias_sm = (float*)(sm + 2 * A_SM + 2 * B_SM);   // [16][64]

    const int tid = threadIdx.x;
    const int wid = tid >> 5;
    const int wm = wid >> 1;          // 0..3 -> 32 rows each
    const int wn = wid & 1;           // 0..1 -> 32 cols each

    for (int i = tid; i < 16 * 64; i += 256)
        bias_sm[i] = bias[ccol0 + (i & 63)];
    __syncthreads();

    wmma::fragment<wmma::accumulator, 16, 16, 16, float> acc[2][2];
    #pragma unroll
    for (int mi = 0; mi < 2; mi++)
        #pragma unroll
        for (int nj = 0; nj < 2; nj++)
            wmma::load_matrix_sync(acc[mi][nj], bias_sm + wn * 32 + nj * 16, 64, wmma::mem_row_major);

    constexpr int KC = KTOT / BK;
    #pragma unroll
    for (int kc = 0; kc < KC; kc++) {
        __syncthreads();
        // A chunk: 128 rows x 64 k (both planes), uint4 = 8 bf16
        #pragma unroll
        for (int i = tid; i < 1024; i += 256) {
            int r = i >> 3, c8 = i & 7;
            const size_t go = (size_t)(m0 + r) * lda + kc * 64 + c8 * 8;
            *reinterpret_cast<uint4*>(Ah + r * LDA_SM + c8 * 8) =
                *reinterpret_cast<const uint4*>(Ah_g + go);
            *reinterpret_cast<uint4*>(Al + r * LDA_SM + c8 * 8) =
                *reinterpret_cast<const uint4*>(Al_g + go);
        }
        // B chunk: 64 k-rows x 64 cols (both planes)
        #pragma unroll
        for (int i = tid; i < 512; i += 256) {
            int r = i >> 3, c8 = i & 7;
            const size_t go = (size_t)(kc * 64 + r) * ldb + ccol0 + c8 * 8;
            *reinterpret_cast<uint4*>(Bh + r * LDB_SM + c8 * 8) =
                *reinterpret_cast<const uint4*>(Bh_g + go);
            *reinterpret_cast<uint4*>(Bl + r * LDB_SM + c8 * 8) =
                *reinterpret_cast<const uint4*>(Bl_g + go);
        }
        __syncthreads();

        #pragma unroll
        for (int kk = 0; kk < BK / 16; kk++) {
            wmma::fragment<wmma::matrix_a, 16, 16, 16, bf16, wmma::row_major> ah[2], al[2];
            wmma::fragment<wmma::matrix_b, 16, 16, 16, bf16, wmma::row_major> bh[2], bl[2];
            #pragma unroll
            for (int mi = 0; mi < 2; mi++) {
                const bf16* ap = Ah + (wm * 32 + mi * 16) * LDA_SM + kk * 16;
                const bf16* alp = Al + (wm * 32 + mi * 16) * LDA_SM + kk * 16;
                wmma::load_matrix_sync(ah[mi], ap, LDA_SM);
                wmma::load_matrix_sync(al[mi], alp, LDA_SM);
            }
            #pragma unroll
            for (int nj = 0; nj < 2; nj++) {
                const bf16* bp = Bh + (kk * 16) * LDB_SM + wn * 32 + nj * 16;
                const bf16* blp = Bl + (kk * 16) * LDB_SM + wn * 32 + nj * 16;
                wmma::load_matrix_sync(bh[nj], bp, LDB_SM);
                wmma::load_matrix_sync(bl[nj], blp, LDB_SM);
            }
            #pragma unroll
            for (int mi = 0; mi < 2; mi++)
                #pragma unroll
                for (int nj = 0; nj < 2; nj++) {
                    wmma::mma_sync(acc[mi][nj], ah[mi], bh[nj], acc[mi][nj]);
                    wmma::mma_sync(acc[mi][nj], ah[mi], bl[nj], acc[mi][nj]);
                    wmma::mma_sync(acc[mi][nj], al[mi], bh[nj], acc[mi][nj]);
                }
        }
    }

    if (GELU) {
        #pragma unroll
        for (int mi = 0; mi < 2; mi++)
            #pragma unroll
            for (int nj = 0; nj < 2; nj++)
                #pragma unroll
                for (int i = 0; i < acc[mi][nj].num_elements; i++) {
                    float x = acc[mi][nj].x[i];
                    acc[mi][nj].x[i] = 0.5f * x * (1.0f + erff(x * 0.70710678118654752f));
                }
    }

    if (!SPLIT_OUT) {
        #pragma unroll
        for (int mi = 0; mi < 2; mi++)
            #pragma unroll
            for (int nj = 0; nj < 2; nj++) {
                float* cp = C + (size_t)(m0 + wm * 32 + mi * 16) * ldc + ccol0 + wn * 32 + nj * 16;
                wmma::store_matrix_sync(cp, acc[mi][nj], ldc, wmma::mem_row_major);
            }
    } else {
        // per-warp staging: 32 x 36 fp32 region, then split -> bf16 planes
        __syncthreads();   // done with A/B smem; reuse it
        float* stage = (float*)sm + wid * (32 * 36);
        #pragma unroll
        for (int mi = 0; mi < 2; mi++)
            #pragma unroll
            for (int nj = 0; nj < 2; nj++)
                wmma::store_matrix_sync(stage + mi * 16 * 36 + nj * 16, acc[mi][nj], 36, wmma::mem_row_major);
        __syncwarp();
        int lane = tid & 31;
        #pragma unroll
        for (int it = 0; it < 8; it++) {
            int j = it * 32 + lane;        // 256 items: 32 rows x 8 col-quads
            int r = j >> 3, c4 = j & 7;
            float4 v = *reinterpret_cast<const float4*>(stage + r * 36 + c4 * 4);
            uint2 h, l;
            split4(v, h, l);
            size_t go = (size_t)(m0 + wm * 32 + r) * ldc + ccol0 + wn * 32 + c4 * 4;
            *reinterpret_cast<uint2*>(Chi + go) = h;
            *reinterpret_cast<uint2*>(Clo + go) = l;
        }
    }
}

__global__ __launch_bounds__(256) void gemm_srcdst(
    const bf16* __restrict__ h_hi, const bf16* __restrict__ h_lo,
    const bf16* __restrict__ Ws_hi, const bf16* __restrict__ Ws_lo,
    const float* __restrict__ bsrc,
    const bf16* __restrict__ Wd_hi, const bf16* __restrict__ Wd_lo,
    const float* __restrict__ bdst,
    float* __restrict__ fs, float* __restrict__ fd)
{
    int m0 = blockIdx.x * BM;
    int y = blockIdx.y;             // 0,1: fs cols 0/64 ; 2,3: fd cols 0/64
    int col0 = (y & 1) * 64;
    if (y < 2)
        gemm_core<128, false, false>(h_hi, h_lo, 128, Ws_hi, Ws_lo, 128, bsrc,
                                     fs, nullptr, nullptr, 128, col0, m0);
    else
        gemm_core<128, false, false>(h_hi, h_lo, 128, Wd_hi, Wd_lo, 128, bdst,
                                     fd, nullptr, nullptr, 128, col0, m0);
}

__global__ __launch_bounds__(256) void gemm_ffn1(
    const bf16* __restrict__ h1_hi, const bf16* __restrict__ h1_lo,
    const bf16* __restrict__ W1_hi, const bf16* __restrict__ W1_lo,
    const float* __restrict__ bf1,
    bf16* __restrict__ t_hi, bf16* __restrict__ t_lo)
{
    gemm_core<128, true, true>(h1_hi, h1_lo, 128, W1_hi, W1_lo, 256, bf1,
                               nullptr, t_hi, t_lo, 256, blockIdx.y * 64, blockIdx.x * BM);
}

__global__ __launch_bounds__(256) void gemm_ffn2(
    const bf16* __restrict__ t_hi, const bf16* __restrict__ t_lo,
    const bf16* __restrict__ W2_hi, const bf16* __restrict__ W2_lo,
    const float* __restrict__ bf2, float* __restrict__ z)
{
    gemm_core<256, false, false>(t_hi, t_lo, 256, W2_hi, W2_lo, 128, bf2,
                                 z, nullptr, nullptr, 128, blockIdx.y * 64, blockIdx.x * BM);
}

// ---------------- fused edge pass ----------------
__global__ __launch_bounds__(256) void edge_fused(
    const float* __restrict__ fs, const float* __restrict__ fd,
    const int* __restrict__ src, const int* __restrict__ dst,
    const float* __restrict__ attn,
    float* __restrict__ denom, float* __restrict__ rst)
{
    int e = blockIdx.x * 8 + (threadIdx.x >> 5);
    if (e >= EE) return;
    int lane = threadIdx.x & 31;

    float4 va = reinterpret_cast<const float4*>(attn)[lane];
    int s = __ldg(src + e), d = __ldg(dst + e);

    float4 vs = reinterpret_cast<const float4*>(fs)[(size_t)s * 32 + lane];
    float4 vd = reinterpret_cast<const float4*>(fd)[(size_t)d * 32 + lane];

    float x, sum = 0.0f;
    x = vs.x + vd.x; x = (x > 0.f) ? x : NEG_SLOPE * x; sum += x * va.x;
    x = vs.y + vd.y; x = (x > 0.f) ? x : NEG_SLOPE * x; sum += x * va.y;
    x = vs.z + vd.z; x = (x > 0.f) ? x : NEG_SLOPE * x; sum += x * va.z;
    x = vs.w + vd.w; x = (x > 0.f) ? x : NEG_SLOPE * x; sum += x * va.w;

    sum += __shfl_xor_sync(0xffffffffu, sum, 4);
    sum += __shfl_xor_sync(0xffffffffu, sum, 2);
    sum += __shfl_xor_sync(0xffffffffu, sum, 1);

    float a = expf(sum);

    if ((lane & 7) == 0)
        atomicAdd(&denom[(size_t)d * 4 + (lane >> 3)], a);

    float4 m;
    m.x = vs.x * a; m.y = vs.y * a; m.z = vs.z * a; m.w = vs.w * a;
    float* p = rst + (size_t)d * HID + lane * 4;
    asm volatile("red.global.add.v4.f32 [%0], {%1,%2,%3,%4};"
                 :: "l"(p), "f"(m.x), "f"(m.y), "f"(m.z), "f"(m.w)
                 : "memory");
}

// ---------------- LN1: normalize, residual, LayerNorm; emits fp32 + planes ----
__global__ __launch_bounds__(256) void ln1_kernel(
    const float* __restrict__ rst, const float* __restrict__ denom,
    const float* __restrict__ resid,
    const float* __restrict__ g, const float* __restrict__ b,
    float* __restrict__ out, bf16* __restrict__ out_hi, bf16* __restrict__ out_lo)
{
    int row = blockIdx.x * 8 + (threadIdx.x >> 5);
    if (row >= NPAD) return;
    int lane = threadIdx.x & 31;

    if (row >= NN) {   // zero padding rows of the planes (read by ffn1 loader)
        uint2 zz = make_uint2(0u, 0u);
        reinterpret_cast<uint2*>(out_hi)[(size_t)row * 32 + lane] = zz;
        reinterpret_cast<uint2*>(out_lo)[(size_t)row * 32 + lane] = zz;
        return;
    }

    float den = denom[(size_t)row * 4 + (lane >> 3)];
    den = (den == 0.0f) ? 1.0f : den;
    float inv = 1.0f / den;

    float4 v = reinterpret_cast<const float4*>(rst)[(size_t)row * 32 + lane];
    float4 r = reinterpret_cast<const float4*>(resid)[(size_t)row * 32 + lane];
    v.x = v.x * inv + r.x; v.y = v.y * inv + r.y;
    v.z = v.z * inv + r.z; v.w = v.w * inv + r.w;

    float s1 = v.x + v.y + v.z + v.w;
    float s2 = v.x * v.x + v.y * v.y + v.z * v.z + v.w * v.w;
    #pragma unroll
    for (int off = 16; off > 0; off >>= 1) {
        s1 += __shfl_xor_sync(0xffffffffu, s1, off);
        s2 += __shfl_xor_sync(0xffffffffu, s2, off);
    }
    float mu = s1 * (1.0f / HID);
    float var = s2 * (1.0f / HID) - mu * mu;
    float rstd = rsqrtf(var + LN_EPS);

    float4 gg = reinterpret_cast<const float4*>(g)[lane];
    float4 bb = reinterpret_cast<const float4*>(b)[lane];
    float4 o;
    o.x = (v.x - mu) * rstd * gg.x + bb.x;
    o.y = (v.y - mu) * rstd * gg.y + bb.y;
    o.z = (v.z - mu) * rstd * gg.z + bb.z;
    o.w = (v.w - mu) * rstd * gg.w + bb.w;
    reinterpret_cast<float4*>(out)[(size_t)row * 32 + lane] = o;

    uint2 h, l;
    split4(o, h, l);
    reinterpret_cast<uint2*>(out_hi)[(size_t)row * 32 + lane] = h;
    reinterpret_cast<uint2*>(out_lo)[(size_t)row * 32 + lane] = l;
}

// ---------------- LN2 ----------------
__global__ __launch_bounds__(256) void ln2_kernel(
    const float* __restrict__ x, const float* __restrict__ resid,
    const float* __restrict__ g, const float* __restrict__ b,
    float* __restrict__ out)
{
    int row = blockIdx.x * 8 + (threadIdx.x >> 5);
    if (row >= NN) return;
    int lane = threadIdx.x & 31;

    float4 v = reinterpret_cast<const float4*>(x)[(size_t)row * 32 + lane];
    float4 r = reinterpret_cast<const float4*>(resid)[(size_t)row * 32 + lane];
    v.x += r.x; v.y += r.y; v.z += r.z; v.w += r.w;

    float s1 = v.x + v.y + v.z + v.w;
    float s2 = v.x * v.x + v.y * v.y + v.z * v.z + v.w * v.w;
    #pragma unroll
    for (int off = 16; off > 0; off >>= 1) {
        s1 += __shfl_xor_sync(0xffffffffu, s1, off);
        s2 += __shfl_xor_sync(0xffffffffu, s2, off);
    }
    float mu = s1 * (1.0f / HID);
    float var = s2 * (1.0f / HID) - mu * mu;
    float rstd = rsqrtf(var + LN_EPS);

    float4 gg = reinterpret_cast<const float4*>(g)[lane];
    float4 bb = reinterpret_cast<const float4*>(b)[lane];
    float4 o;
    o.x = (v.x - mu) * rstd * gg.x + bb.x;
    o.y = (v.y - mu) * rstd * gg.y + bb.y;
    o.z = (v.z - mu) * rstd * gg.z + bb.z;
    o.w = (v.w - mu) * rstd * gg.w + bb.w;
    reinterpret_cast<float4*>(out)[(size_t)row * 32 + lane] = o;
}

// ---------------- launcher ----------------
extern "C" void kernel_launch(void* const* d_in, const int* in_sizes, int n_in,
                              void* d_out, int out_size)
{
    const float* h    = (const float*)d_in[0];
    const int*   src  = (const int*)  d_in[1];
    const int*   dst  = (const int*)  d_in[2];
    const float* Wsrc = (const float*)d_in[3];
    const float* bsrc = (const float*)d_in[4];
    const float* Wdst = (const float*)d_in[5];
    const float* bdst = (const float*)d_in[6];
    const float* attn = (const float*)d_in[7];
    const float* W1   = (const float*)d_in[8];
    const float* bf1  = (const float*)d_in[9];
    const float* W2   = (const float*)d_in[10];
    const float* bf2  = (const float*)d_in[11];
    const float* g1   = (const float*)d_in[12];
    const float* be1  = (const float*)d_in[13];
    const float* g2   = (const float*)d_in[14];
    const float* be2  = (const float*)d_in[15];
    float* out = (float*)d_out;

    float *fs, *fd, *denom, *rst, *h1, *z;
    bf16 *h_hi, *h_lo, *h1_hi, *h1_lo, *t_hi, *t_lo;
    bf16 *Ws_hi, *Ws_lo, *Wd_hi, *Wd_lo, *W1_hi, *W1_lo, *W2_hi, *W2_lo;
    cudaGetSymbolAddress((void**)&fs,    g_fs);
    cudaGetSymbolAddress((void**)&fd,    g_fd);
    cudaGetSymbolAddress((void**)&denom, g_denom);
    cudaGetSymbolAddress((void**)&rst,   g_rst);
    cudaGetSymbolAddress((void**)&h1,    g_h1);
    cudaGetSymbolAddress((void**)&z,     g_z);
    cudaGetSymbolAddress((void**)&h_hi,  g_h_hi);
    cudaGetSymbolAddress((void**)&h_lo,  g_h_lo);
    cudaGetSymbolAddress((void**)&h1_hi, g_h1_hi);
    cudaGetSymbolAddress((void**)&h1_lo, g_h1_lo);
    cudaGetSymbolAddress((void**)&t_hi,  g_t_hi);
    cudaGetSymbolAddress((void**)&t_lo,  g_t_lo);
    cudaGetSymbolAddress((void**)&Ws_hi, g_Wsrc_hi);
    cudaGetSymbolAddress((void**)&Ws_lo, g_Wsrc_lo);
    cudaGetSymbolAddress((void**)&Wd_hi, g_Wdst_hi);
    cudaGetSymbolAddress((void**)&Wd_lo, g_Wdst_lo);
    cudaGetSymbolAddress((void**)&W1_hi, g_W1_hi);
    cudaGetSymbolAddress((void**)&W1_lo, g_W1_lo);
    cudaGetSymbolAddress((void**)&W2_hi, g_W2_hi);
    cudaGetSymbolAddress((void**)&W2_lo, g_W2_lo);

    cudaFuncSetAttribute(gemm_srcdst, cudaFuncAttributeMaxDynamicSharedMemorySize, SM_BYTES);
    cudaFuncSetAttribute(gemm_ffn1,   cudaFuncAttributeMaxDynamicSharedMemorySize, SM_BYTES);
    cudaFuncSetAttribute(gemm_ffn2,   cudaFuncAttributeMaxDynamicSharedMemorySize, SM_BYTES);

    cudaMemsetAsync(denom, 0, NN * HEADS * sizeof(float));
    cudaMemsetAsync(rst,   0, NN * HID * sizeof(float));

    // pre-split h and weights
    split_h<<<(NPAD * 32 + 255) / 256, 256>>>(h, h_hi, h_lo);
    split_mat<<<(HID * HID / 4 + 255) / 256, 256>>>(Wsrc, Ws_hi, Ws_lo, HID * HID / 4);
    split_mat<<<(HID * HID / 4 + 255) / 256, 256>>>(Wdst, Wd_hi, Wd_lo, HID * HID / 4);
    split_mat<<<(HID * 2 * HID / 4 + 255) / 256, 256>>>(W1, W1_hi, W1_lo, HID * 2 * HID / 4);
    split_mat<<<(2 * HID * HID / 4 + 255) / 256, 256>>>(W2, W2_hi, W2_lo, 2 * HID * HID / 4);

    const int GXM = NPAD / BM;   // 391

    gemm_srcdst<<<dim3(GXM, 4), 256, SM_BYTES>>>(h_hi, h_lo, Ws_hi, Ws_lo, bsrc,
                                                 Wd_hi, Wd_lo, bdst, fs, fd);

    int eblocks = (EE + 7) / 8;
    edge_fused<<<eblocks, 256>>>(fs, fd, src, dst, attn, denom, rst);

    int lblocks1 = (NPAD + 7) / 8;
    ln1_kernel<<<lblocks1, 256>>>(rst, denom, h, g1, be1, h1, h1_hi, h1_lo);

    gemm_ffn1<<<dim3(GXM, 4), 256, SM_BYTES>>>(h1_hi, h1_lo, W1_hi, W1_lo, bf1, t_hi, t_lo);
    gemm_ffn2<<<dim3(GXM, 2), 256, SM_BYTES>>>(t_hi, t_lo, W2_hi, W2_lo, bf2, z);

    int lblocks = (NN + 7) / 8;
    ln2_kernel<<<lblocks, 256>>>(z, h1, g2, be2, out);
}

// round 6
// speedup vs baseline: 1.9908x; 1.1009x over previous
#include <cuda_runtime.h>
#include <cuda_bf16.h>
#include <mma.h>
#include <math.h>

using namespace nvcuda;
typedef __nv_bfloat16 bf16;

// ---------------- problem constants ----------------
#define NN 50000
#define NPAD 50048            // 391 * 128
#define EE 600000
#define HID 128
#define HEADS 4
#define NEG_SLOPE 0.2f
#define LN_EPS 1e-5f

// GEMM tile geometry
#define BM 128
#define BN 64
#define BK 64
#define LDA_SM 72
#define LDB_SM 72
#define A_SM 9216             // 128 * 72
#define B_SM 4608             // 64 * 72
#define SM_BYTES ((2 * A_SM + 2 * B_SM) * 2 + 16 * 64 * 4)   // 59392

// ---------------- scratch ----------------
__device__ float g_fs[NPAD * HID];
__device__ float g_fd[NPAD * HID];
__device__ float g_denom[NN * HEADS];
__device__ float g_rst[NN * HID];
__device__ float g_h1[NPAD * HID];
__device__ float g_z[NPAD * HID];
// CSR scratch
__device__ int g_ecnt[NN];
__device__ int g_eoff[NN];
__device__ int g_cursor[NN];
__device__ int g_bsum[128];
__device__ int g_esrc[EE];
// bf16 hi/lo planes
__device__ bf16 g_h_hi[NPAD * HID];
__device__ bf16 g_h_lo[NPAD * HID];
__device__ bf16 g_h1_hi[NPAD * HID];
__device__ bf16 g_h1_lo[NPAD * HID];
__device__ bf16 g_t_hi[NPAD * 2 * HID];
__device__ bf16 g_t_lo[NPAD * 2 * HID];
__device__ bf16 g_Wsrc_hi[HID * HID];
__device__ bf16 g_Wsrc_lo[HID * HID];
__device__ bf16 g_Wdst_hi[HID * HID];
__device__ bf16 g_Wdst_lo[HID * HID];
__device__ bf16 g_W1_hi[HID * 2 * HID];
__device__ bf16 g_W1_lo[HID * 2 * HID];
__device__ bf16 g_W2_hi[2 * HID * HID];
__device__ bf16 g_W2_lo[2 * HID * HID];

// ---------------- split helper ----------------
__device__ __forceinline__ void split4(float4 v, uint2& hi, uint2& lo) {
    bf16 h0 = __float2bfloat16(v.x), h1 = __float2bfloat16(v.y);
    bf16 h2 = __float2bfloat16(v.z), h3 = __float2bfloat16(v.w);
    bf16 l0 = __float2bfloat16(v.x - __bfloat162float(h0));
    bf16 l1 = __float2bfloat16(v.y - __bfloat162float(h1));
    bf16 l2 = __float2bfloat16(v.z - __bfloat162float(h2));
    bf16 l3 = __float2bfloat16(v.w - __bfloat162float(h3));
    hi.x = (unsigned)__bfloat16_as_ushort(h0) | ((unsigned)__bfloat16_as_ushort(h1) << 16);
    hi.y = (unsigned)__bfloat16_as_ushort(h2) | ((unsigned)__bfloat16_as_ushort(h3) << 16);
    lo.x = (unsigned)__bfloat16_as_ushort(l0) | ((unsigned)__bfloat16_as_ushort(l1) << 16);
    lo.y = (unsigned)__bfloat16_as_ushort(l2) | ((unsigned)__bfloat16_as_ushort(l3) << 16);
}

// ---------------- split kernels ----------------
// all four weight matrices in one launch: [Wsrc|Wdst|W1|W2] = 24576 float4s
__global__ void split_weights(
    const float* __restrict__ Ws, const float* __restrict__ Wd,
    const float* __restrict__ W1, const float* __restrict__ W2,
    bf16* __restrict__ Ws_hi, bf16* __restrict__ Ws_lo,
    bf16* __restrict__ Wd_hi, bf16* __restrict__ Wd_lo,
    bf16* __restrict__ W1_hi, bf16* __restrict__ W1_lo,
    bf16* __restrict__ W2_hi, bf16* __restrict__ W2_lo)
{
    int i = blockIdx.x * blockDim.x + threadIdx.x;
    const float* s; bf16 *ph, *pl; int j = i;
    if (j < 4096)        { s = Ws; ph = Ws_hi; pl = Ws_lo; }
    else if (j < 8192)   { j -= 4096;  s = Wd; ph = Wd_hi; pl = Wd_lo; }
    else if (j < 16384)  { j -= 8192;  s = W1; ph = W1_hi; pl = W1_lo; }
    else if (j < 24576)  { j -= 16384; s = W2; ph = W2_hi; pl = W2_lo; }
    else return;
    float4 v = reinterpret_cast<const float4*>(s)[j];
    uint2 h, l;
    split4(v, h, l);
    reinterpret_cast<uint2*>(ph)[j] = h;
    reinterpret_cast<uint2*>(pl)[j] = l;
}

__global__ void split_h(const float* __restrict__ src, bf16* __restrict__ hi,
                        bf16* __restrict__ lo) {
    int i = blockIdx.x * blockDim.x + threadIdx.x;
    if (i >= NPAD * 32) return;
    int row = i >> 5;
    float4 v = make_float4(0.f, 0.f, 0.f, 0.f);
    if (row < NN) v = reinterpret_cast<const float4*>(src)[i];
    uint2 h, l;
    split4(v, h, l);
    reinterpret_cast<uint2*>(hi)[i] = h;
    reinterpret_cast<uint2*>(lo)[i] = l;
}

// ---------------- CSR build ----------------
__global__ void hist_kernel(const int* __restrict__ dst, int* __restrict__ cnt) {
    int e = blockIdx.x * blockDim.x + threadIdx.x;
    if (e < EE) atomicAdd(&cnt[dst[e]], 1);
}

__global__ void scan1(const int* __restrict__ cnt, int* __restrict__ excl,
                      int* __restrict__ bsum) {
    __shared__ int sh[512];
    int i = blockIdx.x * 512 + threadIdx.x;
    int v = (i < NN) ? cnt[i] : 0;
    sh[threadIdx.x] = v;
    __syncthreads();
    #pragma unroll
    for (int off = 1; off < 512; off <<= 1) {
        int t = (threadIdx.x >= off) ? sh[threadIdx.x - off] : 0;
        __syncthreads();
        sh[threadIdx.x] += t;
        __syncthreads();
    }
    if (i < NN) excl[i] = sh[threadIdx.x] - v;
    if (threadIdx.x == 511) bsum[blockIdx.x] = sh[511];
}

__global__ void scan2(int* __restrict__ bsum, int nb) {
    __shared__ int sh[128];
    int v = (threadIdx.x < nb) ? bsum[threadIdx.x] : 0;
    sh[threadIdx.x] = v;
    __syncthreads();
    #pragma unroll
    for (int off = 1; off < 128; off <<= 1) {
        int t = (threadIdx.x >= off) ? sh[threadIdx.x - off] : 0;
        __syncthreads();
        sh[threadIdx.x] += t;
        __syncthreads();
    }
    if (threadIdx.x < nb) bsum[threadIdx.x] = sh[threadIdx.x] - v;
}

__global__ void scan3(int* __restrict__ excl, const int* __restrict__ bsum,
                      int* __restrict__ cursor) {
    int i = blockIdx.x * 512 + threadIdx.x;
    if (i < NN) {
        int v = excl[i] + bsum[blockIdx.x];
        excl[i] = v;
        cursor[i] = v;
    }
}

__global__ void scatter_kernel(const int* __restrict__ src, const int* __restrict__ dst,
                               int* __restrict__ cursor, int* __restrict__ esrc) {
    int e = blockIdx.x * blockDim.x + threadIdx.x;
    if (e >= EE) return;
    int pos = atomicAdd(&cursor[dst[e]], 1);
    esrc[pos] = src[e];
}

// ---------------- WMMA split-bf16 GEMM core (unchanged from R5) ----------------
template <int KTOT, bool GELU, bool SPLIT_OUT>
__device__ __forceinline__ void gemm_core(
    const bf16* __restrict__ Ah_g, const bf16* __restrict__ Al_g, int lda,
    const bf16* __restrict__ Bh_g, const bf16* __restrict__ Bl_g, int ldb,
    const float* __restrict__ bias,
    float* __restrict__ C, bf16* __restrict__ Chi, bf16* __restrict__ Clo,
    int ldc, int ccol0, int m0)
{
    extern __shared__ bf16 sm[];
    bf16* Ah = sm;
    bf16* Al = sm + A_SM;
    bf16* Bh = sm + 2 * A_SM;
    bf16* Bl = sm + 2 * A_SM + B_SM;
    float* bias_sm = (float*)(sm + 2 * A_SM + 2 * B_SM);

    const int tid = threadIdx.x;
    const int wid = tid >> 5;
    const int wm = wid >> 1;
    const int wn = wid & 1;

    for (int i = tid; i < 16 * 64; i += 256)
        bias_sm[i] = bias[ccol0 + (i & 63)];
    __syncthreads();

    wmma::fragment<wmma::accumulator, 16, 16, 16, float> acc[2][2];
    #pragma unroll
    for (int mi = 0; mi < 2; mi++)
        #pragma unroll
        for (int nj = 0; nj < 2; nj++)
            wmma::load_matrix_sync(acc[mi][nj], bias_sm + wn * 32 + nj * 16, 64, wmma::mem_row_major);

    constexpr int KC = KTOT / BK;
    #pragma unroll
    for (int kc = 0; kc < KC; kc++) {
        __syncthreads();
        #pragma unroll
        for (int i = tid; i < 1024; i += 256) {
            int r = i >> 3, c8 = i & 7;
            const size_t go = (size_t)(m0 + r) * lda + kc * 64 + c8 * 8;
            *reinterpret_cast<uint4*>(Ah + r * LDA_SM + c8 * 8) =
                *reinterpret_cast<const uint4*>(Ah_g + go);
            *reinterpret_cast<uint4*>(Al + r * LDA_SM + c8 * 8) =
                *reinterpret_cast<const uint4*>(Al_g + go);
        }
        #pragma unroll
        for (int i = tid; i < 512; i += 256) {
            int r = i >> 3, c8 = i & 7;
            const size_t go = (size_t)(kc * 64 + r) * ldb + ccol0 + c8 * 8;
            *reinterpret_cast<uint4*>(Bh + r * LDB_SM + c8 * 8) =
                *reinterpret_cast<const uint4*>(Bh_g + go);
            *reinterpret_cast<uint4*>(Bl + r * LDB_SM + c8 * 8) =
                *reinterpret_cast<const uint4*>(Bl_g + go);
        }
        __syncthreads();

        #pragma unroll
        for (int kk = 0; kk < BK / 16; kk++) {
            wmma::fragment<wmma::matrix_a, 16, 16, 16, bf16, wmma::row_major> ah[2], al[2];
            wmma::fragment<wmma::matrix_b, 16, 16, 16, bf16, wmma::row_major> bh[2], bl[2];
            #pragma unroll
            for (int mi = 0; mi < 2; mi++) {
                const bf16* ap = Ah + (wm * 32 + mi * 16) * LDA_SM + kk * 16;
                const bf16* alp = Al + (wm * 32 + mi * 16) * LDA_SM + kk * 16;
                wmma::load_matrix_sync(ah[mi], ap, LDA_SM);
                wmma::load_matrix_sync(al[mi], alp, LDA_SM);
            }
            #pragma unroll
            for (int nj = 0; nj < 2; nj++) {
                const bf16* bp = Bh + (kk * 16) * LDB_SM + wn * 32 + nj * 16;
                const bf16* blp = Bl + (kk * 16) * LDB_SM + wn * 32 + nj * 16;
                wmma::load_matrix_sync(bh[nj], bp, LDB_SM);
                wmma::load_matrix_sync(bl[nj], blp, LDB_SM);
            }
            #pragma unroll
            for (int mi = 0; mi < 2; mi++)
                #pragma unroll
                for (int nj = 0; nj < 2; nj++) {
                    wmma::mma_sync(acc[mi][nj], ah[mi], bh[nj], acc[mi][nj]);
                    wmma::mma_sync(acc[mi][nj], ah[mi], bl[nj], acc[mi][nj]);
                    wmma::mma_sync(acc[mi][nj], al[mi], bh[nj], acc[mi][nj]);
                }
        }
    }

    if (GELU) {
        #pragma unroll
        for (int mi = 0; mi < 2; mi++)
            #pragma unroll
            for (int nj = 0; nj < 2; nj++)
                #pragma unroll
                for (int i = 0; i < acc[mi][nj].num_elements; i++) {
                    float x = acc[mi][nj].x[i];
                    acc[mi][nj].x[i] = 0.5f * x * (1.0f + erff(x * 0.70710678118654752f));
                }
    }

    if (!SPLIT_OUT) {
        #pragma unroll
        for (int mi = 0; mi < 2; mi++)
            #pragma unroll
            for (int nj = 0; nj < 2; nj++) {
                float* cp = C + (size_t)(m0 + wm * 32 + mi * 16) * ldc + ccol0 + wn * 32 + nj * 16;
                wmma::store_matrix_sync(cp, acc[mi][nj], ldc, wmma::mem_row_major);
            }
    } else {
        __syncthreads();
        float* stage = (float*)sm + wid * (32 * 36);
        #pragma unroll
        for (int mi = 0; mi < 2; mi++)
            #pragma unroll
            for (int nj = 0; nj < 2; nj++)
                wmma::store_matrix_sync(stage + mi * 16 * 36 + nj * 16, acc[mi][nj], 36, wmma::mem_row_major);
        __syncwarp();
        int lane = tid & 31;
        #pragma unroll
        for (int it = 0; it < 8; it++) {
            int j = it * 32 + lane;
            int r = j >> 3, c4 = j & 7;
            float4 v = *reinterpret_cast<const float4*>(stage + r * 36 + c4 * 4);
            uint2 h, l;
            split4(v, h, l);
            size_t go = (size_t)(m0 + wm * 32 + r) * ldc + ccol0 + wn * 32 + c4 * 4;
            *reinterpret_cast<uint2*>(Chi + go) = h;
            *reinterpret_cast<uint2*>(Clo + go) = l;
        }
    }
}

__global__ __launch_bounds__(256) void gemm_srcdst(
    const bf16* __restrict__ h_hi, const bf16* __restrict__ h_lo,
    const bf16* __restrict__ Ws_hi, const bf16* __restrict__ Ws_lo,
    const float* __restrict__ bsrc,
    const bf16* __restrict__ Wd_hi, const bf16* __restrict__ Wd_lo,
    const float* __restrict__ bdst,
    float* __restrict__ fs, float* __restrict__ fd)
{
    int m0 = blockIdx.x * BM;
    int y = blockIdx.y;
    int col0 = (y & 1) * 64;
    if (y < 2)
        gemm_core<128, false, false>(h_hi, h_lo, 128, Ws_hi, Ws_lo, 128, bsrc,
                                     fs, nullptr, nullptr, 128, col0, m0);
    else
        gemm_core<128, false, false>(h_hi, h_lo, 128, Wd_hi, Wd_lo, 128, bdst,
                                     fd, nullptr, nullptr, 128, col0, m0);
}

__global__ __launch_bounds__(256) void gemm_ffn1(
    const bf16* __restrict__ h1_hi, const bf16* __restrict__ h1_lo,
    const bf16* __restrict__ W1_hi, const bf16* __restrict__ W1_lo,
    const float* __restrict__ bf1,
    bf16* __restrict__ t_hi, bf16* __restrict__ t_lo)
{
    gemm_core<128, true, true>(h1_hi, h1_lo, 128, W1_hi, W1_lo, 256, bf1,
                               nullptr, t_hi, t_lo, 256, blockIdx.y * 64, blockIdx.x * BM);
}

__global__ __launch_bounds__(256) void gemm_ffn2(
    const bf16* __restrict__ t_hi, const bf16* __restrict__ t_lo,
    const bf16* __restrict__ W2_hi, const bf16* __restrict__ W2_lo,
    const float* __restrict__ bf2, float* __restrict__ z)
{
    gemm_core<256, false, false>(t_hi, t_lo, 256, W2_hi, W2_lo, 128, bf2,
                                 z, nullptr, nullptr, 128, blockIdx.y * 64, blockIdx.x * BM);
}

// ---------------- CSR edge aggregation: one warp per dst node ----------------
// fd[d] loaded once; numerator + denom accumulate in registers; plain stores.
// Softmax max-subtraction dropped (logits O(1), softmax shift-invariant).
__global__ __launch_bounds__(256) void edge_agg(
    const float* __restrict__ fs, const float* __restrict__ fd,
    const int* __restrict__ eoff, const int* __restrict__ ecnt,
    const int* __restrict__ esrc, const float* __restrict__ attn,
    float* __restrict__ denom, float* __restrict__ rst)
{
    int d = blockIdx.x * 8 + (threadIdx.x >> 5);
    if (d >= NN) return;
    int lane = threadIdx.x & 31;

    float4 va = reinterpret_cast<const float4*>(attn)[lane];
    float4 vd = reinterpret_cast<const float4*>(fd)[(size_t)d * 32 + lane];

    int start = eoff[d];
    int cnt = ecnt[d];

    float4 acc = make_float4(0.f, 0.f, 0.f, 0.f);
    float den = 0.0f;

    for (int i = 0; i < cnt; i++) {
        int s = __ldg(esrc + start + i);
        float4 vs = reinterpret_cast<const float4*>(fs)[(size_t)s * 32 + lane];

        float x, sum = 0.0f;
        x = vs.x + vd.x; x = (x > 0.f) ? x : NEG_SLOPE * x; sum += x * va.x;
        x = vs.y + vd.y; x = (x > 0.f) ? x : NEG_SLOPE * x; sum += x * va.y;
        x = vs.z + vd.z; x = (x > 0.f) ? x : NEG_SLOPE * x; sum += x * va.z;
        x = vs.w + vd.w; x = (x > 0.f) ? x : NEG_SLOPE * x; sum += x * va.w;

        sum += __shfl_xor_sync(0xffffffffu, sum, 4);
        sum += __shfl_xor_sync(0xffffffffu, sum, 2);
        sum += __shfl_xor_sync(0xffffffffu, sum, 1);

        float a = __expf(sum);
        acc.x += vs.x * a; acc.y += vs.y * a;
        acc.z += vs.z * a; acc.w += vs.w * a;
        den += a;
    }

    reinterpret_cast<float4*>(rst)[(size_t)d * 32 + lane] = acc;
    if ((lane & 7) == 0)
        denom[(size_t)d * 4 + (lane >> 3)] = den;
}

// ---------------- LN1: normalize by denom, residual, LN; emits fp32 + planes ----
__global__ __launch_bounds__(256) void ln1_kernel(
    const float* __restrict__ rst, const float* __restrict__ denom,
    const float* __restrict__ resid,
    const float* __restrict__ g, const float* __restrict__ b,
    float* __restrict__ out, bf16* __restrict__ out_hi, bf16* __restrict__ out_lo)
{
    int row = blockIdx.x * 8 + (threadIdx.x >> 5);
    if (row >= NPAD) return;
    int lane = threadIdx.x & 31;

    if (row >= NN) {
        uint2 zz = make_uint2(0u, 0u);
        reinterpret_cast<uint2*>(out_hi)[(size_t)row * 32 + lane] = zz;
        reinterpret_cast<uint2*>(out_lo)[(size_t)row * 32 + lane] = zz;
        return;
    }

    float den = denom[(size_t)row * 4 + (lane >> 3)];
    den = (den == 0.0f) ? 1.0f : den;
    float inv = 1.0f / den;

    float4 v = reinterpret_cast<const float4*>(rst)[(size_t)row * 32 + lane];
    float4 r = reinterpret_cast<const float4*>(resid)[(size_t)row * 32 + lane];
    v.x = v.x * inv + r.x; v.y = v.y * inv + r.y;
    v.z = v.z * inv + r.z; v.w = v.w * inv + r.w;

    float s1 = v.x + v.y + v.z + v.w;
    float s2 = v.x * v.x + v.y * v.y + v.z * v.z + v.w * v.w;
    #pragma unroll
    for (int off = 16; off > 0; off >>= 1) {
        s1 += __shfl_xor_sync(0xffffffffu, s1, off);
        s2 += __shfl_xor_sync(0xffffffffu, s2, off);
    }
    float mu = s1 * (1.0f / HID);
    float var = s2 * (1.0f / HID) - mu * mu;
    float rstd = rsqrtf(var + LN_EPS);

    float4 gg = reinterpret_cast<const float4*>(g)[lane];
    float4 bb = reinterpret_cast<const float4*>(b)[lane];
    float4 o;
    o.x = (v.x - mu) * rstd * gg.x + bb.x;
    o.y = (v.y - mu) * rstd * gg.y + bb.y;
    o.z = (v.z - mu) * rstd * gg.z + bb.z;
    o.w = (v.w - mu) * rstd * gg.w + bb.w;
    reinterpret_cast<float4*>(out)[(size_t)row * 32 + lane] = o;

    uint2 h, l;
    split4(o, h, l);
    reinterpret_cast<uint2*>(out_hi)[(size_t)row * 32 + lane] = h;
    reinterpret_cast<uint2*>(out_lo)[(size_t)row * 32 + lane] = l;
}

// ---------------- LN2 ----------------
__global__ __launch_bounds__(256) void ln2_kernel(
    const float* __restrict__ x, const float* __restrict__ resid,
    const float* __restrict__ g, const float* __restrict__ b,
    float* __restrict__ out)
{
    int row = blockIdx.x * 8 + (threadIdx.x >> 5);
    if (row >= NN) return;
    int lane = threadIdx.x & 31;

    float4 v = reinterpret_cast<const float4*>(x)[(size_t)row * 32 + lane];
    float4 r = reinterpret_cast<const float4*>(resid)[(size_t)row * 32 + lane];
    v.x += r.x; v.y += r.y; v.z += r.z; v.w += r.w;

    float s1 = v.x + v.y + v.z + v.w;
    float s2 = v.x * v.x + v.y * v.y + v.z * v.z + v.w * v.w;
    #pragma unroll
    for (int off = 16; off > 0; off >>= 1) {
        s1 += __shfl_xor_sync(0xffffffffu, s1, off);
        s2 += __shfl_xor_sync(0xffffffffu, s2, off);
    }
    float mu = s1 * (1.0f / HID);
    float var = s2 * (1.0f / HID) - mu * mu;
    float rstd = rsqrtf(var + LN_EPS);

    float4 gg = reinterpret_cast<const float4*>(g)[lane];
    float4 bb = reinterpret_cast<const float4*>(b)[lane];
    float4 o;
    o.x = (v.x - mu) * rstd * gg.x + bb.x;
    o.y = (v.y - mu) * rstd * gg.y + bb.y;
    o.z = (v.z - mu) * rstd * gg.z + bb.z;
    o.w = (v.w - mu) * rstd * gg.w + bb.w;
    reinterpret_cast<float4*>(out)[(size_t)row * 32 + lane] = o;
}

// ---------------- launcher ----------------
extern "C" void kernel_launch(void* const* d_in, const int* in_sizes, int n_in,
                              void* d_out, int out_size)
{
    const float* h    = (const float*)d_in[0];
    const int*   src  = (const int*)  d_in[1];
    const int*   dst  = (const int*)  d_in[2];
    const float* Wsrc = (const float*)d_in[3];
    const float* bsrc = (const float*)d_in[4];
    const float* Wdst = (const float*)d_in[5];
    const float* bdst = (const float*)d_in[6];
    const float* attn = (const float*)d_in[7];
    const float* W1   = (const float*)d_in[8];
    const float* bf1  = (const float*)d_in[9];
    const float* W2   = (const float*)d_in[10];
    const float* bf2  = (const float*)d_in[11];
    const float* g1   = (const float*)d_in[12];
    const float* be1  = (const float*)d_in[13];
    const float* g2   = (const float*)d_in[14];
    const float* be2  = (const float*)d_in[15];
    float* out = (float*)d_out;

    float *fs, *fd, *denom, *rst, *h1, *z;
    int *ecnt, *eoff, *cursor, *bsum, *esrc;
    bf16 *h_hi, *h_lo, *h1_hi, *h1_lo, *t_hi, *t_lo;
    bf16 *Ws_hi, *Ws_lo, *Wd_hi, *Wd_lo, *W1_hi, *W1_lo, *W2_hi, *W2_lo;
    cudaGetSymbolAddress((void**)&fs,    g_fs);
    cudaGetSymbolAddress((void**)&fd,    g_fd);
    cudaGetSymbolAddress((void**)&denom, g_denom);
    cudaGetSymbolAddress((void**)&rst,   g_rst);
    cudaGetSymbolAddress((void**)&h1,    g_h1);
    cudaGetSymbolAddress((void**)&z,     g_z);
    cudaGetSymbolAddress((void**)&ecnt,  g_ecnt);
    cudaGetSymbolAddress((void**)&eoff,  g_eoff);
    cudaGetSymbolAddress((void**)&cursor,g_cursor);
    cudaGetSymbolAddress((void**)&bsum,  g_bsum);
    cudaGetSymbolAddress((void**)&esrc,  g_esrc);
    cudaGetSymbolAddress((void**)&h_hi,  g_h_hi);
    cudaGetSymbolAddress((void**)&h_lo,  g_h_lo);
    cudaGetSymbolAddress((void**)&h1_hi, g_h1_hi);
    cudaGetSymbolAddress((void**)&h1_lo, g_h1_lo);
    cudaGetSymbolAddress((void**)&t_hi,  g_t_hi);
    cudaGetSymbolAddress((void**)&t_lo,  g_t_lo);
    cudaGetSymbolAddress((void**)&Ws_hi, g_Wsrc_hi);
    cudaGetSymbolAddress((void**)&Ws_lo, g_Wsrc_lo);
    cudaGetSymbolAddress((void**)&Wd_hi, g_Wdst_hi);
    cudaGetSymbolAddress((void**)&Wd_lo, g_Wdst_lo);
    cudaGetSymbolAddress((void**)&W1_hi, g_W1_hi);
    cudaGetSymbolAddress((void**)&W1_lo, g_W1_lo);
    cudaGetSymbolAddress((void**)&W2_hi, g_W2_hi);
    cudaGetSymbolAddress((void**)&W2_lo, g_W2_lo);

    cudaFuncSetAttribute(gemm_srcdst, cudaFuncAttributeMaxDynamicSharedMemorySize, SM_BYTES);
    cudaFuncSetAttribute(gemm_ffn1,   cudaFuncAttributeMaxDynamicSharedMemorySize, SM_BYTES);
    cudaFuncSetAttribute(gemm_ffn2,   cudaFuncAttributeMaxDynamicSharedMemorySize, SM_BYTES);

    // ---- CSR build (independent of GEMMs) ----
    const int NB = (NN + 511) / 512;   // 98 blocks
    cudaMemsetAsync(ecnt, 0, NN * sizeof(int));
    hist_kernel<<<(EE + 255) / 256, 256>>>(dst, ecnt);
    scan1<<<NB, 512>>>(ecnt, eoff, bsum);
    scan2<<<1, 128>>>(bsum, NB);
    scan3<<<NB, 512>>>(eoff, bsum, cursor);
    scatter_kernel<<<(EE + 255) / 256, 256>>>(src, dst, cursor, esrc);

    // ---- splits ----
    split_h<<<(NPAD * 32 + 255) / 256, 256>>>(h, h_hi, h_lo);
    split_weights<<<(24576 + 255) / 256, 256>>>(Wsrc, Wdst, W1, W2,
                                                Ws_hi, Ws_lo, Wd_hi, Wd_lo,
                                                W1_hi, W1_lo, W2_hi, W2_lo);

    const int GXM = NPAD / BM;   // 391

    gemm_srcdst<<<dim3(GXM, 4), 256, SM_BYTES>>>(h_hi, h_lo, Ws_hi, Ws_lo, bsrc,
                                                 Wd_hi, Wd_lo, bdst, fs, fd);

    edge_agg<<<(NN + 7) / 8, 256>>>(fs, fd, eoff, ecnt, esrc, attn, denom, rst);

    int lblocks1 = (NPAD + 7) / 8;
    ln1_kernel<<<lblocks1, 256>>>(rst, denom, h, g1, be1, h1, h1_hi, h1_lo);

    gemm_ffn1<<<dim3(GXM, 4), 256, SM_BYTES>>>(h1_hi, h1_lo, W1_hi, W1_lo, bf1, t_hi, t_lo);
    gemm_ffn2<<<dim3(GXM, 2), 256, SM_BYTES>>>(t_hi, t_lo, W2_hi, W2_lo, bf2, z);

    int lblocks = (NN + 7) / 8;
    ln2_kernel<<<lblocks, 256>>>(z, h1, g2, be2, out);
}

// round 7
// speedup vs baseline: 2.0059x; 1.0076x over previous
#include <cuda_runtime.h>
#include <cuda_bf16.h>
#include <mma.h>
#include <math.h>

using namespace nvcuda;
typedef __nv_bfloat16 bf16;

// ---------------- problem constants ----------------
#define NN 50000
#define NPAD 50048            // 391 * 128
#define EE 600000
#define HID 128
#define HEADS 4
#define NEG_SLOPE 0.2f
#define LN_EPS 1e-5f

// GEMM v3 tile geometry: BM=128, BN=128, BK=32, 2-stage cp.async pipeline
#define LDA_SM 48             // 32 + 16 pad (96B row stride: 16B-aligned, conflict-free)
#define LDB_SM 136            // 128 + 8 pad (272B row stride)
#define A_ST (128 * LDA_SM)   // 6144 bf16 per plane per stage
#define B_ST (32 * LDB_SM)    // 4352 bf16 per plane per stage
#define SM_ELEMS (4 * A_ST + 4 * B_ST)          // 41984 bf16
#define SM_BYTES (SM_ELEMS * 2 + 16 * 128 * 4)  // 92160

// ---------------- scratch ----------------
__device__ float g_fs[NPAD * HID];
__device__ float g_fd[NPAD * HID];
__device__ float g_denom[NN * HEADS];
__device__ float g_rst[NN * HID];
__device__ float g_h1[NPAD * HID];
__device__ float g_z[NPAD * HID];
// CSR scratch
__device__ int g_ecnt[NN];
__device__ int g_eoff[NN];
__device__ int g_cursor[NN];
__device__ int g_bsum[128];
__device__ int g_esrc[EE];
// bf16 hi/lo planes
__device__ bf16 g_h_hi[NPAD * HID];
__device__ bf16 g_h_lo[NPAD * HID];
__device__ bf16 g_h1_hi[NPAD * HID];
__device__ bf16 g_h1_lo[NPAD * HID];
__device__ bf16 g_t_hi[NPAD * 2 * HID];
__device__ bf16 g_t_lo[NPAD * 2 * HID];
__device__ bf16 g_Wsrc_hi[HID * HID];
__device__ bf16 g_Wsrc_lo[HID * HID];
__device__ bf16 g_Wdst_hi[HID * HID];
__device__ bf16 g_Wdst_lo[HID * HID];
__device__ bf16 g_W1_hi[HID * 2 * HID];
__device__ bf16 g_W1_lo[HID * 2 * HID];
__device__ bf16 g_W2_hi[2 * HID * HID];
__device__ bf16 g_W2_lo[2 * HID * HID];

// ---------------- cp.async helpers ----------------
__device__ __forceinline__ void cp16(void* smem, const void* gmem) {
    unsigned saddr = (unsigned)__cvta_generic_to_shared(smem);
    asm volatile("cp.async.cg.shared.global [%0], [%1], 16;" :: "r"(saddr), "l"(gmem));
}
__device__ __forceinline__ void cp_commit() {
    asm volatile("cp.async.commit_group;" ::: "memory");
}
template <int N>
__device__ __forceinline__ void cp_wait() {
    asm volatile("cp.async.wait_group %0;" :: "n"(N) : "memory");
}

// ---------------- split helper ----------------
__device__ __forceinline__ void split4(float4 v, uint2& hi, uint2& lo) {
    bf16 h0 = __float2bfloat16(v.x), h1 = __float2bfloat16(v.y);
    bf16 h2 = __float2bfloat16(v.z), h3 = __float2bfloat16(v.w);
    bf16 l0 = __float2bfloat16(v.x - __bfloat162float(h0));
    bf16 l1 = __float2bfloat16(v.y - __bfloat162float(h1));
    bf16 l2 = __float2bfloat16(v.z - __bfloat162float(h2));
    bf16 l3 = __float2bfloat16(v.w - __bfloat162float(h3));
    hi.x = (unsigned)__bfloat16_as_ushort(h0) | ((unsigned)__bfloat16_as_ushort(h1) << 16);
    hi.y = (unsigned)__bfloat16_as_ushort(h2) | ((unsigned)__bfloat16_as_ushort(h3) << 16);
    lo.x = (unsigned)__bfloat16_as_ushort(l0) | ((unsigned)__bfloat16_as_ushort(l1) << 16);
    lo.y = (unsigned)__bfloat16_as_ushort(l2) | ((unsigned)__bfloat16_as_ushort(l3) << 16);
}

// ---------------- split kernels ----------------
__global__ void split_weights(
    const float* __restrict__ Ws, const float* __restrict__ Wd,
    const float* __restrict__ W1, const float* __restrict__ W2,
    bf16* __restrict__ Ws_hi, bf16* __restrict__ Ws_lo,
    bf16* __restrict__ Wd_hi, bf16* __restrict__ Wd_lo,
    bf16* __restrict__ W1_hi, bf16* __restrict__ W1_lo,
    bf16* __restrict__ W2_hi, bf16* __restrict__ W2_lo)
{
    int i = blockIdx.x * blockDim.x + threadIdx.x;
    const float* s; bf16 *ph, *pl; int j = i;
    if (j < 4096)        { s = Ws; ph = Ws_hi; pl = Ws_lo; }
    else if (j < 8192)   { j -= 4096;  s = Wd; ph = Wd_hi; pl = Wd_lo; }
    else if (j < 16384)  { j -= 8192;  s = W1; ph = W1_hi; pl = W1_lo; }
    else if (j < 24576)  { j -= 16384; s = W2; ph = W2_hi; pl = W2_lo; }
    else return;
    float4 v = reinterpret_cast<const float4*>(s)[j];
    uint2 h, l;
    split4(v, h, l);
    reinterpret_cast<uint2*>(ph)[j] = h;
    reinterpret_cast<uint2*>(pl)[j] = l;
}

__global__ void split_h(const float* __restrict__ src, bf16* __restrict__ hi,
                        bf16* __restrict__ lo) {
    int i = blockIdx.x * blockDim.x + threadIdx.x;
    if (i >= NPAD * 32) return;
    int row = i >> 5;
    float4 v = make_float4(0.f, 0.f, 0.f, 0.f);
    if (row < NN) v = reinterpret_cast<const float4*>(src)[i];
    uint2 h, l;
    split4(v, h, l);
    reinterpret_cast<uint2*>(hi)[i] = h;
    reinterpret_cast<uint2*>(lo)[i] = l;
}

// ---------------- CSR build ----------------
__global__ void hist_kernel(const int* __restrict__ dst, int* __restrict__ cnt) {
    int e = blockIdx.x * blockDim.x + threadIdx.x;
    if (e < EE) atomicAdd(&cnt[dst[e]], 1);
}

__global__ void scan1(const int* __restrict__ cnt, int* __restrict__ excl,
                      int* __restrict__ bsum) {
    __shared__ int sh[512];
    int i = blockIdx.x * 512 + threadIdx.x;
    int v = (i < NN) ? cnt[i] : 0;
    sh[threadIdx.x] = v;
    __syncthreads();
    #pragma unroll
    for (int off = 1; off < 512; off <<= 1) {
        int t = (threadIdx.x >= off) ? sh[threadIdx.x - off] : 0;
        __syncthreads();
        sh[threadIdx.x] += t;
        __syncthreads();
    }
    if (i < NN) excl[i] = sh[threadIdx.x] - v;
    if (threadIdx.x == 511) bsum[blockIdx.x] = sh[511];
}

__global__ void scan2(int* __restrict__ bsum, int nb) {
    __shared__ int sh[128];
    int v = (threadIdx.x < nb) ? bsum[threadIdx.x] : 0;
    sh[threadIdx.x] = v;
    __syncthreads();
    #pragma unroll
    for (int off = 1; off < 128; off <<= 1) {
        int t = (threadIdx.x >= off) ? sh[threadIdx.x - off] : 0;
        __syncthreads();
        sh[threadIdx.x] += t;
        __syncthreads();
    }
    if (threadIdx.x < nb) bsum[threadIdx.x] = sh[threadIdx.x] - v;
}

__global__ void scan3(int* __restrict__ excl, const int* __restrict__ bsum,
                      int* __restrict__ cursor) {
    int i = blockIdx.x * 512 + threadIdx.x;
    if (i < NN) {
        int v = excl[i] + bsum[blockIdx.x];
        excl[i] = v;
        cursor[i] = v;
    }
}

__global__ void scatter_kernel(const int* __restrict__ src, const int* __restrict__ dst,
                               int* __restrict__ cursor, int* __restrict__ esrc) {
    int e = blockIdx.x * blockDim.x + threadIdx.x;
    if (e >= EE) return;
    int pos = atomicAdd(&cursor[dst[e]], 1);
    esrc[pos] = src[e];
}

// ---------------- WMMA split-bf16 GEMM core v3 ----------------
// C(128x128 tile) = A@B + bias. 2-stage cp.async pipeline, BK=32.
// 8 warps: 4(m) x 2(n); warp tile 32 rows x 64 cols.
template <int KTOT, bool GELU, bool SPLIT_OUT>
__device__ __forceinline__ void gemm_core(
    const bf16* __restrict__ Ah_g, const bf16* __restrict__ Al_g, int lda,
    const bf16* __restrict__ Bh_g, const bf16* __restrict__ Bl_g, int ldb,
    const float* __restrict__ bias,
    float* __restrict__ C, bf16* __restrict__ Chi, bf16* __restrict__ Clo,
    int ldc, int ccol0, int m0)
{
    extern __shared__ bf16 sm[];
    bf16* AhS[2] = { sm,            sm + A_ST };
    bf16* AlS[2] = { sm + 2 * A_ST, sm + 3 * A_ST };
    bf16* BhS[2] = { sm + 4 * A_ST,             sm + 4 * A_ST + B_ST };
    bf16* BlS[2] = { sm + 4 * A_ST + 2 * B_ST,  sm + 4 * A_ST + 3 * B_ST };
    float* bias_sm = (float*)(sm + SM_ELEMS);   // [16][128]

    const int tid = threadIdx.x;
    const int wid = tid >> 5;
    const int wm = wid >> 1;          // 0..3 -> 32 rows each
    const int wn = wid & 1;           // 0..1 -> 64 cols each

    constexpr int KC = KTOT / 32;

    // stage loader: A 128x32, B 32x128, both planes, 16B cp.async
    auto load_stage = [&](int kc, int st) {
        #pragma unroll
        for (int i = tid; i < 512; i += 256) {
            int r = i >> 2, c8 = (i & 3) * 8;
            size_t go = (size_t)(m0 + r) * lda + kc * 32 + c8;
            cp16(AhS[st] + r * LDA_SM + c8, Ah_g + go);
            cp16(AlS[st] + r * LDA_SM + c8, Al_g + go);
        }
        #pragma unroll
        for (int i = tid; i < 512; i += 256) {
            int r = i >> 4, c8 = (i & 15) * 8;
            size_t go = (size_t)(kc * 32 + r) * ldb + ccol0 + c8;
            cp16(BhS[st] + r * LDB_SM + c8, Bh_g + go);
            cp16(BlS[st] + r * LDB_SM + c8, Bl_g + go);
        }
        cp_commit();
    };

    load_stage(0, 0);

    // bias tile while stage-0 loads fly
    for (int i = tid; i < 16 * 128; i += 256)
        bias_sm[i] = bias[ccol0 + (i & 127)];
    __syncthreads();

    wmma::fragment<wmma::accumulator, 16, 16, 16, float> acc[2][4];
    #pragma unroll
    for (int mi = 0; mi < 2; mi++)
        #pragma unroll
        for (int nj = 0; nj < 4; nj++)
            wmma::load_matrix_sync(acc[mi][nj], bias_sm + wn * 64 + nj * 16, 128, wmma::mem_row_major);

    #pragma unroll
    for (int kc = 0; kc < KC; kc++) {
        if (kc + 1 < KC) load_stage(kc + 1, (kc + 1) & 1);
        if (kc + 1 < KC) cp_wait<1>(); else cp_wait<0>();
        __syncthreads();

        const int st = kc & 1;
        #pragma unroll
        for (int kk = 0; kk < 2; kk++) {
            wmma::fragment<wmma::matrix_a, 16, 16, 16, bf16, wmma::row_major> ah[2], al[2];
            wmma::fragment<wmma::matrix_b, 16, 16, 16, bf16, wmma::row_major> bh[4], bl[4];
            #pragma unroll
            for (int mi = 0; mi < 2; mi++) {
                const bf16* ap = AhS[st] + (wm * 32 + mi * 16) * LDA_SM + kk * 16;
                const bf16* alp = AlS[st] + (wm * 32 + mi * 16) * LDA_SM + kk * 16;
                wmma::load_matrix_sync(ah[mi], ap, LDA_SM);
                wmma::load_matrix_sync(al[mi], alp, LDA_SM);
            }
            #pragma unroll
            for (int nj = 0; nj < 4; nj++) {
                const bf16* bp = BhS[st] + (kk * 16) * LDB_SM + wn * 64 + nj * 16;
                const bf16* blp = BlS[st] + (kk * 16) * LDB_SM + wn * 64 + nj * 16;
                wmma::load_matrix_sync(bh[nj], bp, LDB_SM);
                wmma::load_matrix_sync(bl[nj], blp, LDB_SM);
            }
            #pragma unroll
            for (int mi = 0; mi < 2; mi++)
                #pragma unroll
                for (int nj = 0; nj < 4; nj++) {
                    wmma::mma_sync(acc[mi][nj], ah[mi], bh[nj], acc[mi][nj]);
                    wmma::mma_sync(acc[mi][nj], ah[mi], bl[nj], acc[mi][nj]);
                    wmma::mma_sync(acc[mi][nj], al[mi], bh[nj], acc[mi][nj]);
                }
        }
        __syncthreads();
    }

    if (GELU) {
        #pragma unroll
        for (int mi = 0; mi < 2; mi++)
            #pragma unroll
            for (int nj = 0; nj < 4; nj++)
                #pragma unroll
                for (int i = 0; i < acc[mi][nj].num_elements; i++) {
                    float x = acc[mi][nj].x[i];
                    acc[mi][nj].x[i] = 0.5f * x * (1.0f + erff(x * 0.70710678118654752f));
                }
    }

    if (!SPLIT_OUT) {
        #pragma unroll
        for (int mi = 0; mi < 2; mi++)
            #pragma unroll
            for (int nj = 0; nj < 4; nj++) {
                float* cp = C + (size_t)(m0 + wm * 32 + mi * 16) * ldc + ccol0 + wn * 64 + nj * 16;
                wmma::store_matrix_sync(cp, acc[mi][nj], ldc, wmma::mem_row_major);
            }
    } else {
        // per-warp staging: 32 x 68 fp32, then split -> bf16 planes
        float* stage = (float*)sm + wid * (32 * 68);
        #pragma unroll
        for (int mi = 0; mi < 2; mi++)
            #pragma unroll
            for (int nj = 0; nj < 4; nj++)
                wmma::store_matrix_sync(stage + mi * 16 * 68 + nj * 16, acc[mi][nj], 68, wmma::mem_row_major);
        __syncwarp();
        int lane = tid & 31;
        #pragma unroll
        for (int it = 0; it < 16; it++) {
            int j = it * 32 + lane;        // 512 items: 32 rows x 16 col-quads
            int r = j >> 4, c4 = j & 15;
            float4 v = *reinterpret_cast<const float4*>(stage + r * 68 + c4 * 4);
            uint2 h, l;
            split4(v, h, l);
            size_t go = (size_t)(m0 + wm * 32 + r) * ldc + ccol0 + wn * 64 + c4 * 4;
            *reinterpret_cast<uint2*>(Chi + go) = h;
            *reinterpret_cast<uint2*>(Clo + go) = l;
        }
    }
}

__global__ __launch_bounds__(256, 2) void gemm_srcdst(
    const bf16* __restrict__ h_hi, const bf16* __restrict__ h_lo,
    const bf16* __restrict__ Ws_hi, const bf16* __restrict__ Ws_lo,
    const float* __restrict__ bsrc,
    const bf16* __restrict__ Wd_hi, const bf16* __restrict__ Wd_lo,
    const float* __restrict__ bdst,
    float* __restrict__ fs, float* __restrict__ fd)
{
    int m0 = blockIdx.x * 128;
    if (blockIdx.y == 0)
        gemm_core<128, false, false>(h_hi, h_lo, 128, Ws_hi, Ws_lo, 128, bsrc,
                                     fs, nullptr, nullptr, 128, 0, m0);
    else
        gemm_core<128, false, false>(h_hi, h_lo, 128, Wd_hi, Wd_lo, 128, bdst,
                                     fd, nullptr, nullptr, 128, 0, m0);
}

__global__ __launch_bounds__(256, 2) void gemm_ffn1(
    const bf16* __restrict__ h1_hi, const bf16* __restrict__ h1_lo,
    const bf16* __restrict__ W1_hi, const bf16* __restrict__ W1_lo,
    const float* __restrict__ bf1,
    bf16* __restrict__ t_hi, bf16* __restrict__ t_lo)
{
    gemm_core<128, true, true>(h1_hi, h1_lo, 128, W1_hi, W1_lo, 256, bf1,
                               nullptr, t_hi, t_lo, 256, blockIdx.y * 128, blockIdx.x * 128);
}

__global__ __launch_bounds__(256, 2) void gemm_ffn2(
    const bf16* __restrict__ t_hi, const bf16* __restrict__ t_lo,
    const bf16* __restrict__ W2_hi, const bf16* __restrict__ W2_lo,
    const float* __restrict__ bf2, float* __restrict__ z)
{
    gemm_core<256, false, false>(t_hi, t_lo, 256, W2_hi, W2_lo, 128, bf2,
                                 z, nullptr, nullptr, 128, 0, blockIdx.x * 128);
}

// ---------------- CSR edge aggregation: one warp per dst node ----------------
__global__ __launch_bounds__(256) void edge_agg(
    const float* __restrict__ fs, const float* __restrict__ fd,
    const int* __restrict__ eoff, const int* __restrict__ ecnt,
    const int* __restrict__ esrc, const float* __restrict__ attn,
    float* __restrict__ denom, float* __restrict__ rst)
{
    int d = blockIdx.x * 8 + (threadIdx.x >> 5);
    if (d >= NN) return;
    int lane = threadIdx.x & 31;

    float4 va = reinterpret_cast<const float4*>(attn)[lane];
    float4 vd = reinterpret_cast<const float4*>(fd)[(size_t)d * 32 + lane];

    int start = eoff[d];
    int cnt = ecnt[d];

    float4 acc = make_float4(0.f, 0.f, 0.f, 0.f);
    float den = 0.0f;

    for (int i = 0; i < cnt; i++) {
        int s = __ldg(esrc + start + i);
        float4 vs = reinterpret_cast<const float4*>(fs)[(size_t)s * 32 + lane];

        float x, sum = 0.0f;
        x = vs.x + vd.x; x = (x > 0.f) ? x : NEG_SLOPE * x; sum += x * va.x;
        x = vs.y + vd.y; x = (x > 0.f) ? x : NEG_SLOPE * x; sum += x * va.y;
        x = vs.z + vd.z; x = (x > 0.f) ? x : NEG_SLOPE * x; sum += x * va.z;
        x = vs.w + vd.w; x = (x > 0.f) ? x : NEG_SLOPE * x; sum += x * va.w;

        sum += __shfl_xor_sync(0xffffffffu, sum, 4);
        sum += __shfl_xor_sync(0xffffffffu, sum, 2);
        sum += __shfl_xor_sync(0xffffffffu, sum, 1);

        float a = __expf(sum);
        acc.x += vs.x * a; acc.y += vs.y * a;
        acc.z += vs.z * a; acc.w += vs.w * a;
        den += a;
    }

    reinterpret_cast<float4*>(rst)[(size_t)d * 32 + lane] = acc;
    if ((lane & 7) == 0)
        denom[(size_t)d * 4 + (lane >> 3)] = den;
}

// ---------------- LN1 ----------------
__global__ __launch_bounds__(256) void ln1_kernel(
    const float* __restrict__ rst, const float* __restrict__ denom,
    const float* __restrict__ resid,
    const float* __restrict__ g, const float* __restrict__ b,
    float* __restrict__ out, bf16* __restrict__ out_hi, bf16* __restrict__ out_lo)
{
    int row = blockIdx.x * 8 + (threadIdx.x >> 5);
    if (row >= NPAD) return;
    int lane = threadIdx.x & 31;

    if (row >= NN) {
        uint2 zz = make_uint2(0u, 0u);
        reinterpret_cast<uint2*>(out_hi)[(size_t)row * 32 + lane] = zz;
        reinterpret_cast<uint2*>(out_lo)[(size_t)row * 32 + lane] = zz;
        return;
    }

    float den = denom[(size_t)row * 4 + (lane >> 3)];
    den = (den == 0.0f) ? 1.0f : den;
    float inv = 1.0f / den;

    float4 v = reinterpret_cast<const float4*>(rst)[(size_t)row * 32 + lane];
    float4 r = reinterpret_cast<const float4*>(resid)[(size_t)row * 32 + lane];
    v.x = v.x * inv + r.x; v.y = v.y * inv + r.y;
    v.z = v.z * inv + r.z; v.w = v.w * inv + r.w;

    float s1 = v.x + v.y + v.z + v.w;
    float s2 = v.x * v.x + v.y * v.y + v.z * v.z + v.w * v.w;
    #pragma unroll
    for (int off = 16; off > 0; off >>= 1) {
        s1 += __shfl_xor_sync(0xffffffffu, s1, off);
        s2 += __shfl_xor_sync(0xffffffffu, s2, off);
    }
    float mu = s1 * (1.0f / HID);
    float var = s2 * (1.0f / HID) - mu * mu;
    float rstd = rsqrtf(var + LN_EPS);

    float4 gg = reinterpret_cast<const float4*>(g)[lane];
    float4 bb = reinterpret_cast<const float4*>(b)[lane];
    float4 o;
    o.x = (v.x - mu) * rstd * gg.x + bb.x;
    o.y = (v.y - mu) * rstd * gg.y + bb.y;
    o.z = (v.z - mu) * rstd * gg.z + bb.z;
    o.w = (v.w - mu) * rstd * gg.w + bb.w;
    reinterpret_cast<float4*>(out)[(size_t)row * 32 + lane] = o;

    uint2 h, l;
    split4(o, h, l);
    reinterpret_cast<uint2*>(out_hi)[(size_t)row * 32 + lane] = h;
    reinterpret_cast<uint2*>(out_lo)[(size_t)row * 32 + lane] = l;
}

// ---------------- LN2 ----------------
__global__ __launch_bounds__(256) void ln2_kernel(
    const float* __restrict__ x, const float* __restrict__ resid,
    const float* __restrict__ g, const float* __restrict__ b,
    float* __restrict__ out)
{
    int row = blockIdx.x * 8 + (threadIdx.x >> 5);
    if (row >= NN) return;
    int lane = threadIdx.x & 31;

    float4 v = reinterpret_cast<const float4*>(x)[(size_t)row * 32 + lane];
    float4 r = reinterpret_cast<const float4*>(resid)[(size_t)row * 32 + lane];
    v.x += r.x; v.y += r.y; v.z += r.z; v.w += r.w;

    float s1 = v.x + v.y + v.z + v.w;
    float s2 = v.x * v.x + v.y * v.y + v.z * v.z + v.w * v.w;
    #pragma unroll
    for (int off = 16; off > 0; off >>= 1) {
        s1 += __shfl_xor_sync(0xffffffffu, s1, off);
        s2 += __shfl_xor_sync(0xffffffffu, s2, off);
    }
    float mu = s1 * (1.0f / HID);
    float var = s2 * (1.0f / HID) - mu * mu;
    float rstd = rsqrtf(var + LN_EPS);

    float4 gg = reinterpret_cast<const float4*>(g)[lane];
    float4 bb = reinterpret_cast<const float4*>(b)[lane];
    float4 o;
    o.x = (v.x - mu) * rstd * gg.x + bb.x;
    o.y = (v.y - mu) * rstd * gg.y + bb.y;
    o.z = (v.z - mu) * rstd * gg.z + bb.z;
    o.w = (v.w - mu) * rstd * gg.w + bb.w;
    reinterpret_cast<float4*>(out)[(size_t)row * 32 + lane] = o;
}

// ---------------- launcher ----------------
extern "C" void kernel_launch(void* const* d_in, const int* in_sizes, int n_in,
                              void* d_out, int out_size)
{
    const float* h    = (const float*)d_in[0];
    const int*   src  = (const int*)  d_in[1];
    const int*   dst  = (const int*)  d_in[2];
    const float* Wsrc = (const float*)d_in[3];
    const float* bsrc = (const float*)d_in[4];
    const float* Wdst = (const float*)d_in[5];
    const float* bdst = (const float*)d_in[6];
    const float* attn = (const float*)d_in[7];
    const float* W1   = (const float*)d_in[8];
    const float* bf1  = (const float*)d_in[9];
    const float* W2   = (const float*)d_in[10];
    const float* bf2  = (const float*)d_in[11];
    const float* g1   = (const float*)d_in[12];
    const float* be1  = (const float*)d_in[13];
    const float* g2   = (const float*)d_in[14];
    const float* be2  = (const float*)d_in[15];
    float* out = (float*)d_out;

    float *fs, *fd, *denom, *rst, *h1, *z;
    int *ecnt, *eoff, *cursor, *bsum, *esrc;
    bf16 *h_hi, *h_lo, *h1_hi, *h1_lo, *t_hi, *t_lo;
    bf16 *Ws_hi, *Ws_lo, *Wd_hi, *Wd_lo, *W1_hi, *W1_lo, *W2_hi, *W2_lo;
    cudaGetSymbolAddress((void**)&fs,    g_fs);
    cudaGetSymbolAddress((void**)&fd,    g_fd);
    cudaGetSymbolAddress((void**)&denom, g_denom);
    cudaGetSymbolAddress((void**)&rst,   g_rst);
    cudaGetSymbolAddress((void**)&h1,    g_h1);
    cudaGetSymbolAddress((void**)&z,     g_z);
    cudaGetSymbolAddress((void**)&ecnt,  g_ecnt);
    cudaGetSymbolAddress((void**)&eoff,  g_eoff);
    cudaGetSymbolAddress((void**)&cursor,g_cursor);
    cudaGetSymbolAddress((void**)&bsum,  g_bsum);
    cudaGetSymbolAddress((void**)&esrc,  g_esrc);
    cudaGetSymbolAddress((void**)&h_hi,  g_h_hi);
    cudaGetSymbolAddress((void**)&h_lo,  g_h_lo);
    cudaGetSymbolAddress((void**)&h1_hi, g_h1_hi);
    cudaGetSymbolAddress((void**)&h1_lo, g_h1_lo);
    cudaGetSymbolAddress((void**)&t_hi,  g_t_hi);
    cudaGetSymbolAddress((void**)&t_lo,  g_t_lo);
    cudaGetSymbolAddress((void**)&Ws_hi, g_Wsrc_hi);
    cudaGetSymbolAddress((void**)&Ws_lo, g_Wsrc_lo);
    cudaGetSymbolAddress((void**)&Wd_hi, g_Wdst_hi);
    cudaGetSymbolAddress((void**)&Wd_lo, g_Wdst_lo);
    cudaGetSymbolAddress((void**)&W1_hi, g_W1_hi);
    cudaGetSymbolAddress((void**)&W1_lo, g_W1_lo);
    cudaGetSymbolAddress((void**)&W2_hi, g_W2_hi);
    cudaGetSymbolAddress((void**)&W2_lo, g_W2_lo);

    cudaFuncSetAttribute(gemm_srcdst, cudaFuncAttributeMaxDynamicSharedMemorySize, SM_BYTES);
    cudaFuncSetAttribute(gemm_ffn1,   cudaFuncAttributeMaxDynamicSharedMemorySize, SM_BYTES);
    cudaFuncSetAttribute(gemm_ffn2,   cudaFuncAttributeMaxDynamicSharedMemorySize, SM_BYTES);

    // ---- CSR build ----
    const int NB = (NN + 511) / 512;
    cudaMemsetAsync(ecnt, 0, NN * sizeof(int));
    hist_kernel<<<(EE + 255) / 256, 256>>>(dst, ecnt);
    scan1<<<NB, 512>>>(ecnt, eoff, bsum);
    scan2<<<1, 128>>>(bsum, NB);
    scan3<<<NB, 512>>>(eoff, bsum, cursor);
    scatter_kernel<<<(EE + 255) / 256, 256>>>(src, dst, cursor, esrc);

    // ---- splits ----
    split_h<<<(NPAD * 32 + 255) / 256, 256>>>(h, h_hi, h_lo);
    split_weights<<<(24576 + 255) / 256, 256>>>(Wsrc, Wdst, W1, W2,
                                                Ws_hi, Ws_lo, Wd_hi, Wd_lo,
                                                W1_hi, W1_lo, W2_hi, W2_lo);

    const int GXM = NPAD / 128;   // 391

    gemm_srcdst<<<dim3(GXM, 2), 256, SM_BYTES>>>(h_hi, h_lo, Ws_hi, Ws_lo, bsrc,
                                                 Wd_hi, Wd_lo, bdst, fs, fd);

    edge_agg<<<(NN + 7) / 8, 256>>>(fs, fd, eoff, ecnt, esrc, attn, denom, rst);

    int lblocks1 = (NPAD + 7) / 8;
    ln1_kernel<<<lblocks1, 256>>>(rst, denom, h, g1, be1, h1, h1_hi, h1_lo);

    gemm_ffn1<<<dim3(GXM, 2), 256, SM_BYTES>>>(h1_hi, h1_lo, W1_hi, W1_lo, bf1, t_hi, t_lo);
    gemm_ffn2<<<dim3(GXM, 1), 256, SM_BYTES>>>(t_hi, t_lo, W2_hi, W2_lo, bf2, z);

    int lblocks = (NN + 7) / 8;
    ln2_kernel<<<lblocks, 256>>>(z, h1, g2, be2, out);
}

// round 8
// speedup vs baseline: 2.1361x; 1.0649x over previous
#include <cuda_runtime.h>
#include <cuda_bf16.h>
#include <mma.h>
#include <math.h>

using namespace nvcuda;
typedef __nv_bfloat16 bf16;

// ---------------- problem constants ----------------
#define NN 50000
#define NPAD 50048            // 391 * 128
#define EE 600000
#define HID 128
#define HEADS 4
#define NEG_SLOPE 0.2f
#define LN_EPS 1e-5f

// GEMM tile geometry: BM=128, BN=128, BK=32, 2-stage cp.async pipeline
#define LDA_SM 48
#define LDB_SM 136
#define A_ST (128 * LDA_SM)
#define B_ST (32 * LDB_SM)
#define SM_ELEMS (4 * A_ST + 4 * B_ST)
#define SM_BYTES (SM_ELEMS * 2 + 16 * 128 * 4)  // 92160 (also >= 128*132*4 for LN stage)

// ---------------- scratch ----------------
__device__ float g_fs[NPAD * HID];
__device__ float g_fd[NPAD * HID];
__device__ float g_h1[NPAD * HID];
// CSR scratch
__device__ int g_ecnt[NN];
__device__ int g_eoff[NN];
__device__ int g_cursor[NN];
__device__ int g_bsum[128];
__device__ int g_esrc[EE];
// bf16 hi/lo planes
__device__ bf16 g_h_hi[NPAD * HID];
__device__ bf16 g_h_lo[NPAD * HID];
__device__ bf16 g_h1_hi[NPAD * HID];
__device__ bf16 g_h1_lo[NPAD * HID];
__device__ bf16 g_t_hi[NPAD * 2 * HID];
__device__ bf16 g_t_lo[NPAD * 2 * HID];
__device__ bf16 g_Wsrc_hi[HID * HID];
__device__ bf16 g_Wsrc_lo[HID * HID];
__device__ bf16 g_Wdst_hi[HID * HID];
__device__ bf16 g_Wdst_lo[HID * HID];
__device__ bf16 g_W1_hi[HID * 2 * HID];
__device__ bf16 g_W1_lo[HID * 2 * HID];
__device__ bf16 g_W2_hi[2 * HID * HID];
__device__ bf16 g_W2_lo[2 * HID * HID];

// ---------------- cp.async helpers ----------------
__device__ __forceinline__ void cp16(void* smem, const void* gmem) {
    unsigned saddr = (unsigned)__cvta_generic_to_shared(smem);
    asm volatile("cp.async.cg.shared.global [%0], [%1], 16;" :: "r"(saddr), "l"(gmem));
}
__device__ __forceinline__ void cp_commit() {
    asm volatile("cp.async.commit_group;" ::: "memory");
}
template <int N>
__device__ __forceinline__ void cp_wait() {
    asm volatile("cp.async.wait_group %0;" :: "n"(N) : "memory");
}

// ---------------- split helper ----------------
__device__ __forceinline__ void split4(float4 v, uint2& hi, uint2& lo) {
    bf16 h0 = __float2bfloat16(v.x), h1 = __float2bfloat16(v.y);
    bf16 h2 = __float2bfloat16(v.z), h3 = __float2bfloat16(v.w);
    bf16 l0 = __float2bfloat16(v.x - __bfloat162float(h0));
    bf16 l1 = __float2bfloat16(v.y - __bfloat162float(h1));
    bf16 l2 = __float2bfloat16(v.z - __bfloat162float(h2));
    bf16 l3 = __float2bfloat16(v.w - __bfloat162float(h3));
    hi.x = (unsigned)__bfloat16_as_ushort(h0) | ((unsigned)__bfloat16_as_ushort(h1) << 16);
    hi.y = (unsigned)__bfloat16_as_ushort(h2) | ((unsigned)__bfloat16_as_ushort(h3) << 16);
    lo.x = (unsigned)__bfloat16_as_ushort(l0) | ((unsigned)__bfloat16_as_ushort(l1) << 16);
    lo.y = (unsigned)__bfloat16_as_ushort(l2) | ((unsigned)__bfloat16_as_ushort(l3) << 16);
}

// ---------------- split kernels ----------------
__global__ void split_weights(
    const float* __restrict__ Ws, const float* __restrict__ Wd,
    const float* __restrict__ W1, const float* __restrict__ W2,
    bf16* __restrict__ Ws_hi, bf16* __restrict__ Ws_lo,
    bf16* __restrict__ Wd_hi, bf16* __restrict__ Wd_lo,
    bf16* __restrict__ W1_hi, bf16* __restrict__ W1_lo,
    bf16* __restrict__ W2_hi, bf16* __restrict__ W2_lo,
    bf16* __restrict__ h1_hi, bf16* __restrict__ h1_lo)
{
    int i = blockIdx.x * blockDim.x + threadIdx.x;
    // zero h1-plane padding rows (NN..NPAD) while we're here
    if (i < 24576 + (NPAD - NN) * 32) {
        if (i >= 24576) {
            int j = i - 24576;
            reinterpret_cast<uint2*>(h1_hi + (size_t)NN * HID)[j] = make_uint2(0u, 0u);
            reinterpret_cast<uint2*>(h1_lo + (size_t)NN * HID)[j] = make_uint2(0u, 0u);
            return;
        }
    } else return;
    const float* s; bf16 *ph, *pl; int j = i;
    if (j < 4096)        { s = Ws; ph = Ws_hi; pl = Ws_lo; }
    else if (j < 8192)   { j -= 4096;  s = Wd; ph = Wd_hi; pl = Wd_lo; }
    else if (j < 16384)  { j -= 8192;  s = W1; ph = W1_hi; pl = W1_lo; }
    else                 { j -= 16384; s = W2; ph = W2_hi; pl = W2_lo; }
    float4 v = reinterpret_cast<const float4*>(s)[j];
    uint2 h, l;
    split4(v, h, l);
    reinterpret_cast<uint2*>(ph)[j] = h;
    reinterpret_cast<uint2*>(pl)[j] = l;
}

__global__ void split_h(const float* __restrict__ src, bf16* __restrict__ hi,
                        bf16* __restrict__ lo) {
    int i = blockIdx.x * blockDim.x + threadIdx.x;
    if (i >= NPAD * 32) return;
    int row = i >> 5;
    float4 v = make_float4(0.f, 0.f, 0.f, 0.f);
    if (row < NN) v = reinterpret_cast<const float4*>(src)[i];
    uint2 h, l;
    split4(v, h, l);
    reinterpret_cast<uint2*>(hi)[i] = h;
    reinterpret_cast<uint2*>(lo)[i] = l;
}

// ---------------- CSR build ----------------
__global__ void hist_kernel(const int* __restrict__ dst, int* __restrict__ cnt) {
    int e = blockIdx.x * blockDim.x + threadIdx.x;
    if (e < EE) atomicAdd(&cnt[dst[e]], 1);
}

__global__ void scan1(const int* __restrict__ cnt, int* __restrict__ excl,
                      int* __restrict__ bsum) {
    __shared__ int sh[512];
    int i = blockIdx.x * 512 + threadIdx.x;
    int v = (i < NN) ? cnt[i] : 0;
    sh[threadIdx.x] = v;
    __syncthreads();
    #pragma unroll
    for (int off = 1; off < 512; off <<= 1) {
        int t = (threadIdx.x >= off) ? sh[threadIdx.x - off] : 0;
        __syncthreads();
        sh[threadIdx.x] += t;
        __syncthreads();
    }
    if (i < NN) excl[i] = sh[threadIdx.x] - v;
    if (threadIdx.x == 511) bsum[blockIdx.x] = sh[511];
}

__global__ void scan2(int* __restrict__ bsum, int nb) {
    __shared__ int sh[128];
    int v = (threadIdx.x < nb) ? bsum[threadIdx.x] : 0;
    sh[threadIdx.x] = v;
    __syncthreads();
    #pragma unroll
    for (int off = 1; off < 128; off <<= 1) {
        int t = (threadIdx.x >= off) ? sh[threadIdx.x - off] : 0;
        __syncthreads();
        sh[threadIdx.x] += t;
        __syncthreads();
    }
    if (threadIdx.x < nb) bsum[threadIdx.x] = sh[threadIdx.x] - v;
}

__global__ void scan3(int* __restrict__ excl, const int* __restrict__ bsum,
                      int* __restrict__ cursor) {
    int i = blockIdx.x * 512 + threadIdx.x;
    if (i < NN) {
        int v = excl[i] + bsum[blockIdx.x];
        excl[i] = v;
        cursor[i] = v;
    }
}

__global__ void scatter_kernel(const int* __restrict__ src, const int* __restrict__ dst,
                               int* __restrict__ cursor, int* __restrict__ esrc) {
    int e = blockIdx.x * blockDim.x + threadIdx.x;
    if (e >= EE) return;
    int pos = atomicAdd(&cursor[dst[e]], 1);
    esrc[pos] = src[e];
}

// ---------------- WMMA split-bf16 GEMM core ----------------
// EPI: 0 = fp32 store, 1 = split planes, 2 = fused residual+LayerNorm
template <int KTOT, bool GELU, int EPI>
__device__ __forceinline__ void gemm_core(
    const bf16* __restrict__ Ah_g, const bf16* __restrict__ Al_g, int lda,
    const bf16* __restrict__ Bh_g, const bf16* __restrict__ Bl_g, int ldb,
    const float* __restrict__ bias,
    float* __restrict__ C, bf16* __restrict__ Chi, bf16* __restrict__ Clo,
    int ldc, int ccol0, int m0,
    const float* __restrict__ resid, const float* __restrict__ lng,
    const float* __restrict__ lnb, float* __restrict__ outp)
{
    extern __shared__ bf16 sm[];
    bf16* AhS[2] = { sm,            sm + A_ST };
    bf16* AlS[2] = { sm + 2 * A_ST, sm + 3 * A_ST };
    bf16* BhS[2] = { sm + 4 * A_ST,             sm + 4 * A_ST + B_ST };
    bf16* BlS[2] = { sm + 4 * A_ST + 2 * B_ST,  sm + 4 * A_ST + 3 * B_ST };
    float* bias_sm = (float*)(sm + SM_ELEMS);   // [16][128]

    const int tid = threadIdx.x;
    const int wid = tid >> 5;
    const int wm = wid >> 1;
    const int wn = wid & 1;

    constexpr int KC = KTOT / 32;

    auto load_stage = [&](int kc, int st) {
        #pragma unroll
        for (int i = tid; i < 512; i += 256) {
            int r = i >> 2, c8 = (i & 3) * 8;
            size_t go = (size_t)(m0 + r) * lda + kc * 32 + c8;
            cp16(AhS[st] + r * LDA_SM + c8, Ah_g + go);
            cp16(AlS[st] + r * LDA_SM + c8, Al_g + go);
        }
        #pragma unroll
        for (int i = tid; i < 512; i += 256) {
            int r = i >> 4, c8 = (i & 15) * 8;
            size_t go = (size_t)(kc * 32 + r) * ldb + ccol0 + c8;
            cp16(BhS[st] + r * LDB_SM + c8, Bh_g + go);
            cp16(BlS[st] + r * LDB_SM + c8, Bl_g + go);
        }
        cp_commit();
    };

    load_stage(0, 0);

    for (int i = tid; i < 16 * 128; i += 256)
        bias_sm[i] = bias[ccol0 + (i & 127)];
    __syncthreads();

    wmma::fragment<wmma::accumulator, 16, 16, 16, float> acc[2][4];
    #pragma unroll
    for (int mi = 0; mi < 2; mi++)
        #pragma unroll
        for (int nj = 0; nj < 4; nj++)
            wmma::load_matrix_sync(acc[mi][nj], bias_sm + wn * 64 + nj * 16, 128, wmma::mem_row_major);

    #pragma unroll
    for (int kc = 0; kc < KC; kc++) {
        if (kc + 1 < KC) load_stage(kc + 1, (kc + 1) & 1);
        if (kc + 1 < KC) cp_wait<1>(); else cp_wait<0>();
        __syncthreads();

        const int st = kc & 1;
        #pragma unroll
        for (int kk = 0; kk < 2; kk++) {
            wmma::fragment<wmma::matrix_a, 16, 16, 16, bf16, wmma::row_major> ah[2], al[2];
            wmma::fragment<wmma::matrix_b, 16, 16, 16, bf16, wmma::row_major> bh[4], bl[4];
            #pragma unroll
            for (int mi = 0; mi < 2; mi++) {
                const bf16* ap = AhS[st] + (wm * 32 + mi * 16) * LDA_SM + kk * 16;
                const bf16* alp = AlS[st] + (wm * 32 + mi * 16) * LDA_SM + kk * 16;
                wmma::load_matrix_sync(ah[mi], ap, LDA_SM);
                wmma::load_matrix_sync(al[mi], alp, LDA_SM);
            }
            #pragma unroll
            for (int nj = 0; nj < 4; nj++) {
                const bf16* bp = BhS[st] + (kk * 16) * LDB_SM + wn * 64 + nj * 16;
                const bf16* blp = BlS[st] + (kk * 16) * LDB_SM + wn * 64 + nj * 16;
                wmma::load_matrix_sync(bh[nj], bp, LDB_SM);
                wmma::load_matrix_sync(bl[nj], blp, LDB_SM);
            }
            #pragma unroll
            for (int mi = 0; mi < 2; mi++)
                #pragma unroll
                for (int nj = 0; nj < 4; nj++) {
                    wmma::mma_sync(acc[mi][nj], ah[mi], bh[nj], acc[mi][nj]);
                    wmma::mma_sync(acc[mi][nj], ah[mi], bl[nj], acc[mi][nj]);
                    wmma::mma_sync(acc[mi][nj], al[mi], bh[nj], acc[mi][nj]);
                }
        }
        __syncthreads();
    }

    if (GELU) {
        #pragma unroll
        for (int mi = 0; mi < 2; mi++)
            #pragma unroll
            for (int nj = 0; nj < 4; nj++)
                #pragma unroll
                for (int i = 0; i < acc[mi][nj].num_elements; i++) {
                    float x = acc[mi][nj].x[i];
                    acc[mi][nj].x[i] = 0.5f * x * (1.0f + erff(x * 0.70710678118654752f));
                }
    }

    if (EPI == 0) {
        #pragma unroll
        for (int mi = 0; mi < 2; mi++)
            #pragma unroll
            for (int nj = 0; nj < 4; nj++) {
                float* cp = C + (size_t)(m0 + wm * 32 + mi * 16) * ldc + ccol0 + wn * 64 + nj * 16;
                wmma::store_matrix_sync(cp, acc[mi][nj], ldc, wmma::mem_row_major);
            }
    } else if (EPI == 1) {
        float* stage = (float*)sm + wid * (32 * 68);
        #pragma unroll
        for (int mi = 0; mi < 2; mi++)
            #pragma unroll
            for (int nj = 0; nj < 4; nj++)
                wmma::store_matrix_sync(stage + mi * 16 * 68 + nj * 16, acc[mi][nj], 68, wmma::mem_row_major);
        __syncwarp();
        int lane = tid & 31;
        #pragma unroll
        for (int it = 0; it < 16; it++) {
            int j = it * 32 + lane;
            int r = j >> 4, c4 = j & 15;
            float4 v = *reinterpret_cast<const float4*>(stage + r * 68 + c4 * 4);
            uint2 h, l;
            split4(v, h, l);
            size_t go = (size_t)(m0 + wm * 32 + r) * ldc + ccol0 + wn * 64 + c4 * 4;
            *reinterpret_cast<uint2*>(Chi + go) = h;
            *reinterpret_cast<uint2*>(Clo + go) = l;
        }
    } else {
        // EPI==2: fused residual + LayerNorm. Full 128-wide rows in this block.
        float* stageF = (float*)sm;   // 128 x 132 fp32 = 67584 B
        #pragma unroll
        for (int mi = 0; mi < 2; mi++)
            #pragma unroll
            for (int nj = 0; nj < 4; nj++)
                wmma::store_matrix_sync(stageF + (wm * 32 + mi * 16) * 132 + wn * 64 + nj * 16,
                                        acc[mi][nj], 132, wmma::mem_row_major);
        __syncthreads();
        int lane = tid & 31;
        float4 gg = reinterpret_cast<const float4*>(lng)[lane];
        float4 bb = reinterpret_cast<const float4*>(lnb)[lane];
        #pragma unroll
        for (int rr = 0; rr < 16; rr++) {
            int r = wid * 16 + rr;
            int row = m0 + r;
            if (row >= NN) continue;
            float4 v = *reinterpret_cast<const float4*>(stageF + r * 132 + lane * 4);
            float4 rv = reinterpret_cast<const float4*>(resid)[(size_t)row * 32 + lane];
            v.x += rv.x; v.y += rv.y; v.z += rv.z; v.w += rv.w;

            float s1 = v.x + v.y + v.z + v.w;
            float s2 = v.x * v.x + v.y * v.y + v.z * v.z + v.w * v.w;
            #pragma unroll
            for (int off = 16; off > 0; off >>= 1) {
                s1 += __shfl_xor_sync(0xffffffffu, s1, off);
                s2 += __shfl_xor_sync(0xffffffffu, s2, off);
            }
            float mu = s1 * (1.0f / HID);
            float var = s2 * (1.0f / HID) - mu * mu;
            float rstd = rsqrtf(var + LN_EPS);

            float4 o;
            o.x = (v.x - mu) * rstd * gg.x + bb.x;
            o.y = (v.y - mu) * rstd * gg.y + bb.y;
            o.z = (v.z - mu) * rstd * gg.z + bb.z;
            o.w = (v.w - mu) * rstd * gg.w + bb.w;
            reinterpret_cast<float4*>(outp)[(size_t)row * 32 + lane] = o;
        }
    }
}

__global__ __launch_bounds__(256, 2) void gemm_srcdst(
    const bf16* __restrict__ h_hi, const bf16* __restrict__ h_lo,
    const bf16* __restrict__ Ws_hi, const bf16* __restrict__ Ws_lo,
    const float* __restrict__ bsrc,
    const bf16* __restrict__ Wd_hi, const bf16* __restrict__ Wd_lo,
    const float* __restrict__ bdst,
    float* __restrict__ fs, float* __restrict__ fd)
{
    int m0 = blockIdx.x * 128;
    if (blockIdx.y == 0)
        gemm_core<128, false, 0>(h_hi, h_lo, 128, Ws_hi, Ws_lo, 128, bsrc,
                                 fs, nullptr, nullptr, 128, 0, m0,
                                 nullptr, nullptr, nullptr, nullptr);
    else
        gemm_core<128, false, 0>(h_hi, h_lo, 128, Wd_hi, Wd_lo, 128, bdst,
                                 fd, nullptr, nullptr, 128, 0, m0,
                                 nullptr, nullptr, nullptr, nullptr);
}

__global__ __launch_bounds__(256, 2) void gemm_ffn1(
    const bf16* __restrict__ h1_hi, const bf16* __restrict__ h1_lo,
    const bf16* __restrict__ W1_hi, const bf16* __restrict__ W1_lo,
    const float* __restrict__ bf1,
    bf16* __restrict__ t_hi, bf16* __restrict__ t_lo)
{
    gemm_core<128, true, 1>(h1_hi, h1_lo, 128, W1_hi, W1_lo, 256, bf1,
                            nullptr, t_hi, t_lo, 256, blockIdx.y * 128, blockIdx.x * 128,
                            nullptr, nullptr, nullptr, nullptr);
}

// ffn2 + residual(h1) + LayerNorm2 fused -> writes final out
__global__ __launch_bounds__(256, 2) void gemm_ffn2_ln(
    const bf16* __restrict__ t_hi, const bf16* __restrict__ t_lo,
    const bf16* __restrict__ W2_hi, const bf16* __restrict__ W2_lo,
    const float* __restrict__ bf2,
    const float* __restrict__ h1, const float* __restrict__ g2,
    const float* __restrict__ be2, float* __restrict__ out)
{
    gemm_core<256, false, 2>(t_hi, t_lo, 256, W2_hi, W2_lo, 128, bf2,
                             nullptr, nullptr, nullptr, 128, 0, blockIdx.x * 128,
                             h1, g2, be2, out);
}

// ---------------- fused edge aggregation + LN1 ----------------
// One warp per dst node: aggregate, normalize by register denom, add residual,
// LayerNorm, emit h1 fp32 + bf16 planes. 2-way unrolled gather loop (MLP=2).
__global__ __launch_bounds__(256) void edge_agg_ln(
    const float* __restrict__ fs, const float* __restrict__ fd,
    const int* __restrict__ eoff, const int* __restrict__ ecnt,
    const int* __restrict__ esrc, const float* __restrict__ attn,
    const float* __restrict__ resid,
    const float* __restrict__ g, const float* __restrict__ b,
    float* __restrict__ out, bf16* __restrict__ out_hi, bf16* __restrict__ out_lo)
{
    int d = blockIdx.x * 8 + (threadIdx.x >> 5);
    if (d >= NN) return;
    int lane = threadIdx.x & 31;

    float4 va = reinterpret_cast<const float4*>(attn)[lane];
    float4 vd = reinterpret_cast<const float4*>(fd)[(size_t)d * 32 + lane];

    int i = eoff[d];
    int end = i + ecnt[d];

    float4 acc = make_float4(0.f, 0.f, 0.f, 0.f);
    float den = 0.0f;

    for (; i + 1 < end; i += 2) {
        int s0 = __ldg(esrc + i);
        int s1 = __ldg(esrc + i + 1);
        float4 vs0 = reinterpret_cast<const float4*>(fs)[(size_t)s0 * 32 + lane];
        float4 vs1 = reinterpret_cast<const float4*>(fs)[(size_t)s1 * 32 + lane];

        float x, sum0 = 0.0f, sum1 = 0.0f;
        x = vs0.x + vd.x; x = (x > 0.f) ? x : NEG_SLOPE * x; sum0 += x * va.x;
        x = vs0.y + vd.y; x = (x > 0.f) ? x : NEG_SLOPE * x; sum0 += x * va.y;
        x = vs0.z + vd.z; x = (x > 0.f) ? x : NEG_SLOPE * x; sum0 += x * va.z;
        x = vs0.w + vd.w; x = (x > 0.f) ? x : NEG_SLOPE * x; sum0 += x * va.w;
        x = vs1.x + vd.x; x = (x > 0.f) ? x : NEG_SLOPE * x; sum1 += x * va.x;
        x = vs1.y + vd.y; x = (x > 0.f) ? x : NEG_SLOPE * x; sum1 += x * va.y;
        x = vs1.z + vd.z; x = (x > 0.f) ? x : NEG_SLOPE * x; sum1 += x * va.z;
        x = vs1.w + vd.w; x = (x > 0.f) ? x : NEG_SLOPE * x; sum1 += x * va.w;

        sum0 += __shfl_xor_sync(0xffffffffu, sum0, 4);
        sum0 += __shfl_xor_sync(0xffffffffu, sum0, 2);
        sum0 += __shfl_xor_sync(0xffffffffu, sum0, 1);
        sum1 += __shfl_xor_sync(0xffffffffu, sum1, 4);
        sum1 += __shfl_xor_sync(0xffffffffu, sum1, 2);
        sum1 += __shfl_xor_sync(0xffffffffu, sum1, 1);

        float a0 = __expf(sum0);
        float a1 = __expf(sum1);
        acc.x += vs0.x * a0 + vs1.x * a1;
        acc.y += vs0.y * a0 + vs1.y * a1;
        acc.z += vs0.z * a0 + vs1.z * a1;
        acc.w += vs0.w * a0 + vs1.w * a1;
        den += a0 + a1;
    }
    if (i < end) {
        int s = __ldg(esrc + i);
        float4 vs = reinterpret_cast<const float4*>(fs)[(size_t)s * 32 + lane];
        float x, sum = 0.0f;
        x = vs.x + vd.x; x = (x > 0.f) ? x : NEG_SLOPE * x; sum += x * va.x;
        x = vs.y + vd.y; x = (x > 0.f) ? x : NEG_SLOPE * x; sum += x * va.y;
        x = vs.z + vd.z; x = (x > 0.f) ? x : NEG_SLOPE * x; sum += x * va.z;
        x = vs.w + vd.w; x = (x > 0.f) ? x : NEG_SLOPE * x; sum += x * va.w;
        sum += __shfl_xor_sync(0xffffffffu, sum, 4);
        sum += __shfl_xor_sync(0xffffffffu, sum, 2);
        sum += __shfl_xor_sync(0xffffffffu, sum, 1);
        float a = __expf(sum);
        acc.x += vs.x * a; acc.y += vs.y * a;
        acc.z += vs.z * a; acc.w += vs.w * a;
        den += a;
    }

    // normalize + residual + LayerNorm
    den = (den == 0.0f) ? 1.0f : den;
    float inv = 1.0f / den;
    float4 rv = reinterpret_cast<const float4*>(resid)[(size_t)d * 32 + lane];
    float4 v;
    v.x = acc.x * inv + rv.x; v.y = acc.y * inv + rv.y;
    v.z = acc.z * inv + rv.z; v.w = acc.w * inv + rv.w;

    float s1 = v.x + v.y + v.z + v.w;
    float s2 = v.x * v.x + v.y * v.y + v.z * v.z + v.w * v.w;
    #pragma unroll
    for (int off = 16; off > 0; off >>= 1) {
        s1 += __shfl_xor_sync(0xffffffffu, s1, off);
        s2 += __shfl_xor_sync(0xffffffffu, s2, off);
    }
    float mu = s1 * (1.0f / HID);
    float var = s2 * (1.0f / HID) - mu * mu;
    float rstd = rsqrtf(var + LN_EPS);

    float4 gg = reinterpret_cast<const float4*>(g)[lane];
    float4 bb = reinterpret_cast<const float4*>(b)[lane];
    float4 o;
    o.x = (v.x - mu) * rstd * gg.x + bb.x;
    o.y = (v.y - mu) * rstd * gg.y + bb.y;
    o.z = (v.z - mu) * rstd * gg.z + bb.z;
    o.w = (v.w - mu) * rstd * gg.w + bb.w;
    reinterpret_cast<float4*>(out)[(size_t)d * 32 + lane] = o;

    uint2 h, l;
    split4(o, h, l);
    reinterpret_cast<uint2*>(out_hi)[(size_t)d * 32 + lane] = h;
    reinterpret_cast<uint2*>(out_lo)[(size_t)d * 32 + lane] = l;
}

// ---------------- launcher ----------------
extern "C" void kernel_launch(void* const* d_in, const int* in_sizes, int n_in,
                              void* d_out, int out_size)
{
    const float* h    = (const float*)d_in[0];
    const int*   src  = (const int*)  d_in[1];
    const int*   dst  = (const int*)  d_in[2];
    const float* Wsrc = (const float*)d_in[3];
    const float* bsrc = (const float*)d_in[4];
    const float* Wdst = (const float*)d_in[5];
    const float* bdst = (const float*)d_in[6];
    const float* attn = (const float*)d_in[7];
    const float* W1   = (const float*)d_in[8];
    const float* bf1  = (const float*)d_in[9];
    const float* W2   = (const float*)d_in[10];
    const float* bf2  = (const float*)d_in[11];
    const float* g1   = (const float*)d_in[12];
    const float* be1  = (const float*)d_in[13];
    const float* g2   = (const float*)d_in[14];
    const float* be2  = (const float*)d_in[15];
    float* out = (float*)d_out;

    float *fs, *fd, *h1;
    int *ecnt, *eoff, *cursor, *bsum, *esrc;
    bf16 *h_hi, *h_lo, *h1_hi, *h1_lo, *t_hi, *t_lo;
    bf16 *Ws_hi, *Ws_lo, *Wd_hi, *Wd_lo, *W1_hi, *W1_lo, *W2_hi, *W2_lo;
    cudaGetSymbolAddress((void**)&fs,    g_fs);
    cudaGetSymbolAddress((void**)&fd,    g_fd);
    cudaGetSymbolAddress((void**)&h1,    g_h1);
    cudaGetSymbolAddress((void**)&ecnt,  g_ecnt);
    cudaGetSymbolAddress((void**)&eoff,  g_eoff);
    cudaGetSymbolAddress((void**)&cursor,g_cursor);
    cudaGetSymbolAddress((void**)&bsum,  g_bsum);
    cudaGetSymbolAddress((void**)&esrc,  g_esrc);
    cudaGetSymbolAddress((void**)&h_hi,  g_h_hi);
    cudaGetSymbolAddress((void**)&h_lo,  g_h_lo);
    cudaGetSymbolAddress((void**)&h1_hi, g_h1_hi);
    cudaGetSymbolAddress((void**)&h1_lo, g_h1_lo);
    cudaGetSymbolAddress((void**)&t_hi,  g_t_hi);
    cudaGetSymbolAddress((void**)&t_lo,  g_t_lo);
    cudaGetSymbolAddress((void**)&Ws_hi, g_Wsrc_hi);
    cudaGetSymbolAddress((void**)&Ws_lo, g_Wsrc_lo);
    cudaGetSymbolAddress((void**)&Wd_hi, g_Wdst_hi);
    cudaGetSymbolAddress((void**)&Wd_lo, g_Wdst_lo);
    cudaGetSymbolAddress((void**)&W1_hi, g_W1_hi);
    cudaGetSymbolAddress((void**)&W1_lo, g_W1_lo);
    cudaGetSymbolAddress((void**)&W2_hi, g_W2_hi);
    cudaGetSymbolAddress((void**)&W2_lo, g_W2_lo);

    cudaFuncSetAttribute(gemm_srcdst,  cudaFuncAttributeMaxDynamicSharedMemorySize, SM_BYTES);
    cudaFuncSetAttribute(gemm_ffn1,    cudaFuncAttributeMaxDynamicSharedMemorySize, SM_BYTES);
    cudaFuncSetAttribute(gemm_ffn2_ln, cudaFuncAttributeMaxDynamicSharedMemorySize, SM_BYTES);

    const int GXM = NPAD / 128;   // 391
    const int NB = (NN + 511) / 512;

    // Launch order places gemm_srcdst at the ncu capture slot.
    cudaMemsetAsync(ecnt, 0, NN * sizeof(int));                       // 1
    hist_kernel<<<(EE + 255) / 256, 256>>>(dst, ecnt);                // 2
    split_h<<<(NPAD * 32 + 255) / 256, 256>>>(h, h_hi, h_lo);         // 3
    split_weights<<<(24576 + (NPAD - NN) * 32 + 255) / 256, 256>>>(   // 4
        Wsrc, Wdst, W1, W2, Ws_hi, Ws_lo, Wd_hi, Wd_lo,
        W1_hi, W1_lo, W2_hi, W2_lo, h1_hi, h1_lo);
    gemm_srcdst<<<dim3(GXM, 2), 256, SM_BYTES>>>(h_hi, h_lo,          // 5 <- captured
                                                 Ws_hi, Ws_lo, bsrc,
                                                 Wd_hi, Wd_lo, bdst, fs, fd);
    scan1<<<NB, 512>>>(ecnt, eoff, bsum);                             // 6
    scan2<<<1, 128>>>(bsum, NB);                                      // 7
    scan3<<<NB, 512>>>(eoff, bsum, cursor);                           // 8
    scatter_kernel<<<(EE + 255) / 256, 256>>>(src, dst, cursor, esrc);// 9

    edge_agg_ln<<<(NN + 7) / 8, 256>>>(fs, fd, eoff, ecnt, esrc, attn,
                                       h, g1, be1, h1, h1_hi, h1_lo); // 10

    gemm_ffn1<<<dim3(GXM, 2), 256, SM_BYTES>>>(h1_hi, h1_lo, W1_hi, W1_lo,
                                               bf1, t_hi, t_lo);      // 11
    gemm_ffn2_ln<<<dim3(GXM, 1), 256, SM_BYTES>>>(t_hi, t_lo, W2_hi, W2_lo,
                                                  bf2, h1, g2, be2, out); // 12
}

// round 10
// speedup vs baseline: 2.1494x; 1.0062x over previous
#include <cuda_runtime.h>
#include <cuda_bf16.h>
#include <mma.h>
#include <math.h>

using namespace nvcuda;
typedef __nv_bfloat16 bf16;

// ---------------- problem constants ----------------
#define NN 50000
#define NPAD 50048            // 391 * 128
#define EE 600000
#define HID 128
#define HEADS 4
#define NEG_SLOPE 0.2f
#define LN_EPS 1e-5f

// GEMM tile geometry: BM=128, BK=32, 2-stage cp.async pipeline; BN templated (64/128)
#define LDA_SM 48
#define A_ST (128 * LDA_SM)               // 6144 bf16 per A plane per stage
#define BST(BN) (32 * ((BN) + 8))
#define SMB(BN) ((4 * A_ST + 4 * BST(BN)) * 2 + 16 * (BN) * 4)
// SMB(64) = 71680 -> 3 CTA/SM ; SMB(128) = 92160 -> 2 CTA/SM

// ---------------- scratch ----------------
__device__ float g_fs[NPAD * HID];
__device__ float g_fd[NPAD * HID];
__device__ float g_h1[NPAD * HID];
// CSR scratch
__device__ int g_ecnt[NN];
__device__ int g_eoff[NN];
__device__ int g_cursor[NN];
__device__ int g_bsum[128];
__device__ int g_esrc[EE];
// bf16 hi/lo planes
__device__ bf16 g_h_hi[NPAD * HID];
__device__ bf16 g_h_lo[NPAD * HID];
__device__ bf16 g_h1_hi[NPAD * HID];
__device__ bf16 g_h1_lo[NPAD * HID];
__device__ bf16 g_t_hi[NPAD * 2 * HID];
__device__ bf16 g_t_lo[NPAD * 2 * HID];
__device__ bf16 g_Wsrc_hi[HID * HID];
__device__ bf16 g_Wsrc_lo[HID * HID];
__device__ bf16 g_Wdst_hi[HID * HID];
__device__ bf16 g_Wdst_lo[HID * HID];
__device__ bf16 g_W1_hi[HID * 2 * HID];
__device__ bf16 g_W1_lo[HID * 2 * HID];
__device__ bf16 g_W2_hi[2 * HID * HID];
__device__ bf16 g_W2_lo[2 * HID * HID];

// ---------------- cp.async helpers ----------------
__device__ __forceinline__ void cp16(void* smem, const void* gmem) {
    unsigned saddr = (unsigned)__cvta_generic_to_shared(smem);
    asm volatile("cp.async.cg.shared.global [%0], [%1], 16;" :: "r"(saddr), "l"(gmem));
}
__device__ __forceinline__ void cp_commit() {
    asm volatile("cp.async.commit_group;" ::: "memory");
}
template <int N>
__device__ __forceinline__ void cp_wait() {
    asm volatile("cp.async.wait_group %0;" :: "n"(N) : "memory");
}

// ---------------- split helper ----------------
__device__ __forceinline__ void split4(float4 v, uint2& hi, uint2& lo) {
    bf16 h0 = __float2bfloat16(v.x), h1 = __float2bfloat16(v.y);
    bf16 h2 = __float2bfloat16(v.z), h3 = __float2bfloat16(v.w);
    bf16 l0 = __float2bfloat16(v.x - __bfloat162float(h0));
    bf16 l1 = __float2bfloat16(v.y - __bfloat162float(h1));
    bf16 l2 = __float2bfloat16(v.z - __bfloat162float(h2));
    bf16 l3 = __float2bfloat16(v.w - __bfloat162float(h3));
    hi.x = (unsigned)__bfloat16_as_ushort(h0) | ((unsigned)__bfloat16_as_ushort(h1) << 16);
    hi.y = (unsigned)__bfloat16_as_ushort(h2) | ((unsigned)__bfloat16_as_ushort(h3) << 16);
    lo.x = (unsigned)__bfloat16_as_ushort(l0) | ((unsigned)__bfloat16_as_ushort(l1) << 16);
    lo.y = (unsigned)__bfloat16_as_ushort(l2) | ((unsigned)__bfloat16_as_ushort(l3) << 16);
}

// ---------------- split kernels ----------------
__global__ void split_weights(
    const float* __restrict__ Ws, const float* __restrict__ Wd,
    const float* __restrict__ W1, const float* __restrict__ W2,
    bf16* __restrict__ Ws_hi, bf16* __restrict__ Ws_lo,
    bf16* __restrict__ Wd_hi, bf16* __restrict__ Wd_lo,
    bf16* __restrict__ W1_hi, bf16* __restrict__ W1_lo,
    bf16* __restrict__ W2_hi, bf16* __restrict__ W2_lo,
    bf16* __restrict__ h1_hi, bf16* __restrict__ h1_lo)
{
    int i = blockIdx.x * blockDim.x + threadIdx.x;
    if (i < 24576 + (NPAD - NN) * 32) {
        if (i >= 24576) {
            int j = i - 24576;
            reinterpret_cast<uint2*>(h1_hi + (size_t)NN * HID)[j] = make_uint2(0u, 0u);
            reinterpret_cast<uint2*>(h1_lo + (size_t)NN * HID)[j] = make_uint2(0u, 0u);
            return;
        }
    } else return;
    const float* s; bf16 *ph, *pl; int j = i;
    if (j < 4096)        { s = Ws; ph = Ws_hi; pl = Ws_lo; }
    else if (j < 8192)   { j -= 4096;  s = Wd; ph = Wd_hi; pl = Wd_lo; }
    else if (j < 16384)  { j -= 8192;  s = W1; ph = W1_hi; pl = W1_lo; }
    else                 { j -= 16384; s = W2; ph = W2_hi; pl = W2_lo; }
    float4 v = reinterpret_cast<const float4*>(s)[j];
    uint2 h, l;
    split4(v, h, l);
    reinterpret_cast<uint2*>(ph)[j] = h;
    reinterpret_cast<uint2*>(pl)[j] = l;
}

__global__ void split_h(const float* __restrict__ src, bf16* __restrict__ hi,
                        bf16* __restrict__ lo) {
    int i = blockIdx.x * blockDim.x + threadIdx.x;
    if (i >= NPAD * 32) return;
    int row = i >> 5;
    float4 v = make_float4(0.f, 0.f, 0.f, 0.f);
    if (row < NN) v = reinterpret_cast<const float4*>(src)[i];
    uint2 h, l;
    split4(v, h, l);
    reinterpret_cast<uint2*>(hi)[i] = h;
    reinterpret_cast<uint2*>(lo)[i] = l;
}

// ---------------- CSR build ----------------
__global__ void hist_kernel(const int* __restrict__ dst, int* __restrict__ cnt) {
    int e = blockIdx.x * blockDim.x + threadIdx.x;
    if (e < EE) atomicAdd(&cnt[dst[e]], 1);
}

__global__ void scan1(const int* __restrict__ cnt, int* __restrict__ excl,
                      int* __restrict__ bsum) {
    __shared__ int sh[512];
    int i = blockIdx.x * 512 + threadIdx.x;
    int v = (i < NN) ? cnt[i] : 0;
    sh[threadIdx.x] = v;
    __syncthreads();
    #pragma unroll
    for (int off = 1; off < 512; off <<= 1) {
        int t = (threadIdx.x >= off) ? sh[threadIdx.x - off] : 0;
        __syncthreads();
        sh[threadIdx.x] += t;
        __syncthreads();
    }
    if (i < NN) excl[i] = sh[threadIdx.x] - v;
    if (threadIdx.x == 511) bsum[blockIdx.x] = sh[511];
}

__global__ void scan2(int* __restrict__ bsum, int nb) {
    __shared__ int sh[128];
    int v = (threadIdx.x < nb) ? bsum[threadIdx.x] : 0;
    sh[threadIdx.x] = v;
    __syncthreads();
    #pragma unroll
    for (int off = 1; off < 128; off <<= 1) {
        int t = (threadIdx.x >= off) ? sh[threadIdx.x - off] : 0;
        __syncthreads();
        sh[threadIdx.x] += t;
        __syncthreads();
    }
    if (threadIdx.x < nb) bsum[threadIdx.x] = sh[threadIdx.x] - v;
}

__global__ void scan3(int* __restrict__ excl, const int* __restrict__ bsum,
                      int* __restrict__ cursor) {
    int i = blockIdx.x * 512 + threadIdx.x;
    if (i < NN) {
        int v = excl[i] + bsum[blockIdx.x];
        excl[i] = v;
        cursor[i] = v;
    }
}

__global__ void scatter_kernel(const int* __restrict__ src, const int* __restrict__ dst,
                               int* __restrict__ cursor, int* __restrict__ esrc) {
    int e = blockIdx.x * blockDim.x + threadIdx.x;
    if (e >= EE) return;
    int pos = atomicAdd(&cursor[dst[e]], 1);
    esrc[pos] = src[e];
}

// ---------------- WMMA split-bf16 GEMM core, BN-templated ----------------
// EPI: 0 = fp32 store, 1 = split planes, 2 = fused residual+LayerNorm (BN=128 only)
template <int KTOT, int BN, bool GELU, int EPI>
__device__ __forceinline__ void gemm_core(
    const bf16* __restrict__ Ah_g, const bf16* __restrict__ Al_g, int lda,
    const bf16* __restrict__ Bh_g, const bf16* __restrict__ Bl_g, int ldb,
    const float* __restrict__ bias,
    float* __restrict__ C, bf16* __restrict__ Chi, bf16* __restrict__ Clo,
    int ldc, int ccol0, int m0,
    const float* __restrict__ resid, const float* __restrict__ lng,
    const float* __restrict__ lnb, float* __restrict__ outp)
{
    constexpr int LDB = BN + 8;
    constexpr int B_ST = 32 * LDB;
    constexpr int WN = BN / 2;        // cols per warp
    constexpr int NJ = BN / 32;       // 16-col fragments per warp

    extern __shared__ bf16 sm[];
    bf16* AhS[2] = { sm,            sm + A_ST };
    bf16* AlS[2] = { sm + 2 * A_ST, sm + 3 * A_ST };
    bf16* BhS[2] = { sm + 4 * A_ST,             sm + 4 * A_ST + B_ST };
    bf16* BlS[2] = { sm + 4 * A_ST + 2 * B_ST,  sm + 4 * A_ST + 3 * B_ST };
    float* bias_sm = (float*)(sm + 4 * A_ST + 4 * B_ST);   // [16][BN]

    const int tid = threadIdx.x;
    const int wid = tid >> 5;
    const int wm = wid >> 1;          // 0..3 -> 32 rows each
    const int wn = wid & 1;           // 0..1 -> WN cols each

    constexpr int KC = KTOT / 32;

    auto load_stage = [&](int kc, int st) {
        #pragma unroll
        for (int i = tid; i < 512; i += 256) {
            int r = i >> 2, c8 = (i & 3) * 8;
            size_t go = (size_t)(m0 + r) * lda + kc * 32 + c8;
            cp16(AhS[st] + r * LDA_SM + c8, Ah_g + go);
            cp16(AlS[st] + r * LDA_SM + c8, Al_g + go);
        }
        constexpr int BI = 32 * (BN / 8);
        #pragma unroll
        for (int i = tid; i < BI; i += 256) {
            int r = i / (BN / 8), c8 = (i % (BN / 8)) * 8;
            size_t go = (size_t)(kc * 32 + r) * ldb + ccol0 + c8;
            cp16(BhS[st] + r * LDB + c8, Bh_g + go);
            cp16(BlS[st] + r * LDB + c8, Bl_g + go);
        }
        cp_commit();
    };

    load_stage(0, 0);

    for (int i = tid; i < 16 * BN; i += 256)
        bias_sm[i] = bias[ccol0 + (i & (BN - 1))];
    __syncthreads();

    wmma::fragment<wmma::accumulator, 16, 16, 16, float> acc[2][NJ];
    #pragma unroll
    for (int mi = 0; mi < 2; mi++)
        #pragma unroll
        for (int nj = 0; nj < NJ; nj++)
            wmma::load_matrix_sync(acc[mi][nj], bias_sm + wn * WN + nj * 16, BN, wmma::mem_row_major);

    #pragma unroll
    for (int kc = 0; kc < KC; kc++) {
        if (kc + 1 < KC) load_stage(kc + 1, (kc + 1) & 1);
        if (kc + 1 < KC) cp_wait<1>(); else cp_wait<0>();
        __syncthreads();

        const int st = kc & 1;
        #pragma unroll
        for (int kk = 0; kk < 2; kk++) {
            wmma::fragment<wmma::matrix_a, 16, 16, 16, bf16, wmma::row_major> ah[2], al[2];
            wmma::fragment<wmma::matrix_b, 16, 16, 16, bf16, wmma::row_major> bh[NJ], bl[NJ];
            #pragma unroll
            for (int mi = 0; mi < 2; mi++) {
                const bf16* ap = AhS[st] + (wm * 32 + mi * 16) * LDA_SM + kk * 16;
                const bf16* alp = AlS[st] + (wm * 32 + mi * 16) * LDA_SM + kk * 16;
                wmma::load_matrix_sync(ah[mi], ap, LDA_SM);
                wmma::load_matrix_sync(al[mi], alp, LDA_SM);
            }
            #pragma unroll
            for (int nj = 0; nj < NJ; nj++) {
                const bf16* bp = BhS[st] + (kk * 16) * LDB + wn * WN + nj * 16;
                const bf16* blp = BlS[st] + (kk * 16) * LDB + wn * WN + nj * 16;
                wmma::load_matrix_sync(bh[nj], bp, LDB);
                wmma::load_matrix_sync(bl[nj], blp, LDB);
            }
            #pragma unroll
            for (int mi = 0; mi < 2; mi++)
                #pragma unroll
                for (int nj = 0; nj < NJ; nj++) {
                    wmma::mma_sync(acc[mi][nj], ah[mi], bh[nj], acc[mi][nj]);
                    wmma::mma_sync(acc[mi][nj], ah[mi], bl[nj], acc[mi][nj]);
                    wmma::mma_sync(acc[mi][nj], al[mi], bh[nj], acc[mi][nj]);
                }
        }
        __syncthreads();
    }

    if (GELU) {
        #pragma unroll
        for (int mi = 0; mi < 2; mi++)
            #pragma unroll
            for (int nj = 0; nj < NJ; nj++)
                #pragma unroll
                for (int i = 0; i < acc[mi][nj].num_elements; i++) {
                    float x = acc[mi][nj].x[i];
                    acc[mi][nj].x[i] = 0.5f * x * (1.0f + erff(x * 0.70710678118654752f));
                }
    }

    if (EPI == 0) {
        #pragma unroll
        for (int mi = 0; mi < 2; mi++)
            #pragma unroll
            for (int nj = 0; nj < NJ; nj++) {
                float* cp = C + (size_t)(m0 + wm * 32 + mi * 16) * ldc + ccol0 + wn * WN + nj * 16;
                wmma::store_matrix_sync(cp, acc[mi][nj], ldc, wmma::mem_row_major);
            }
    } else if (EPI == 1) {
        constexpr int SS = WN + 4;
        float* stage = (float*)sm + wid * (32 * SS);
        #pragma unroll
        for (int mi = 0; mi < 2; mi++)
            #pragma unroll
            for (int nj = 0; nj < NJ; nj++)
                wmma::store_matrix_sync(stage + mi * 16 * SS + nj * 16, acc[mi][nj], SS, wmma::mem_row_major);
        __syncwarp();
        int lane = tid & 31;
        constexpr int QN = WN / 4;     // col quads per row
        #pragma unroll
        for (int it = 0; it < QN; it++) {
            int j = it * 32 + lane;
            int r = j / QN, c4 = j % QN;
            float4 v = *reinterpret_cast<const float4*>(stage + r * SS + c4 * 4);
            uint2 h, l;
            split4(v, h, l);
            size_t go = (size_t)(m0 + wm * 32 + r) * ldc + ccol0 + wn * WN + c4 * 4;
            *reinterpret_cast<uint2*>(Chi + go) = h;
            *reinterpret_cast<uint2*>(Clo + go) = l;
        }
    } else {
        // EPI==2 (BN=128 only): fused residual + LayerNorm on complete rows.
        float* stageF = (float*)sm;   // 128 x 132 fp32
        #pragma unroll
        for (int mi = 0; mi < 2; mi++)
            #pragma unroll
            for (int nj = 0; nj < NJ; nj++)
                wmma::store_matrix_sync(stageF + (wm * 32 + mi * 16) * 132 + wn * WN + nj * 16,
                                        acc[mi][nj], 132, wmma::mem_row_major);
        __syncthreads();
        int lane = tid & 31;
        float4 gg = reinterpret_cast<const float4*>(lng)[lane];
        float4 bb = reinterpret_cast<const float4*>(lnb)[lane];
        #pragma unroll
        for (int rr = 0; rr < 16; rr++) {
            int r = wid * 16 + rr;
            int row = m0 + r;
            if (row >= NN) continue;
            float4 v = *reinterpret_cast<const float4*>(stageF + r * 132 + lane * 4);
            float4 rv = reinterpret_cast<const float4*>(resid)[(size_t)row * 32 + lane];
            v.x += rv.x; v.y += rv.y; v.z += rv.z; v.w += rv.w;

            float s1 = v.x + v.y + v.z + v.w;
            float s2 = v.x * v.x + v.y * v.y + v.z * v.z + v.w * v.w;
            #pragma unroll
            for (int off = 16; off > 0; off >>= 1) {
                s1 += __shfl_xor_sync(0xffffffffu, s1, off);
                s2 += __shfl_xor_sync(0xffffffffu, s2, off);
            }
            float mu = s1 * (1.0f / HID);
            float var = s2 * (1.0f / HID) - mu * mu;
            float rstd = rsqrtf(var + LN_EPS);

            float4 o;
            o.x = (v.x - mu) * rstd * gg.x + bb.x;
            o.y = (v.y - mu) * rstd * gg.y + bb.y;
            o.z = (v.z - mu) * rstd * gg.z + bb.z;
            o.w = (v.w - mu) * rstd * gg.w + bb.w;
            reinterpret_cast<float4*>(outp)[(size_t)row * 32 + lane] = o;
        }
    }
}

__global__ __launch_bounds__(256, 3) void gemm_srcdst(
    const bf16* __restrict__ h_hi, const bf16* __restrict__ h_lo,
    const bf16* __restrict__ Ws_hi, const bf16* __restrict__ Ws_lo,
    const float* __restrict__ bsrc,
    const bf16* __restrict__ Wd_hi, const bf16* __restrict__ Wd_lo,
    const float* __restrict__ bdst,
    float* __restrict__ fs, float* __restrict__ fd)
{
    int m0 = blockIdx.x * 128;
    int y = blockIdx.y;              // 0,1 -> fs cols 0/64 ; 2,3 -> fd cols 0/64
    int col0 = (y & 1) * 64;
    if (y < 2)
        gemm_core<128, 64, false, 0>(h_hi, h_lo, 128, Ws_hi, Ws_lo, 128, bsrc,
                                     fs, nullptr, nullptr, 128, col0, m0,
                                     nullptr, nullptr, nullptr, nullptr);
    else
        gemm_core<128, 64, false, 0>(h_hi, h_lo, 128, Wd_hi, Wd_lo, 128, bdst,
                                     fd, nullptr, nullptr, 128, col0, m0,
                                     nullptr, nullptr, nullptr, nullptr);
}

__global__ __launch_bounds__(256, 3) void gemm_ffn1(
    const bf16* __restrict__ h1_hi, const bf16* __restrict__ h1_lo,
    const bf16* __restrict__ W1_hi, const bf16* __restrict__ W1_lo,
    const float* __restrict__ bf1,
    bf16* __restrict__ t_hi, bf16* __restrict__ t_lo)
{
    gemm_core<128, 64, true, 1>(h1_hi, h1_lo, 128, W1_hi, W1_lo, 256, bf1,
                                nullptr, t_hi, t_lo, 256, blockIdx.y * 64, blockIdx.x * 128,
                                nullptr, nullptr, nullptr, nullptr);
}

__global__ __launch_bounds__(256, 2) void gemm_ffn2_ln(
    const bf16* __restrict__ t_hi, const bf16* __restrict__ t_lo,
    const bf16* __restrict__ W2_hi, const bf16* __restrict__ W2_lo,
    const float* __restrict__ bf2,
    const float* __restrict__ h1, const float* __restrict__ g2,
    const float* __restrict__ be2, float* __restrict__ out)
{
    gemm_core<256, 128, false, 2>(t_hi, t_lo, 256, W2_hi, W2_lo, 128, bf2,
                                  nullptr, nullptr, nullptr, 128, 0, blockIdx.x * 128,
                                  h1, g2, be2, out);
}

// ---------------- fused edge aggregation + LN1 ----------------
__global__ __launch_bounds__(256) void edge_agg_ln(
    const float* __restrict__ fs, const float* __restrict__ fd,
    const int* __restrict__ eoff, const int* __restrict__ ecnt,
    const int* __restrict__ esrc, const float* __restrict__ attn,
    const float* __restrict__ resid,
    const float* __restrict__ g, const float* __restrict__ b,
    float* __restrict__ out, bf16* __restrict__ out_hi, bf16* __restrict__ out_lo)
{
    int d = blockIdx.x * 8 + (threadIdx.x >> 5);
    if (d >= NN) return;
    int lane = threadIdx.x & 31;

    float4 va = reinterpret_cast<const float4*>(attn)[lane];
    float4 vd = reinterpret_cast<const float4*>(fd)[(size_t)d * 32 + lane];

    int i = eoff[d];
    int end = i + ecnt[d];

    float4 acc = make_float4(0.f, 0.f, 0.f, 0.f);
    float den = 0.0f;

    for (; i + 1 < end; i += 2) {
        int s0 = __ldg(esrc + i);
        int s1 = __ldg(esrc + i + 1);
        float4 vs0 = reinterpret_cast<const float4*>(fs)[(size_t)s0 * 32 + lane];
        float4 vs1 = reinterpret_cast<const float4*>(fs)[(size_t)s1 * 32 + lane];

        float x, sum0 = 0.0f, sum1 = 0.0f;
        x = vs0.x + vd.x; x = (x > 0.f) ? x : NEG_SLOPE * x; sum0 += x * va.x;
        x = vs0.y + vd.y; x = (x > 0.f) ? x : NEG_SLOPE * x; sum0 += x * va.y;
        x = vs0.z + vd.z; x = (x > 0.f) ? x : NEG_SLOPE * x; sum0 += x * va.z;
        x = vs0.w + vd.w; x = (x > 0.f) ? x : NEG_SLOPE * x; sum0 += x * va.w;
        x = vs1.x + vd.x; x = (x > 0.f) ? x : NEG_SLOPE * x; sum1 += x * va.x;
        x = vs1.y + vd.y; x = (x > 0.f) ? x : NEG_SLOPE * x; sum1 += x * va.y;
        x = vs1.z + vd.z; x = (x > 0.f) ? x : NEG_SLOPE * x; sum1 += x * va.z;
        x = vs1.w + vd.w; x = (x > 0.f) ? x : NEG_SLOPE * x; sum1 += x * va.w;

        sum0 += __shfl_xor_sync(0xffffffffu, sum0, 4);
        sum0 += __shfl_xor_sync(0xffffffffu, sum0, 2);
        sum0 += __shfl_xor_sync(0xffffffffu, sum0, 1);
        sum1 += __shfl_xor_sync(0xffffffffu, sum1, 4);
        sum1 += __shfl_xor_sync(0xffffffffu, sum1, 2);
        sum1 += __shfl_xor_sync(0xffffffffu, sum1, 1);

        float a0 = __expf(sum0);
        float a1 = __expf(sum1);
        acc.x += vs0.x * a0 + vs1.x * a1;
        acc.y += vs0.y * a0 + vs1.y * a1;
        acc.z += vs0.z * a0 + vs1.z * a1;
        acc.w += vs0.w * a0 + vs1.w * a1;
        den += a0 + a1;
    }
    if (i < end) {
        int s = __ldg(esrc + i);
        float4 vs = reinterpret_cast<const float4*>(fs)[(size_t)s * 32 + lane];
        float x, sum = 0.0f;
        x = vs.x + vd.x; x = (x > 0.f) ? x : NEG_SLOPE * x; sum += x * va.x;
        x = vs.y + vd.y; x = (x > 0.f) ? x : NEG_SLOPE * x; sum += x * va.y;
        x = vs.z + vd.z; x = (x > 0.f) ? x : NEG_SLOPE * x; sum += x * va.z;
        x = vs.w + vd.w; x = (x > 0.f) ? x : NEG_SLOPE * x; sum += x * va.w;
        sum += __shfl_xor_sync(0xffffffffu, sum, 4);
        sum += __shfl_xor_sync(0xffffffffu, sum, 2);
        sum += __shfl_xor_sync(0xffffffffu, sum, 1);
        float a = __expf(sum);
        acc.x += vs.x * a; acc.y += vs.y * a;
        acc.z += vs.z * a; acc.w += vs.w * a;
        den += a;
    }

    den = (den == 0.0f) ? 1.0f : den;
    float inv = 1.0f / den;
    float4 rv = reinterpret_cast<const float4*>(resid)[(size_t)d * 32 + lane];
    float4 v;
    v.x = acc.x * inv + rv.x; v.y = acc.y * inv + rv.y;
    v.z = acc.z * inv + rv.z; v.w = acc.w * inv + rv.w;

    float s1 = v.x + v.y + v.z + v.w;
    float s2 = v.x * v.x + v.y * v.y + v.z * v.z + v.w * v.w;
    #pragma unroll
    for (int off = 16; off > 0; off >>= 1) {
        s1 += __shfl_xor_sync(0xffffffffu, s1, off);
        s2 += __shfl_xor_sync(0xffffffffu, s2, off);
    }
    float mu = s1 * (1.0f / HID);
    float var = s2 * (1.0f / HID) - mu * mu;
    float rstd = rsqrtf(var + LN_EPS);

    float4 gg = reinterpret_cast<const float4*>(g)[lane];
    float4 bb = reinterpret_cast<const float4*>(b)[lane];
    float4 o;
    o.x = (v.x - mu) * rstd * gg.x + bb.x;
    o.y = (v.y - mu) * rstd * gg.y + bb.y;
    o.z = (v.z - mu) * rstd * gg.z + bb.z;
    o.w = (v.w - mu) * rstd * gg.w + bb.w;
    reinterpret_cast<float4*>(out)[(size_t)d * 32 + lane] = o;

    uint2 h, l;
    split4(o, h, l);
    reinterpret_cast<uint2*>(out_hi)[(size_t)d * 32 + lane] = h;
    reinterpret_cast<uint2*>(out_lo)[(size_t)d * 32 + lane] = l;
}

// ---------------- launcher ----------------
extern "C" void kernel_launch(void* const* d_in, const int* in_sizes, int n_in,
                              void* d_out, int out_size)
{
    const float* h    = (const float*)d_in[0];
    const int*   src  = (const int*)  d_in[1];
    const int*   dst  = (const int*)  d_in[2];
    const float* Wsrc = (const float*)d_in[3];
    const float* bsrc = (const float*)d_in[4];
    const float* Wdst = (const float*)d_in[5];
    const float* bdst = (const float*)d_in[6];
    const float* attn = (const float*)d_in[7];
    const float* W1   = (const float*)d_in[8];
    const float* bf1  = (const float*)d_in[9];
    const float* W2   = (const float*)d_in[10];
    const float* bf2  = (const float*)d_in[11];
    const float* g1   = (const float*)d_in[12];
    const float* be1  = (const float*)d_in[13];
    const float* g2   = (const float*)d_in[14];
    const float* be2  = (const float*)d_in[15];
    float* out = (float*)d_out;

    float *fs, *fd, *h1;
    int *ecnt, *eoff, *cursor, *bsum, *esrc;
    bf16 *h_hi, *h_lo, *h1_hi, *h1_lo, *t_hi, *t_lo;
    bf16 *Ws_hi, *Ws_lo, *Wd_hi, *Wd_lo, *W1_hi, *W1_lo, *W2_hi, *W2_lo;
    cudaGetSymbolAddress((void**)&fs,    g_fs);
    cudaGetSymbolAddress((void**)&fd,    g_fd);
    cudaGetSymbolAddress((void**)&h1,    g_h1);
    cudaGetSymbolAddress((void**)&ecnt,  g_ecnt);
    cudaGetSymbolAddress((void**)&eoff,  g_eoff);
    cudaGetSymbolAddress((void**)&cursor,g_cursor);
    cudaGetSymbolAddress((void**)&bsum,  g_bsum);
    cudaGetSymbolAddress((void**)&esrc,  g_esrc);
    cudaGetSymbolAddress((void**)&h_hi,  g_h_hi);
    cudaGetSymbolAddress((void**)&h_lo,  g_h_lo);
    cudaGetSymbolAddress((void**)&h1_hi, g_h1_hi);
    cudaGetSymbolAddress((void**)&h1_lo, g_h1_lo);
    cudaGetSymbolAddress((void**)&t_hi,  g_t_hi);
    cudaGetSymbolAddress((void**)&t_lo,  g_t_lo);
    cudaGetSymbolAddress((void**)&Ws_hi, g_Wsrc_hi);
    cudaGetSymbolAddress((void**)&Ws_lo, g_Wsrc_lo);
    cudaGetSymbolAddress((void**)&Wd_hi, g_Wdst_hi);
    cudaGetSymbolAddress((void**)&Wd_lo, g_Wdst_lo);
    cudaGetSymbolAddress((void**)&W1_hi, g_W1_hi);
    cudaGetSymbolAddress((void**)&W1_lo, g_W1_lo);
    cudaGetSymbolAddress((void**)&W2_hi, g_W2_hi);
    cudaGetSymbolAddress((void**)&W2_lo, g_W2_lo);

    const int SM64 = SMB(64);    // 71680
    const int SM128 = SMB(128);  // 92160
    cudaFuncSetAttribute(gemm_srcdst,  cudaFuncAttributeMaxDynamicSharedMemorySize, SM64);
    cudaFuncSetAttribute(gemm_ffn1,    cudaFuncAttributeMaxDynamicSharedMemorySize, SM64);
    cudaFuncSetAttribute(gemm_ffn2_ln, cudaFuncAttributeMaxDynamicSharedMemorySize, SM128);

    const int GXM = NPAD / 128;   // 391
    const int NB = (NN + 511) / 512;

    // Launch order keeps gemm_srcdst at the ncu capture slot (5th node).
    cudaMemsetAsync(ecnt, 0, NN * sizeof(int));                       // 1
    hist_kernel<<<(EE + 255) / 256, 256>>>(dst, ecnt);                // 2
    split_h<<<(NPAD * 32 + 255) / 256, 256>>>(h, h_hi, h_lo);         // 3
    split_weights<<<(24576 + (NPAD - NN) * 32 + 255) / 256, 256>>>(   // 4
        Wsrc, Wdst, W1, W2, Ws_hi, Ws_lo, Wd_hi, Wd_lo,
        W1_hi, W1_lo, W2_hi, W2_lo, h1_hi, h1_lo);
    gemm_srcdst<<<dim3(GXM, 4), 256, SM64>>>(h_hi, h_lo,              // 5 <- captured
                                             Ws_hi, Ws_lo, bsrc,
                                             Wd_hi, Wd_lo, bdst, fs, fd);
    scan1<<<NB, 512>>>(ecnt, eoff, bsum);                             // 6
    scan2<<<1, 128>>>(bsum, NB);                                      // 7
    scan3<<<NB, 512>>>(eoff, bsum, cursor);                           // 8
    scatter_kernel<<<(EE + 255) / 256, 256>>>(src, dst, cursor, esrc);// 9

    edge_agg_ln<<<(NN + 7) / 8, 256>>>(fs, fd, eoff, ecnt, esrc, attn,
                                       h, g1, be1, h1, h1_hi, h1_lo); // 10

    gemm_ffn1<<<dim3(GXM, 4), 256, SM64>>>(h1_hi, h1_lo, W1_hi, W1_lo,
                                           bf1, t_hi, t_lo);          // 11
    gemm_ffn2_ln<<<dim3(GXM, 1), 256, SM128>>>(t_hi, t_lo, W2_hi, W2_lo,
                                               bf2, h1, g2, be2, out); // 12
}

// round 11
// speedup vs baseline: 2.2475x; 1.0457x over previous
#include <cuda_runtime.h>
#include <cuda_bf16.h>
#include <mma.h>
#include <math.h>

using namespace nvcuda;
typedef __nv_bfloat16 bf16;

// ---------------- problem constants ----------------
#define NN 50000
#define NPAD 50048            // 391 * 128
#define EE 600000
#define HID 128
#define HEADS 4
#define NEG_SLOPE 0.2f
#define LN_EPS 1e-5f

// GEMM tile geometry: BM=128, BK=32, 2-stage cp.async pipeline; BN templated (64/128)
#define LDA_SM 48
#define A_ST (128 * LDA_SM)
#define BST(BN) (32 * ((BN) + 8))
#define SMB(BN) ((4 * A_ST + 4 * BST(BN)) * 2 + 16 * (BN) * 4)

// prep kernel block partition
#define PREP_HIST_B ((EE + 255) / 256)                 // 2344
#define PREP_SPH_B  ((NPAD * 32 + 255) / 256)          // 6256
#define PREP_SPW_B  ((24576 + (NPAD - NN) * 32 + 255) / 256)  // 102
#define PREP_TOTAL_B (PREP_HIST_B + PREP_SPH_B + PREP_SPW_B)

// ---------------- scratch ----------------
__device__ float g_fs[NPAD * HID];
__device__ float g_fd[NPAD * HID];
__device__ float g_h1[NPAD * HID];
// CSR scratch
__device__ int g_ecnt[NN];
__device__ int g_eoff[NN];
__device__ int g_cursor[NN];
__device__ int g_bsum[128];
__device__ int g_esrc[EE];
// bf16 hi/lo planes
__device__ bf16 g_h_hi[NPAD * HID];
__device__ bf16 g_h_lo[NPAD * HID];
__device__ bf16 g_h1_hi[NPAD * HID];
__device__ bf16 g_h1_lo[NPAD * HID];
__device__ bf16 g_t_hi[NPAD * 2 * HID];
__device__ bf16 g_t_lo[NPAD * 2 * HID];
__device__ bf16 g_Wsrc_hi[HID * HID];
__device__ bf16 g_Wsrc_lo[HID * HID];
__device__ bf16 g_Wdst_hi[HID * HID];
__device__ bf16 g_Wdst_lo[HID * HID];
__device__ bf16 g_W1_hi[HID * 2 * HID];
__device__ bf16 g_W1_lo[HID * 2 * HID];
__device__ bf16 g_W2_hi[2 * HID * HID];
__device__ bf16 g_W2_lo[2 * HID * HID];

// ---------------- cp.async helpers ----------------
__device__ __forceinline__ void cp16(void* smem, const void* gmem) {
    unsigned saddr = (unsigned)__cvta_generic_to_shared(smem);
    asm volatile("cp.async.cg.shared.global [%0], [%1], 16;" :: "r"(saddr), "l"(gmem));
}
__device__ __forceinline__ void cp_commit() {
    asm volatile("cp.async.commit_group;" ::: "memory");
}
template <int N>
__device__ __forceinline__ void cp_wait() {
    asm volatile("cp.async.wait_group %0;" :: "n"(N) : "memory");
}

// ---------------- split helper ----------------
__device__ __forceinline__ void split4(float4 v, uint2& hi, uint2& lo) {
    bf16 h0 = __float2bfloat16(v.x), h1 = __float2bfloat16(v.y);
    bf16 h2 = __float2bfloat16(v.z), h3 = __float2bfloat16(v.w);
    bf16 l0 = __float2bfloat16(v.x - __bfloat162float(h0));
    bf16 l1 = __float2bfloat16(v.y - __bfloat162float(h1));
    bf16 l2 = __float2bfloat16(v.z - __bfloat162float(h2));
    bf16 l3 = __float2bfloat16(v.w - __bfloat162float(h3));
    hi.x = (unsigned)__bfloat16_as_ushort(h0) | ((unsigned)__bfloat16_as_ushort(h1) << 16);
    hi.y = (unsigned)__bfloat16_as_ushort(h2) | ((unsigned)__bfloat16_as_ushort(h3) << 16);
    lo.x = (unsigned)__bfloat16_as_ushort(l0) | ((unsigned)__bfloat16_as_ushort(l1) << 16);
    lo.y = (unsigned)__bfloat16_as_ushort(l2) | ((unsigned)__bfloat16_as_ushort(l3) << 16);
}

// ---------------- merged prep kernel: hist + split_h + split_weights ----------------
__global__ void prep_kernel(
    const int* __restrict__ dst, int* __restrict__ cnt,
    const float* __restrict__ h, bf16* __restrict__ h_hi, bf16* __restrict__ h_lo,
    const float* __restrict__ Ws, const float* __restrict__ Wd,
    const float* __restrict__ W1, const float* __restrict__ W2,
    bf16* __restrict__ Ws_hi, bf16* __restrict__ Ws_lo,
    bf16* __restrict__ Wd_hi, bf16* __restrict__ Wd_lo,
    bf16* __restrict__ W1_hi, bf16* __restrict__ W1_lo,
    bf16* __restrict__ W2_hi, bf16* __restrict__ W2_lo,
    bf16* __restrict__ h1_hi, bf16* __restrict__ h1_lo)
{
    int b = blockIdx.x;
    if (b < PREP_HIST_B) {
        int e = b * 256 + threadIdx.x;
        if (e < EE) atomicAdd(&cnt[dst[e]], 1);
        return;
    }
    b -= PREP_HIST_B;
    if (b < PREP_SPH_B) {
        int i = b * 256 + threadIdx.x;
        if (i >= NPAD * 32) return;
        int row = i >> 5;
        float4 v = make_float4(0.f, 0.f, 0.f, 0.f);
        if (row < NN) v = reinterpret_cast<const float4*>(h)[i];
        uint2 hh, ll;
        split4(v, hh, ll);
        reinterpret_cast<uint2*>(h_hi)[i] = hh;
        reinterpret_cast<uint2*>(h_lo)[i] = ll;
        return;
    }
    b -= PREP_SPH_B;
    {
        int i = b * 256 + threadIdx.x;
        if (i >= 24576 + (NPAD - NN) * 32) return;
        if (i >= 24576) {
            int j = i - 24576;
            reinterpret_cast<uint2*>(h1_hi + (size_t)NN * HID)[j] = make_uint2(0u, 0u);
            reinterpret_cast<uint2*>(h1_lo + (size_t)NN * HID)[j] = make_uint2(0u, 0u);
            return;
        }
        const float* s; bf16 *ph, *pl; int j = i;
        if (j < 4096)        { s = Ws; ph = Ws_hi; pl = Ws_lo; }
        else if (j < 8192)   { j -= 4096;  s = Wd; ph = Wd_hi; pl = Wd_lo; }
        else if (j < 16384)  { j -= 8192;  s = W1; ph = W1_hi; pl = W1_lo; }
        else                 { j -= 16384; s = W2; ph = W2_hi; pl = W2_lo; }
        float4 v = reinterpret_cast<const float4*>(s)[j];
        uint2 hh, ll;
        split4(v, hh, ll);
        reinterpret_cast<uint2*>(ph)[j] = hh;
        reinterpret_cast<uint2*>(pl)[j] = ll;
    }
}

// ---------------- CSR scan/scatter ----------------
__global__ void scan1(const int* __restrict__ cnt, int* __restrict__ excl,
                      int* __restrict__ bsum) {
    __shared__ int sh[512];
    int i = blockIdx.x * 512 + threadIdx.x;
    int v = (i < NN) ? cnt[i] : 0;
    sh[threadIdx.x] = v;
    __syncthreads();
    #pragma unroll
    for (int off = 1; off < 512; off <<= 1) {
        int t = (threadIdx.x >= off) ? sh[threadIdx.x - off] : 0;
        __syncthreads();
        sh[threadIdx.x] += t;
        __syncthreads();
    }
    if (i < NN) excl[i] = sh[threadIdx.x] - v;
    if (threadIdx.x == 511) bsum[blockIdx.x] = sh[511];
}

__global__ void scan2(int* __restrict__ bsum, int nb) {
    __shared__ int sh[128];
    int v = (threadIdx.x < nb) ? bsum[threadIdx.x] : 0;
    sh[threadIdx.x] = v;
    __syncthreads();
    #pragma unroll
    for (int off = 1; off < 128; off <<= 1) {
        int t = (threadIdx.x >= off) ? sh[threadIdx.x - off] : 0;
        __syncthreads();
        sh[threadIdx.x] += t;
        __syncthreads();
    }
    if (threadIdx.x < nb) bsum[threadIdx.x] = sh[threadIdx.x] - v;
}

__global__ void scan3(int* __restrict__ excl, const int* __restrict__ bsum,
                      int* __restrict__ cursor) {
    int i = blockIdx.x * 512 + threadIdx.x;
    if (i < NN) {
        int v = excl[i] + bsum[blockIdx.x];
        excl[i] = v;
        cursor[i] = v;
    }
}

__global__ void scatter_kernel(const int* __restrict__ src, const int* __restrict__ dst,
                               int* __restrict__ cursor, int* __restrict__ esrc) {
    int e = blockIdx.x * blockDim.x + threadIdx.x;
    if (e >= EE) return;
    int pos = atomicAdd(&cursor[dst[e]], 1);
    esrc[pos] = src[e];
}

// ---------------- WMMA split-bf16 GEMM core, BN-templated ----------------
// EPI: 0 = fp32 store, 1 = split planes, 2 = fused residual+LayerNorm (BN=128 only)
template <int KTOT, int BN, bool GELU, int EPI>
__device__ __forceinline__ void gemm_core(
    const bf16* __restrict__ Ah_g, const bf16* __restrict__ Al_g, int lda,
    const bf16* __restrict__ Bh_g, const bf16* __restrict__ Bl_g, int ldb,
    const float* __restrict__ bias,
    float* __restrict__ C, bf16* __restrict__ Chi, bf16* __restrict__ Clo,
    int ldc, int ccol0, int m0,
    const float* __restrict__ resid, const float* __restrict__ lng,
    const float* __restrict__ lnb, float* __restrict__ outp)
{
    constexpr int LDB = BN + 8;
    constexpr int B_ST = 32 * LDB;
    constexpr int WN = BN / 2;
    constexpr int NJ = BN / 32;

    extern __shared__ bf16 sm[];
    bf16* AhS[2] = { sm,            sm + A_ST };
    bf16* AlS[2] = { sm + 2 * A_ST, sm + 3 * A_ST };
    bf16* BhS[2] = { sm + 4 * A_ST,             sm + 4 * A_ST + B_ST };
    bf16* BlS[2] = { sm + 4 * A_ST + 2 * B_ST,  sm + 4 * A_ST + 3 * B_ST };
    float* bias_sm = (float*)(sm + 4 * A_ST + 4 * B_ST);

    const int tid = threadIdx.x;
    const int wid = tid >> 5;
    const int wm = wid >> 1;
    const int wn = wid & 1;

    constexpr int KC = KTOT / 32;

    auto load_stage = [&](int kc, int st) {
        #pragma unroll
        for (int i = tid; i < 512; i += 256) {
            int r = i >> 2, c8 = (i & 3) * 8;
            size_t go = (size_t)(m0 + r) * lda + kc * 32 + c8;
            cp16(AhS[st] + r * LDA_SM + c8, Ah_g + go);
            cp16(AlS[st] + r * LDA_SM + c8, Al_g + go);
        }
        constexpr int BI = 32 * (BN / 8);
        #pragma unroll
        for (int i = tid; i < BI; i += 256) {
            int r = i / (BN / 8), c8 = (i % (BN / 8)) * 8;
            size_t go = (size_t)(kc * 32 + r) * ldb + ccol0 + c8;
            cp16(BhS[st] + r * LDB + c8, Bh_g + go);
            cp16(BlS[st] + r * LDB + c8, Bl_g + go);
        }
        cp_commit();
    };

    load_stage(0, 0);

    for (int i = tid; i < 16 * BN; i += 256)
        bias_sm[i] = bias[ccol0 + (i & (BN - 1))];
    __syncthreads();

    wmma::fragment<wmma::accumulator, 16, 16, 16, float> acc[2][NJ];
    #pragma unroll
    for (int mi = 0; mi < 2; mi++)
        #pragma unroll
        for (int nj = 0; nj < NJ; nj++)
            wmma::load_matrix_sync(acc[mi][nj], bias_sm + wn * WN + nj * 16, BN, wmma::mem_row_major);

    #pragma unroll
    for (int kc = 0; kc < KC; kc++) {
        if (kc + 1 < KC) load_stage(kc + 1, (kc + 1) & 1);
        if (kc + 1 < KC) cp_wait<1>(); else cp_wait<0>();
        __syncthreads();

        const int st = kc & 1;
        #pragma unroll
        for (int kk = 0; kk < 2; kk++) {
            wmma::fragment<wmma::matrix_a, 16, 16, 16, bf16, wmma::row_major> ah[2], al[2];
            wmma::fragment<wmma::matrix_b, 16, 16, 16, bf16, wmma::row_major> bh[NJ], bl[NJ];
            #pragma unroll
            for (int mi = 0; mi < 2; mi++) {
                const bf16* ap = AhS[st] + (wm * 32 + mi * 16) * LDA_SM + kk * 16;
                const bf16* alp = AlS[st] + (wm * 32 + mi * 16) * LDA_SM + kk * 16;
                wmma::load_matrix_sync(ah[mi], ap, LDA_SM);
                wmma::load_matrix_sync(al[mi], alp, LDA_SM);
            }
            #pragma unroll
            for (int nj = 0; nj < NJ; nj++) {
                const bf16* bp = BhS[st] + (kk * 16) * LDB + wn * WN + nj * 16;
                const bf16* blp = BlS[st] + (kk * 16) * LDB + wn * WN + nj * 16;
                wmma::load_matrix_sync(bh[nj], bp, LDB);
                wmma::load_matrix_sync(bl[nj], blp, LDB);
            }
            #pragma unroll
            for (int mi = 0; mi < 2; mi++)
                #pragma unroll
                for (int nj = 0; nj < NJ; nj++) {
                    wmma::mma_sync(acc[mi][nj], ah[mi], bh[nj], acc[mi][nj]);
                    wmma::mma_sync(acc[mi][nj], ah[mi], bl[nj], acc[mi][nj]);
                    wmma::mma_sync(acc[mi][nj], al[mi], bh[nj], acc[mi][nj]);
                }
        }
        __syncthreads();
    }

    if (GELU) {
        #pragma unroll
        for (int mi = 0; mi < 2; mi++)
            #pragma unroll
            for (int nj = 0; nj < NJ; nj++)
                #pragma unroll
                for (int i = 0; i < acc[mi][nj].num_elements; i++) {
                    float x = acc[mi][nj].x[i];
                    acc[mi][nj].x[i] = 0.5f * x * (1.0f + erff(x * 0.70710678118654752f));
                }
    }

    if (EPI == 0) {
        #pragma unroll
        for (int mi = 0; mi < 2; mi++)
            #pragma unroll
            for (int nj = 0; nj < NJ; nj++) {
                float* cp = C + (size_t)(m0 + wm * 32 + mi * 16) * ldc + ccol0 + wn * WN + nj * 16;
                wmma::store_matrix_sync(cp, acc[mi][nj], ldc, wmma::mem_row_major);
            }
    } else if (EPI == 1) {
        constexpr int SS = WN + 4;
        float* stage = (float*)sm + wid * (32 * SS);
        #pragma unroll
        for (int mi = 0; mi < 2; mi++)
            #pragma unroll
            for (int nj = 0; nj < NJ; nj++)
                wmma::store_matrix_sync(stage + mi * 16 * SS + nj * 16, acc[mi][nj], SS, wmma::mem_row_major);
        __syncwarp();
        int lane = tid & 31;
        constexpr int QN = WN / 4;
        #pragma unroll
        for (int it = 0; it < QN; it++) {
            int j = it * 32 + lane;
            int r = j / QN, c4 = j % QN;
            float4 v = *reinterpret_cast<const float4*>(stage + r * SS + c4 * 4);
            uint2 h, l;
            split4(v, h, l);
            size_t go = (size_t)(m0 + wm * 32 + r) * ldc + ccol0 + wn * WN + c4 * 4;
            *reinterpret_cast<uint2*>(Chi + go) = h;
            *reinterpret_cast<uint2*>(Clo + go) = l;
        }
    } else {
        float* stageF = (float*)sm;
        #pragma unroll
        for (int mi = 0; mi < 2; mi++)
            #pragma unroll
            for (int nj = 0; nj < NJ; nj++)
                wmma::store_matrix_sync(stageF + (wm * 32 + mi * 16) * 132 + wn * WN + nj * 16,
                                        acc[mi][nj], 132, wmma::mem_row_major);
        __syncthreads();
        int lane = tid & 31;
        float4 gg = reinterpret_cast<const float4*>(lng)[lane];
        float4 bb = reinterpret_cast<const float4*>(lnb)[lane];
        #pragma unroll
        for (int rr = 0; rr < 16; rr++) {
            int r = wid * 16 + rr;
            int row = m0 + r;
            if (row >= NN) continue;
            float4 v = *reinterpret_cast<const float4*>(stageF + r * 132 + lane * 4);
            float4 rv = reinterpret_cast<const float4*>(resid)[(size_t)row * 32 + lane];
            v.x += rv.x; v.y += rv.y; v.z += rv.z; v.w += rv.w;

            float s1 = v.x + v.y + v.z + v.w;
            float s2 = v.x * v.x + v.y * v.y + v.z * v.z + v.w * v.w;
            #pragma unroll
            for (int off = 16; off > 0; off >>= 1) {
                s1 += __shfl_xor_sync(0xffffffffu, s1, off);
                s2 += __shfl_xor_sync(0xffffffffu, s2, off);
            }
            float mu = s1 * (1.0f / HID);
            float var = s2 * (1.0f / HID) - mu * mu;
            float rstd = rsqrtf(var + LN_EPS);

            float4 o;
            o.x = (v.x - mu) * rstd * gg.x + bb.x;
            o.y = (v.y - mu) * rstd * gg.y + bb.y;
            o.z = (v.z - mu) * rstd * gg.z + bb.z;
            o.w = (v.w - mu) * rstd * gg.w + bb.w;
            reinterpret_cast<float4*>(outp)[(size_t)row * 32 + lane] = o;
        }
    }
}

__global__ __launch_bounds__(256, 3) void gemm_srcdst(
    const bf16* __restrict__ h_hi, const bf16* __restrict__ h_lo,
    const bf16* __restrict__ Ws_hi, const bf16* __restrict__ Ws_lo,
    const float* __restrict__ bsrc,
    const bf16* __restrict__ Wd_hi, const bf16* __restrict__ Wd_lo,
    const float* __restrict__ bdst,
    float* __restrict__ fs, float* __restrict__ fd)
{
    int m0 = blockIdx.x * 128;
    int y = blockIdx.y;
    int col0 = (y & 1) * 64;
    if (y < 2)
        gemm_core<128, 64, false, 0>(h_hi, h_lo, 128, Ws_hi, Ws_lo, 128, bsrc,
                                     fs, nullptr, nullptr, 128, col0, m0,
                                     nullptr, nullptr, nullptr, nullptr);
    else
        gemm_core<128, 64, false, 0>(h_hi, h_lo, 128, Wd_hi, Wd_lo, 128, bdst,
                                     fd, nullptr, nullptr, 128, col0, m0,
                                     nullptr, nullptr, nullptr, nullptr);
}

__global__ __launch_bounds__(256, 3) void gemm_ffn1(
    const bf16* __restrict__ h1_hi, const bf16* __restrict__ h1_lo,
    const bf16* __restrict__ W1_hi, const bf16* __restrict__ W1_lo,
    const float* __restrict__ bf1,
    bf16* __restrict__ t_hi, bf16* __restrict__ t_lo)
{
    gemm_core<128, 64, true, 1>(h1_hi, h1_lo, 128, W1_hi, W1_lo, 256, bf1,
                                nullptr, t_hi, t_lo, 256, blockIdx.y * 64, blockIdx.x * 128,
                                nullptr, nullptr, nullptr, nullptr);
}

__global__ __launch_bounds__(256, 2) void gemm_ffn2_ln(
    const bf16* __restrict__ t_hi, const bf16* __restrict__ t_lo,
    const bf16* __restrict__ W2_hi, const bf16* __restrict__ W2_lo,
    const float* __restrict__ bf2,
    const float* __restrict__ h1, const float* __restrict__ g2,
    const float* __restrict__ be2, float* __restrict__ out)
{
    gemm_core<256, 128, false, 2>(t_hi, t_lo, 256, W2_hi, W2_lo, 128, bf2,
                                  nullptr, nullptr, nullptr, 128, 0, blockIdx.x * 128,
                                  h1, g2, be2, out);
}

// ---------------- fused edge aggregation + LN1 ----------------
__global__ __launch_bounds__(256) void edge_agg_ln(
    const float* __restrict__ fs, const float* __restrict__ fd,
    const int* __restrict__ eoff, const int* __restrict__ ecnt,
    const int* __restrict__ esrc, const float* __restrict__ attn,
    const float* __restrict__ resid,
    const float* __restrict__ g, const float* __restrict__ b,
    float* __restrict__ out, bf16* __restrict__ out_hi, bf16* __restrict__ out_lo)
{
    int d = blockIdx.x * 8 + (threadIdx.x >> 5);
    if (d >= NN) return;
    int lane = threadIdx.x & 31;

    float4 va = reinterpret_cast<const float4*>(attn)[lane];
    float4 vd = reinterpret_cast<const float4*>(fd)[(size_t)d * 32 + lane];

    int i = eoff[d];
    int end = i + ecnt[d];

    float4 acc = make_float4(0.f, 0.f, 0.f, 0.f);
    float den = 0.0f;

    for (; i + 1 < end; i += 2) {
        int s0 = __ldg(esrc + i);
        int s1 = __ldg(esrc + i + 1);
        float4 vs0 = reinterpret_cast<const float4*>(fs)[(size_t)s0 * 32 + lane];
        float4 vs1 = reinterpret_cast<const float4*>(fs)[(size_t)s1 * 32 + lane];

        float x, sum0 = 0.0f, sum1 = 0.0f;
        x = vs0.x + vd.x; x = (x > 0.f) ? x : NEG_SLOPE * x; sum0 += x * va.x;
        x = vs0.y + vd.y; x = (x > 0.f) ? x : NEG_SLOPE * x; sum0 += x * va.y;
        x = vs0.z + vd.z; x = (x > 0.f) ? x : NEG_SLOPE * x; sum0 += x * va.z;
        x = vs0.w + vd.w; x = (x > 0.f) ? x : NEG_SLOPE * x; sum0 += x * va.w;
        x = vs1.x + vd.x; x = (x > 0.f) ? x : NEG_SLOPE * x; sum1 += x * va.x;
        x = vs1.y + vd.y; x = (x > 0.f) ? x : NEG_SLOPE * x; sum1 += x * va.y;
        x = vs1.z + vd.z; x = (x > 0.f) ? x : NEG_SLOPE * x; sum1 += x * va.z;
        x = vs1.w + vd.w; x = (x > 0.f) ? x : NEG_SLOPE * x; sum1 += x * va.w;

        sum0 += __shfl_xor_sync(0xffffffffu, sum0, 4);
        sum0 += __shfl_xor_sync(0xffffffffu, sum0, 2);
        sum0 += __shfl_xor_sync(0xffffffffu, sum0, 1);
        sum1 += __shfl_xor_sync(0xffffffffu, sum1, 4);
        sum1 += __shfl_xor_sync(0xffffffffu, sum1, 2);
        sum1 += __shfl_xor_sync(0xffffffffu, sum1, 1);

        float a0 = __expf(sum0);
        float a1 = __expf(sum1);
        acc.x += vs0.x * a0 + vs1.x * a1;
        acc.y += vs0.y * a0 + vs1.y * a1;
        acc.z += vs0.z * a0 + vs1.z * a1;
        acc.w += vs0.w * a0 + vs1.w * a1;
        den += a0 + a1;
    }
    if (i < end) {
        int s = __ldg(esrc + i);
        float4 vs = reinterpret_cast<const float4*>(fs)[(size_t)s * 32 + lane];
        float x, sum = 0.0f;
        x = vs.x + vd.x; x = (x > 0.f) ? x : NEG_SLOPE * x; sum += x * va.x;
        x = vs.y + vd.y; x = (x > 0.f) ? x : NEG_SLOPE * x; sum += x * va.y;
        x = vs.z + vd.z; x = (x > 0.f) ? x : NEG_SLOPE * x; sum += x * va.z;
        x = vs.w + vd.w; x = (x > 0.f) ? x : NEG_SLOPE * x; sum += x * va.w;
        sum += __shfl_xor_sync(0xffffffffu, sum, 4);
        sum += __shfl_xor_sync(0xffffffffu, sum, 2);
        sum += __shfl_xor_sync(0xffffffffu, sum, 1);
        float a = __expf(sum);
        acc.x += vs.x * a; acc.y += vs.y * a;
        acc.z += vs.z * a; acc.w += vs.w * a;
        den += a;
    }

    den = (den == 0.0f) ? 1.0f : den;
    float inv = 1.0f / den;
    float4 rv = reinterpret_cast<const float4*>(resid)[(size_t)d * 32 + lane];
    float4 v;
    v.x = acc.x * inv + rv.x; v.y = acc.y * inv + rv.y;
    v.z = acc.z * inv + rv.z; v.w = acc.w * inv + rv.w;

    float s1 = v.x + v.y + v.z + v.w;
    float s2 = v.x * v.x + v.y * v.y + v.z * v.z + v.w * v.w;
    #pragma unroll
    for (int off = 16; off > 0; off >>= 1) {
        s1 += __shfl_xor_sync(0xffffffffu, s1, off);
        s2 += __shfl_xor_sync(0xffffffffu, s2, off);
    }
    float mu = s1 * (1.0f / HID);
    float var = s2 * (1.0f / HID) - mu * mu;
    float rstd = rsqrtf(var + LN_EPS);

    float4 gg = reinterpret_cast<const float4*>(g)[lane];
    float4 bb = reinterpret_cast<const float4*>(b)[lane];
    float4 o;
    o.x = (v.x - mu) * rstd * gg.x + bb.x;
    o.y = (v.y - mu) * rstd * gg.y + bb.y;
    o.z = (v.z - mu) * rstd * gg.z + bb.z;
    o.w = (v.w - mu) * rstd * gg.w + bb.w;
    reinterpret_cast<float4*>(out)[(size_t)d * 32 + lane] = o;

    uint2 h, l;
    split4(o, h, l);
    reinterpret_cast<uint2*>(out_hi)[(size_t)d * 32 + lane] = h;
    reinterpret_cast<uint2*>(out_lo)[(size_t)d * 32 + lane] = l;
}

// ---------------- launcher ----------------
extern "C" void kernel_launch(void* const* d_in, const int* in_sizes, int n_in,
                              void* d_out, int out_size)
{
    const float* h    = (const float*)d_in[0];
    const int*   src  = (const int*)  d_in[1];
    const int*   dst  = (const int*)  d_in[2];
    const float* Wsrc = (const float*)d_in[3];
    const float* bsrc = (const float*)d_in[4];
    const float* Wdst = (const float*)d_in[5];
    const float* bdst = (const float*)d_in[6];
    const float* attn = (const float*)d_in[7];
    const float* W1   = (const float*)d_in[8];
    const float* bf1  = (const float*)d_in[9];
    const float* W2   = (const float*)d_in[10];
    const float* bf2  = (const float*)d_in[11];
    const float* g1   = (const float*)d_in[12];
    const float* be1  = (const float*)d_in[13];
    const float* g2   = (const float*)d_in[14];
    const float* be2  = (const float*)d_in[15];
    float* out = (float*)d_out;

    float *fs, *fd, *h1;
    int *ecnt, *eoff, *cursor, *bsum, *esrc;
    bf16 *h_hi, *h_lo, *h1_hi, *h1_lo, *t_hi, *t_lo;
    bf16 *Ws_hi, *Ws_lo, *Wd_hi, *Wd_lo, *W1_hi, *W1_lo, *W2_hi, *W2_lo;
    cudaGetSymbolAddress((void**)&fs,    g_fs);
    cudaGetSymbolAddress((void**)&fd,    g_fd);
    cudaGetSymbolAddress((void**)&h1,    g_h1);
    cudaGetSymbolAddress((void**)&ecnt,  g_ecnt);
    cudaGetSymbolAddress((void**)&eoff,  g_eoff);
    cudaGetSymbolAddress((void**)&cursor,g_cursor);
    cudaGetSymbolAddress((void**)&bsum,  g_bsum);
    cudaGetSymbolAddress((void**)&esrc,  g_esrc);
    cudaGetSymbolAddress((void**)&h_hi,  g_h_hi);
    cudaGetSymbolAddress((void**)&h_lo,  g_h_lo);
    cudaGetSymbolAddress((void**)&h1_hi, g_h1_hi);
    cudaGetSymbolAddress((void**)&h1_lo, g_h1_lo);
    cudaGetSymbolAddress((void**)&t_hi,  g_t_hi);
    cudaGetSymbolAddress((void**)&t_lo,  g_t_lo);
    cudaGetSymbolAddress((void**)&Ws_hi, g_Wsrc_hi);
    cudaGetSymbolAddress((void**)&Ws_lo, g_Wsrc_lo);
    cudaGetSymbolAddress((void**)&Wd_hi, g_Wdst_hi);
    cudaGetSymbolAddress((void**)&Wd_lo, g_Wdst_lo);
    cudaGetSymbolAddress((void**)&W1_hi, g_W1_hi);
    cudaGetSymbolAddress((void**)&W1_lo, g_W1_lo);
    cudaGetSymbolAddress((void**)&W2_hi, g_W2_hi);
    cudaGetSymbolAddress((void**)&W2_lo, g_W2_lo);

    const int SM64 = SMB(64);    // 71680
    const int SM128 = SMB(128);  // 92160
    cudaFuncSetAttribute(gemm_srcdst,  cudaFuncAttributeMaxDynamicSharedMemorySize, SM64);
    cudaFuncSetAttribute(gemm_ffn1,    cudaFuncAttributeMaxDynamicSharedMemorySize, SM64);
    cudaFuncSetAttribute(gemm_ffn2_ln, cudaFuncAttributeMaxDynamicSharedMemorySize, SM128);

    // one-time stream/event setup (first call = correctness run, outside capture)
    static cudaStream_t s_side = nullptr;
    static cudaEvent_t ev_fork = nullptr, ev_join = nullptr;
    if (s_side == nullptr) {
        cudaStreamCreateWithFlags(&s_side, cudaStreamNonBlocking);
        cudaEventCreateWithFlags(&ev_fork, cudaEventDisableTiming);
        cudaEventCreateWithFlags(&ev_join, cudaEventDisableTiming);
    }

    const int GXM = NPAD / 128;   // 391
    const int NB = (NN + 511) / 512;

    // main stream: memset + merged prep (hist/split_h/split_weights)
    cudaMemsetAsync(ecnt, 0, NN * sizeof(int));
    prep_kernel<<<PREP_TOTAL_B, 256>>>(dst, ecnt, h, h_hi, h_lo,          // launch 1
                                       Wsrc, Wdst, W1, W2,
                                       Ws_hi, Ws_lo, Wd_hi, Wd_lo,
                                       W1_hi, W1_lo, W2_hi, W2_lo,
                                       h1_hi, h1_lo);

    // fork: CSR scan/scatter on side stream, concurrent with gemm_srcdst
    cudaEventRecord(ev_fork, 0);
    cudaStreamWaitEvent(s_side, ev_fork, 0);
    scan1<<<NB, 512, 0, s_side>>>(ecnt, eoff, bsum);                      // launch 2
    scan2<<<1, 128, 0, s_side>>>(bsum, NB);                               // launch 3
    scan3<<<NB, 512, 0, s_side>>>(eoff, bsum, cursor);                    // launch 4
    scatter_kernel<<<(EE + 255) / 256, 256, 0, s_side>>>(src, dst, cursor, esrc); // launch 5
    cudaEventRecord(ev_join, s_side);

    gemm_srcdst<<<dim3(GXM, 4), 256, SM64>>>(h_hi, h_lo,                  // launch 6 <- captured
                                             Ws_hi, Ws_lo, bsrc,
                                             Wd_hi, Wd_lo, bdst, fs, fd);

    // join: edge pass needs both fs/fd and CSR
    cudaStreamWaitEvent(0, ev_join, 0);

    edge_agg_ln<<<(NN + 7) / 8, 256>>>(fs, fd, eoff, ecnt, esrc, attn,
                                       h, g1, be1, h1, h1_hi, h1_lo);

    gemm_ffn1<<<dim3(GXM, 4), 256, SM64>>>(h1_hi, h1_lo, W1_hi, W1_lo,
                                           bf1, t_hi, t_lo);
    gemm_ffn2_ln<<<dim3(GXM, 1), 256, SM128>>>(t_hi, t_lo, W2_hi, W2_lo,
                                               bf2, h1, g2, be2, out);
}

// round 12
// speedup vs baseline: 2.7510x; 1.2240x over previous
#include <cuda_runtime.h>
#include <cuda_bf16.h>
#include <cuda_fp16.h>
#include <mma.h>
#include <math.h>

using namespace nvcuda;
typedef __half hf;

// ---------------- problem constants ----------------
#define NN 50000
#define NPAD 50048            // 391 * 128
#define EE 600000
#define HID 128
#define NEG_SLOPE 0.2f
#define LN_EPS 1e-5f

// GEMM tile geometry: BM=128, BK=32, 2-stage cp.async; fp16 2-product scheme
// A: single fp16 plane; B: fp16 hi+lo planes.
#define LDA_SM 48
#define A_ST (128 * LDA_SM)                          // 6144 halves per stage
#define BST(BN) (32 * ((BN) + 8))
#define SMB(BN) ((2 * A_ST + 4 * BST(BN)) * 2 + 16 * (BN) * 4)
// SMB(64) = 47104 -> 3 CTA/SM ; SMB(128) = 67584 -> 3 CTA/SM

// prep kernel block partition
#define PREP_HIST_B ((EE + 255) / 256)
#define PREP_SPH_B  ((NPAD * 32 + 255) / 256)
#define PREP_SPW_B  ((24576 + (NPAD - NN) * 32 + 255) / 256)
#define PREP_TOTAL_B (PREP_HIST_B + PREP_SPH_B + PREP_SPW_B)

// ---------------- scratch ----------------
__device__ float g_fs[NPAD * HID];
__device__ float g_fd[NPAD * HID];
__device__ float g_h1[NPAD * HID];
// CSR scratch
__device__ int g_ecnt[NN];
__device__ int g_eoff[NN];
__device__ int g_cursor[NN];
__device__ int g_bsum[128];
__device__ int g_esrc[EE];
// fp16 operands
__device__ hf g_h_f16[NPAD * HID];        // activations: single plane
__device__ hf g_h1_f16[NPAD * HID];
__device__ hf g_t_f16[NPAD * 2 * HID];
__device__ hf g_Ws_hi[HID * HID];         // weights: hi+lo planes
__device__ hf g_Ws_lo[HID * HID];
__device__ hf g_Wd_hi[HID * HID];
__device__ hf g_Wd_lo[HID * HID];
__device__ hf g_W1_hi[HID * 2 * HID];
__device__ hf g_W1_lo[HID * 2 * HID];
__device__ hf g_W2_hi[2 * HID * HID];
__device__ hf g_W2_lo[2 * HID * HID];

// ---------------- cp.async helpers ----------------
__device__ __forceinline__ void cp16(void* smem, const void* gmem) {
    unsigned saddr = (unsigned)__cvta_generic_to_shared(smem);
    asm volatile("cp.async.cg.shared.global [%0], [%1], 16;" :: "r"(saddr), "l"(gmem));
}
__device__ __forceinline__ void cp_commit() {
    asm volatile("cp.async.commit_group;" ::: "memory");
}
template <int N>
__device__ __forceinline__ void cp_wait() {
    asm volatile("cp.async.wait_group %0;" :: "n"(N) : "memory");
}

// ---------------- conversion helpers ----------------
__device__ __forceinline__ uint2 f4_to_h4(float4 v) {
    __half2 p0 = __floats2half2_rn(v.x, v.y);
    __half2 p1 = __floats2half2_rn(v.z, v.w);
    uint2 u;
    u.x = *reinterpret_cast<unsigned*>(&p0);
    u.y = *reinterpret_cast<unsigned*>(&p1);
    return u;
}

// ---------------- merged prep: hist + h->fp16 + weight hi/lo split ----------------
__global__ void prep_kernel(
    const int* __restrict__ dst, int* __restrict__ cnt,
    const float* __restrict__ h, hf* __restrict__ h_f16,
    const float* __restrict__ Ws, const float* __restrict__ Wd,
    const float* __restrict__ W1, const float* __restrict__ W2,
    hf* __restrict__ Ws_hi, hf* __restrict__ Ws_lo,
    hf* __restrict__ Wd_hi, hf* __restrict__ Wd_lo,
    hf* __restrict__ W1_hi, hf* __restrict__ W1_lo,
    hf* __restrict__ W2_hi, hf* __restrict__ W2_lo,
    hf* __restrict__ h1_f16)
{
    int b = blockIdx.x;
    if (b < PREP_HIST_B) {
        int e = b * 256 + threadIdx.x;
        if (e < EE) atomicAdd(&cnt[dst[e]], 1);
        return;
    }
    b -= PREP_HIST_B;
    if (b < PREP_SPH_B) {
        int i = b * 256 + threadIdx.x;
        if (i >= NPAD * 32) return;
        int row = i >> 5;
        float4 v = make_float4(0.f, 0.f, 0.f, 0.f);
        if (row < NN) v = reinterpret_cast<const float4*>(h)[i];
        reinterpret_cast<uint2*>(h_f16)[i] = f4_to_h4(v);
        return;
    }
    b -= PREP_SPH_B;
    {
        int i = b * 256 + threadIdx.x;
        if (i >= 24576 + (NPAD - NN) * 32) return;
        if (i >= 24576) {
            int j = i - 24576;
            reinterpret_cast<uint2*>(h1_f16 + (size_t)NN * HID)[j] = make_uint2(0u, 0u);
            return;
        }
        const float* s; hf *ph, *pl; int j = i;
        if (j < 4096)        { s = Ws; ph = Ws_hi; pl = Ws_lo; }
        else if (j < 8192)   { j -= 4096;  s = Wd; ph = Wd_hi; pl = Wd_lo; }
        else if (j < 16384)  { j -= 8192;  s = W1; ph = W1_hi; pl = W1_lo; }
        else                 { j -= 16384; s = W2; ph = W2_hi; pl = W2_lo; }
        float4 v = reinterpret_cast<const float4*>(s)[j];
        float vv[4] = {v.x, v.y, v.z, v.w};
        hf hh[4], ll[4];
        #pragma unroll
        for (int q = 0; q < 4; q++) {
            hh[q] = __float2half_rn(vv[q]);
            ll[q] = __float2half_rn(vv[q] - __half2float(hh[q]));
        }
        reinterpret_cast<uint2*>(ph)[j] = make_uint2(
            (unsigned)__half_as_ushort(hh[0]) | ((unsigned)__half_as_ushort(hh[1]) << 16),
            (unsigned)__half_as_ushort(hh[2]) | ((unsigned)__half_as_ushort(hh[3]) << 16));
        reinterpret_cast<uint2*>(pl)[j] = make_uint2(
            (unsigned)__half_as_ushort(ll[0]) | ((unsigned)__half_as_ushort(ll[1]) << 16),
            (unsigned)__half_as_ushort(ll[2]) | ((unsigned)__half_as_ushort(ll[3]) << 16));
    }
}

// ---------------- CSR scan/scatter ----------------
__global__ void scan1(const int* __restrict__ cnt, int* __restrict__ excl,
                      int* __restrict__ bsum) {
    __shared__ int sh[512];
    int i = blockIdx.x * 512 + threadIdx.x;
    int v = (i < NN) ? cnt[i] : 0;
    sh[threadIdx.x] = v;
    __syncthreads();
    #pragma unroll
    for (int off = 1; off < 512; off <<= 1) {
        int t = (threadIdx.x >= off) ? sh[threadIdx.x - off] : 0;
        __syncthreads();
        sh[threadIdx.x] += t;
        __syncthreads();
    }
    if (i < NN) excl[i] = sh[threadIdx.x] - v;
    if (threadIdx.x == 511) bsum[blockIdx.x] = sh[511];
}

__global__ void scan2(int* __restrict__ bsum, int nb) {
    __shared__ int sh[128];
    int v = (threadIdx.x < nb) ? bsum[threadIdx.x] : 0;
    sh[threadIdx.x] = v;
    __syncthreads();
    #pragma unroll
    for (int off = 1; off < 128; off <<= 1) {
        int t = (threadIdx.x >= off) ? sh[threadIdx.x - off] : 0;
        __syncthreads();
        sh[threadIdx.x] += t;
        __syncthreads();
    }
    if (threadIdx.x < nb) bsum[threadIdx.x] = sh[threadIdx.x] - v;
}

__global__ void scan3(int* __restrict__ excl, const int* __restrict__ bsum,
                      int* __restrict__ cursor) {
    int i = blockIdx.x * 512 + threadIdx.x;
    if (i < NN) {
        int v = excl[i] + bsum[blockIdx.x];
        excl[i] = v;
        cursor[i] = v;
    }
}

__global__ void scatter_kernel(const int* __restrict__ src, const int* __restrict__ dst,
                               int* __restrict__ cursor, int* __restrict__ esrc) {
    int e = blockIdx.x * blockDim.x + threadIdx.x;
    if (e >= EE) return;
    int pos = atomicAdd(&cursor[dst[e]], 1);
    esrc[pos] = src[e];
}

// ---------------- WMMA fp16 2-product GEMM core ----------------
// C = A_f16 @ (Bh + Bl) + bias.  EPI: 0 = fp32 store, 1 = fp16 store (+gelu),
// 2 = fused residual+LayerNorm (BN=128 only).
template <int KTOT, int BN, bool GELU, int EPI>
__device__ __forceinline__ void gemm_core(
    const hf* __restrict__ A_g, int lda,
    const hf* __restrict__ Bh_g, const hf* __restrict__ Bl_g, int ldb,
    const float* __restrict__ bias,
    float* __restrict__ C, hf* __restrict__ Cf16,
    int ldc, int ccol0, int m0,
    const float* __restrict__ resid, const float* __restrict__ lng,
    const float* __restrict__ lnb, float* __restrict__ outp)
{
    constexpr int LDB = BN + 8;
    constexpr int B_ST = 32 * LDB;
    constexpr int WN = BN / 2;
    constexpr int NJ = BN / 32;

    extern __shared__ hf sm[];
    hf* AS[2]  = { sm,            sm + A_ST };
    hf* BhS[2] = { sm + 2 * A_ST,             sm + 2 * A_ST + B_ST };
    hf* BlS[2] = { sm + 2 * A_ST + 2 * B_ST,  sm + 2 * A_ST + 3 * B_ST };
    float* bias_sm = (float*)(sm + 2 * A_ST + 4 * B_ST);

    const int tid = threadIdx.x;
    const int wid = tid >> 5;
    const int wm = wid >> 1;
    const int wn = wid & 1;

    constexpr int KC = KTOT / 32;

    auto load_stage = [&](int kc, int st) {
        #pragma unroll
        for (int i = tid; i < 512; i += 256) {
            int r = i >> 2, c8 = (i & 3) * 8;
            size_t go = (size_t)(m0 + r) * lda + kc * 32 + c8;
            cp16(AS[st] + r * LDA_SM + c8, A_g + go);
        }
        constexpr int BI = 32 * (BN / 8);
        #pragma unroll
        for (int i = tid; i < BI; i += 256) {
            int r = i / (BN / 8), c8 = (i % (BN / 8)) * 8;
            size_t go = (size_t)(kc * 32 + r) * ldb + ccol0 + c8;
            cp16(BhS[st] + r * LDB + c8, Bh_g + go);
            cp16(BlS[st] + r * LDB + c8, Bl_g + go);
        }
        cp_commit();
    };

    load_stage(0, 0);

    for (int i = tid; i < 16 * BN; i += 256)
        bias_sm[i] = bias[ccol0 + (i & (BN - 1))];
    __syncthreads();

    wmma::fragment<wmma::accumulator, 16, 16, 16, float> acc[2][NJ];
    #pragma unroll
    for (int mi = 0; mi < 2; mi++)
        #pragma unroll
        for (int nj = 0; nj < NJ; nj++)
            wmma::load_matrix_sync(acc[mi][nj], bias_sm + wn * WN + nj * 16, BN, wmma::mem_row_major);

    #pragma unroll
    for (int kc = 0; kc < KC; kc++) {
        if (kc + 1 < KC) load_stage(kc + 1, (kc + 1) & 1);
        if (kc + 1 < KC) cp_wait<1>(); else cp_wait<0>();
        __syncthreads();

        const int st = kc & 1;
        #pragma unroll
        for (int kk = 0; kk < 2; kk++) {
            wmma::fragment<wmma::matrix_a, 16, 16, 16, hf, wmma::row_major> a[2];
            wmma::fragment<wmma::matrix_b, 16, 16, 16, hf, wmma::row_major> bh[NJ], bl[NJ];
            #pragma unroll
            for (int mi = 0; mi < 2; mi++)
                wmma::load_matrix_sync(a[mi], AS[st] + (wm * 32 + mi * 16) * LDA_SM + kk * 16, LDA_SM);
            #pragma unroll
            for (int nj = 0; nj < NJ; nj++) {
                wmma::load_matrix_sync(bh[nj], BhS[st] + (kk * 16) * LDB + wn * WN + nj * 16, LDB);
                wmma::load_matrix_sync(bl[nj], BlS[st] + (kk * 16) * LDB + wn * WN + nj * 16, LDB);
            }
            #pragma unroll
            for (int mi = 0; mi < 2; mi++)
                #pragma unroll
                for (int nj = 0; nj < NJ; nj++) {
                    wmma::mma_sync(acc[mi][nj], a[mi], bh[nj], acc[mi][nj]);
                    wmma::mma_sync(acc[mi][nj], a[mi], bl[nj], acc[mi][nj]);
                }
        }
        __syncthreads();
    }

    if (GELU) {
        #pragma unroll
        for (int mi = 0; mi < 2; mi++)
            #pragma unroll
            for (int nj = 0; nj < NJ; nj++)
                #pragma unroll
                for (int i = 0; i < acc[mi][nj].num_elements; i++) {
                    float x = acc[mi][nj].x[i];
                    acc[mi][nj].x[i] = 0.5f * x * (1.0f + erff(x * 0.70710678118654752f));
                }
    }

    if (EPI == 0) {
        #pragma unroll
        for (int mi = 0; mi < 2; mi++)
            #pragma unroll
            for (int nj = 0; nj < NJ; nj++) {
                float* cp = C + (size_t)(m0 + wm * 32 + mi * 16) * ldc + ccol0 + wn * WN + nj * 16;
                wmma::store_matrix_sync(cp, acc[mi][nj], ldc, wmma::mem_row_major);
            }
    } else if (EPI == 1) {
        constexpr int SS = WN + 4;
        float* stage = (float*)sm + wid * (32 * SS);
        #pragma unroll
        for (int mi = 0; mi < 2; mi++)
            #pragma unroll
            for (int nj = 0; nj < NJ; nj++)
                wmma::store_matrix_sync(stage + mi * 16 * SS + nj * 16, acc[mi][nj], SS, wmma::mem_row_major);
        __syncwarp();
        int lane = tid & 31;
        constexpr int QN = WN / 4;
        #pragma unroll
        for (int it = 0; it < QN; it++) {
            int j = it * 32 + lane;
            int r = j / QN, c4 = j % QN;
            float4 v = *reinterpret_cast<const float4*>(stage + r * SS + c4 * 4);
            size_t go = (size_t)(m0 + wm * 32 + r) * ldc + ccol0 + wn * WN + c4 * 4;
            *reinterpret_cast<uint2*>(Cf16 + go) = f4_to_h4(v);
        }
    } else {
        float* stageF = (float*)sm;
        #pragma unroll
        for (int mi = 0; mi < 2; mi++)
            #pragma unroll
            for (int nj = 0; nj < NJ; nj++)
                wmma::store_matrix_sync(stageF + (wm * 32 + mi * 16) * 132 + wn * WN + nj * 16,
                                        acc[mi][nj], 132, wmma::mem_row_major);
        __syncthreads();
        int lane = tid & 31;
        float4 gg = reinterpret_cast<const float4*>(lng)[lane];
        float4 bb = reinterpret_cast<const float4*>(lnb)[lane];
        #pragma unroll
        for (int rr = 0; rr < 16; rr++) {
            int r = wid * 16 + rr;
            int row = m0 + r;
            if (row >= NN) continue;
            float4 v = *reinterpret_cast<const float4*>(stageF + r * 132 + lane * 4);
            float4 rv = reinterpret_cast<const float4*>(resid)[(size_t)row * 32 + lane];
            v.x += rv.x; v.y += rv.y; v.z += rv.z; v.w += rv.w;

            float s1 = v.x + v.y + v.z + v.w;
            float s2 = v.x * v.x + v.y * v.y + v.z * v.z + v.w * v.w;
            #pragma unroll
            for (int off = 16; off > 0; off >>= 1) {
                s1 += __shfl_xor_sync(0xffffffffu, s1, off);
                s2 += __shfl_xor_sync(0xffffffffu, s2, off);
            }
            float mu = s1 * (1.0f / HID);
            float var = s2 * (1.0f / HID) - mu * mu;
            float rstd = rsqrtf(var + LN_EPS);

            float4 o;
            o.x = (v.x - mu) * rstd * gg.x + bb.x;
            o.y = (v.y - mu) * rstd * gg.y + bb.y;
            o.z = (v.z - mu) * rstd * gg.z + bb.z;
            o.w = (v.w - mu) * rstd * gg.w + bb.w;
            reinterpret_cast<float4*>(outp)[(size_t)row * 32 + lane] = o;
        }
    }
}

__global__ __launch_bounds__(256, 3) void gemm_srcdst(
    const hf* __restrict__ h_f16,
    const hf* __restrict__ Ws_hi, const hf* __restrict__ Ws_lo,
    const float* __restrict__ bsrc,
    const hf* __restrict__ Wd_hi, const hf* __restrict__ Wd_lo,
    const float* __restrict__ bdst,
    float* __restrict__ fs, float* __restrict__ fd)
{
    int m0 = blockIdx.x * 128;
    int y = blockIdx.y;
    int col0 = (y & 1) * 64;
    if (y < 2)
        gemm_core<128, 64, false, 0>(h_f16, 128, Ws_hi, Ws_lo, 128, bsrc,
                                     fs, nullptr, 128, col0, m0,
                                     nullptr, nullptr, nullptr, nullptr);
    else
        gemm_core<128, 64, false, 0>(h_f16, 128, Wd_hi, Wd_lo, 128, bdst,
                                     fd, nullptr, 128, col0, m0,
                                     nullptr, nullptr, nullptr, nullptr);
}

__global__ __launch_bounds__(256, 3) void gemm_ffn1(
    const hf* __restrict__ h1_f16,
    const hf* __restrict__ W1_hi, const hf* __restrict__ W1_lo,
    const float* __restrict__ bf1, hf* __restrict__ t_f16)
{
    gemm_core<128, 64, true, 1>(h1_f16, 128, W1_hi, W1_lo, 256, bf1,
                                nullptr, t_f16, 256, blockIdx.y * 64, blockIdx.x * 128,
                                nullptr, nullptr, nullptr, nullptr);
}

__global__ __launch_bounds__(256, 3) void gemm_ffn2_ln(
    const hf* __restrict__ t_f16,
    const hf* __restrict__ W2_hi, const hf* __restrict__ W2_lo,
    const float* __restrict__ bf2,
    const float* __restrict__ h1, const float* __restrict__ g2,
    const float* __restrict__ be2, float* __restrict__ out)
{
    gemm_core<256, 128, false, 2>(t_f16, 256, W2_hi, W2_lo, 128, bf2,
                                  nullptr, nullptr, 128, 0, blockIdx.x * 128,
                                  h1, g2, be2, out);
}

// ---------------- edge logit helper ----------------
__device__ __forceinline__ float edge_logit(float4 vs, float4 vd, float4 va) {
    float x, sum = 0.0f;
    x = vs.x + vd.x; x = (x > 0.f) ? x : NEG_SLOPE * x; sum += x * va.x;
    x = vs.y + vd.y; x = (x > 0.f) ? x : NEG_SLOPE * x; sum += x * va.y;
    x = vs.z + vd.z; x = (x > 0.f) ? x : NEG_SLOPE * x; sum += x * va.z;
    x = vs.w + vd.w; x = (x > 0.f) ? x : NEG_SLOPE * x; sum += x * va.w;
    sum += __shfl_xor_sync(0xffffffffu, sum, 4);
    sum += __shfl_xor_sync(0xffffffffu, sum, 2);
    sum += __shfl_xor_sync(0xffffffffu, sum, 1);
    return sum;
}

// ---------------- fused edge aggregation + LN1, 4-way unrolled ----------------
__global__ __launch_bounds__(256) void edge_agg_ln(
    const float* __restrict__ fs, const float* __restrict__ fd,
    const int* __restrict__ eoff, const int* __restrict__ ecnt,
    const int* __restrict__ esrc, const float* __restrict__ attn,
    const float* __restrict__ resid,
    const float* __restrict__ g, const float* __restrict__ b,
    float* __restrict__ out, hf* __restrict__ out_f16)
{
    int d = blockIdx.x * 8 + (threadIdx.x >> 5);
    if (d >= NN) return;
    int lane = threadIdx.x & 31;

    float4 va = reinterpret_cast<const float4*>(attn)[lane];
    float4 vd = reinterpret_cast<const float4*>(fd)[(size_t)d * 32 + lane];

    int i = eoff[d];
    int end = i + ecnt[d];

    float4 acc = make_float4(0.f, 0.f, 0.f, 0.f);
    float den = 0.0f;

    for (; i + 3 < end; i += 4) {
        int s0 = __ldg(esrc + i);
        int s1 = __ldg(esrc + i + 1);
        int s2 = __ldg(esrc + i + 2);
        int s3 = __ldg(esrc + i + 3);
        float4 v0 = reinterpret_cast<const float4*>(fs)[(size_t)s0 * 32 + lane];
        float4 v1 = reinterpret_cast<const float4*>(fs)[(size_t)s1 * 32 + lane];
        float4 v2 = reinterpret_cast<const float4*>(fs)[(size_t)s2 * 32 + lane];
        float4 v3 = reinterpret_cast<const float4*>(fs)[(size_t)s3 * 32 + lane];
        float a0 = __expf(edge_logit(v0, vd, va));
        float a1 = __expf(edge_logit(v1, vd, va));
        float a2 = __expf(edge_logit(v2, vd, va));
        float a3 = __expf(edge_logit(v3, vd, va));
        acc.x += v0.x * a0 + v1.x * a1 + v2.x * a2 + v3.x * a3;
        acc.y += v0.y * a0 + v1.y * a1 + v2.y * a2 + v3.y * a3;
        acc.z += v0.z * a0 + v1.z * a1 + v2.z * a2 + v3.z * a3;
        acc.w += v0.w * a0 + v1.w * a1 + v2.w * a2 + v3.w * a3;
        den += a0 + a1 + a2 + a3;
    }
    for (; i < end; i++) {
        int s = __ldg(esrc + i);
        float4 vs = reinterpret_cast<const float4*>(fs)[(size_t)s * 32 + lane];
        float a = __expf(edge_logit(vs, vd, va));
        acc.x += vs.x * a; acc.y += vs.y * a;
        acc.z += vs.z * a; acc.w += vs.w * a;
        den += a;
    }

    den = (den == 0.0f) ? 1.0f : den;
    float inv = 1.0f / den;
    float4 rv = reinterpret_cast<const float4*>(resid)[(size_t)d * 32 + lane];
    float4 v;
    v.x = acc.x * inv + rv.x; v.y = acc.y * inv + rv.y;
    v.z = acc.z * inv + rv.z; v.w = acc.w * inv + rv.w;

    float s1 = v.x + v.y + v.z + v.w;
    float s2 = v.x * v.x + v.y * v.y + v.z * v.z + v.w * v.w;
    #pragma unroll
    for (int off = 16; off > 0; off >>= 1) {
        s1 += __shfl_xor_sync(0xffffffffu, s1, off);
        s2 += __shfl_xor_sync(0xffffffffu, s2, off);
    }
    float mu = s1 * (1.0f / HID);
    float var = s2 * (1.0f / HID) - mu * mu;
    float rstd = rsqrtf(var + LN_EPS);

    float4 gg = reinterpret_cast<const float4*>(g)[lane];
    float4 bb = reinterpret_cast<const float4*>(b)[lane];
    float4 o;
    o.x = (v.x - mu) * rstd * gg.x + bb.x;
    o.y = (v.y - mu) * rstd * gg.y + bb.y;
    o.z = (v.z - mu) * rstd * gg.z + bb.z;
    o.w = (v.w - mu) * rstd * gg.w + bb.w;
    reinterpret_cast<float4*>(out)[(size_t)d * 32 + lane] = o;
    reinterpret_cast<uint2*>(out_f16)[(size_t)d * 32 + lane] = f4_to_h4(o);
}

// ---------------- launcher ----------------
extern "C" void kernel_launch(void* const* d_in, const int* in_sizes, int n_in,
                              void* d_out, int out_size)
{
    const float* h    = (const float*)d_in[0];
    const int*   src  = (const int*)  d_in[1];
    const int*   dst  = (const int*)  d_in[2];
    const float* Wsrc = (const float*)d_in[3];
    const float* bsrc = (const float*)d_in[4];
    const float* Wdst = (const float*)d_in[5];
    const float* bdst = (const float*)d_in[6];
    const float* attn = (const float*)d_in[7];
    const float* W1   = (const float*)d_in[8];
    const float* bf1  = (const float*)d_in[9];
    const float* W2   = (const float*)d_in[10];
    const float* bf2  = (const float*)d_in[11];
    const float* g1   = (const float*)d_in[12];
    const float* be1  = (const float*)d_in[13];
    const float* g2   = (const float*)d_in[14];
    const float* be2  = (const float*)d_in[15];
    float* out = (float*)d_out;

    float *fs, *fd, *h1;
    int *ecnt, *eoff, *cursor, *bsum, *esrc;
    hf *h_f16, *h1_f16, *t_f16;
    hf *Ws_hi, *Ws_lo, *Wd_hi, *Wd_lo, *W1_hi, *W1_lo, *W2_hi, *W2_lo;
    cudaGetSymbolAddress((void**)&fs,    g_fs);
    cudaGetSymbolAddress((void**)&fd,    g_fd);
    cudaGetSymbolAddress((void**)&h1,    g_h1);
    cudaGetSymbolAddress((void**)&ecnt,  g_ecnt);
    cudaGetSymbolAddress((void**)&eoff,  g_eoff);
    cudaGetSymbolAddress((void**)&cursor,g_cursor);
    cudaGetSymbolAddress((void**)&bsum,  g_bsum);
    cudaGetSymbolAddress((void**)&esrc,  g_esrc);
    cudaGetSymbolAddress((void**)&h_f16, g_h_f16);
    cudaGetSymbolAddress((void**)&h1_f16,g_h1_f16);
    cudaGetSymbolAddress((void**)&t_f16, g_t_f16);
    cudaGetSymbolAddress((void**)&Ws_hi, g_Ws_hi);
    cudaGetSymbolAddress((void**)&Ws_lo, g_Ws_lo);
    cudaGetSymbolAddress((void**)&Wd_hi, g_Wd_hi);
    cudaGetSymbolAddress((void**)&Wd_lo, g_Wd_lo);
    cudaGetSymbolAddress((void**)&W1_hi, g_W1_hi);
    cudaGetSymbolAddress((void**)&W1_lo, g_W1_lo);
    cudaGetSymbolAddress((void**)&W2_hi, g_W2_hi);
    cudaGetSymbolAddress((void**)&W2_lo, g_W2_lo);

    const int SM64 = SMB(64);    // 47104
    const int SM128 = SMB(128);  // 67584
    cudaFuncSetAttribute(gemm_srcdst,  cudaFuncAttributeMaxDynamicSharedMemorySize, SM64);
    cudaFuncSetAttribute(gemm_ffn1,    cudaFuncAttributeMaxDynamicSharedMemorySize, SM64);
    cudaFuncSetAttribute(gemm_ffn2_ln, cudaFuncAttributeMaxDynamicSharedMemorySize, SM128);

    static cudaStream_t s_side = nullptr;
    static cudaEvent_t ev_fork = nullptr, ev_join = nullptr;
    if (s_side == nullptr) {
        cudaStreamCreateWithFlags(&s_side, cudaStreamNonBlocking);
        cudaEventCreateWithFlags(&ev_fork, cudaEventDisableTiming);
        cudaEventCreateWithFlags(&ev_join, cudaEventDisableTiming);
    }

    const int GXM = NPAD / 128;   // 391
    const int NB = (NN + 511) / 512;

    cudaMemsetAsync(ecnt, 0, NN * sizeof(int));
    prep_kernel<<<PREP_TOTAL_B, 256>>>(dst, ecnt, h, h_f16,
                                       Wsrc, Wdst, W1, W2,
                                       Ws_hi, Ws_lo, Wd_hi, Wd_lo,
                                       W1_hi, W1_lo, W2_hi, W2_lo, h1_f16);

    // fork: CSR chain concurrent with gemm_srcdst
    cudaEventRecord(ev_fork, 0);
    cudaStreamWaitEvent(s_side, ev_fork, 0);
    scan1<<<NB, 512, 0, s_side>>>(ecnt, eoff, bsum);
    scan2<<<1, 128, 0, s_side>>>(bsum, NB);
    scan3<<<NB, 512, 0, s_side>>>(eoff, bsum, cursor);
    scatter_kernel<<<(EE + 255) / 256, 256, 0, s_side>>>(src, dst, cursor, esrc);
    cudaEventRecord(ev_join, s_side);

    gemm_srcdst<<<dim3(GXM, 4), 256, SM64>>>(h_f16, Ws_hi, Ws_lo, bsrc,
                                             Wd_hi, Wd_lo, bdst, fs, fd);

    cudaStreamWaitEvent(0, ev_join, 0);

    edge_agg_ln<<<(NN + 7) / 8, 256>>>(fs, fd, eoff, ecnt, esrc, attn,
                                       h, g1, be1, h1, h1_f16);

    gemm_ffn1<<<dim3(GXM, 4), 256, SM64>>>(h1_f16, W1_hi, W1_lo, bf1, t_f16);
    gemm_ffn2_ln<<<dim3(GXM, 1), 256, SM128>>>(t_f16, W2_hi, W2_lo,
                                               bf2, h1, g2, be2, out);
}

// round 13
// speedup vs baseline: 3.0420x; 1.1058x over previous
#include <cuda_runtime.h>
#include <cuda_fp16.h>
#include <mma.h>
#include <math.h>

using namespace nvcuda;
typedef __half hf;

// ---------------- problem constants ----------------
#define NN 50000
#define NPAD 50048            // 391 * 128
#define EE 600000
#define HID 128
#define NEG_SLOPE 0.2f
#define LN_EPS 1e-5f

// GEMM: BM=128, BK=32, 2-stage cp.async; pure fp16 operands (1 MMA product)
#define LDA_SM 48
#define A_ST (128 * LDA_SM)
#define BST(BN) (32 * ((BN) + 8))
#define SMB(BN) ((2 * A_ST + 2 * BST(BN)) * 2 + 16 * (BN) * 4)
// SMB(64) = 37888 ; ffn2 needs the 128x132 fp32 LN stage = 67584
#define SM_FFN2 67584

// prep kernel block partition
#define PREP_HIST_B ((EE + 255) / 256)
#define PREP_SPH_B  ((NPAD * 32 + 255) / 256)
#define PREP_SPW_B  ((24576 + (NPAD - NN) * 32 + 255) / 256)
#define PREP_TOTAL_B (PREP_HIST_B + PREP_SPH_B + PREP_SPW_B)

// ---------------- scratch ----------------
__device__ float g_h1[NPAD * HID];
// CSR scratch
__device__ int g_ecnt[NN];
__device__ int g_eoff[NN];
__device__ int g_cursor[NN];
__device__ int g_bsum[128];
__device__ int g_esrc[EE];
// fp16 tensors
__device__ hf g_fs[NPAD * HID];
__device__ hf g_fd[NPAD * HID];
__device__ hf g_h_f16[NPAD * HID];
__device__ hf g_h1_f16[NPAD * HID];
__device__ hf g_t_f16[NPAD * 2 * HID];
__device__ hf g_Ws[HID * HID];
__device__ hf g_Wd[HID * HID];
__device__ hf g_W1[HID * 2 * HID];
__device__ hf g_W2[2 * HID * HID];

// ---------------- cp.async helpers ----------------
__device__ __forceinline__ void cp16(void* smem, const void* gmem) {
    unsigned saddr = (unsigned)__cvta_generic_to_shared(smem);
    asm volatile("cp.async.cg.shared.global [%0], [%1], 16;" :: "r"(saddr), "l"(gmem));
}
__device__ __forceinline__ void cp_commit() {
    asm volatile("cp.async.commit_group;" ::: "memory");
}
template <int N>
__device__ __forceinline__ void cp_wait() {
    asm volatile("cp.async.wait_group %0;" :: "n"(N) : "memory");
}

// ---------------- conversion helpers ----------------
__device__ __forceinline__ uint2 f4_to_h4(float4 v) {
    __half2 p0 = __floats2half2_rn(v.x, v.y);
    __half2 p1 = __floats2half2_rn(v.z, v.w);
    uint2 u;
    u.x = *reinterpret_cast<unsigned*>(&p0);
    u.y = *reinterpret_cast<unsigned*>(&p1);
    return u;
}
__device__ __forceinline__ float4 h4_to_f4(uint2 u) {
    __half2 p0 = *reinterpret_cast<__half2*>(&u.x);
    __half2 p1 = *reinterpret_cast<__half2*>(&u.y);
    float2 a = __half22float2(p0);
    float2 b = __half22float2(p1);
    return make_float4(a.x, a.y, b.x, b.y);
}

// ---------------- merged prep: hist + h->fp16 + weights->fp16 ----------------
__global__ void prep_kernel(
    const int* __restrict__ dst, int* __restrict__ cnt,
    const float* __restrict__ h, hf* __restrict__ h_f16,
    const float* __restrict__ Ws, const float* __restrict__ Wd,
    const float* __restrict__ W1, const float* __restrict__ W2,
    hf* __restrict__ Wsh, hf* __restrict__ Wdh,
    hf* __restrict__ W1h, hf* __restrict__ W2h,
    hf* __restrict__ h1_f16)
{
    int b = blockIdx.x;
    if (b < PREP_HIST_B) {
        int e = b * 256 + threadIdx.x;
        if (e < EE) atomicAdd(&cnt[dst[e]], 1);
        return;
    }
    b -= PREP_HIST_B;
    if (b < PREP_SPH_B) {
        int i = b * 256 + threadIdx.x;
        if (i >= NPAD * 32) return;
        int row = i >> 5;
        float4 v = make_float4(0.f, 0.f, 0.f, 0.f);
        if (row < NN) v = reinterpret_cast<const float4*>(h)[i];
        reinterpret_cast<uint2*>(h_f16)[i] = f4_to_h4(v);
        return;
    }
    b -= PREP_SPH_B;
    {
        int i = b * 256 + threadIdx.x;
        if (i >= 24576 + (NPAD - NN) * 32) return;
        if (i >= 24576) {
            int j = i - 24576;
            reinterpret_cast<uint2*>(h1_f16 + (size_t)NN * HID)[j] = make_uint2(0u, 0u);
            return;
        }
        const float* s; hf* p; int j = i;
        if (j < 4096)        { s = Ws; p = Wsh; }
        else if (j < 8192)   { j -= 4096;  s = Wd; p = Wdh; }
        else if (j < 16384)  { j -= 8192;  s = W1; p = W1h; }
        else                 { j -= 16384; s = W2; p = W2h; }
        float4 v = reinterpret_cast<const float4*>(s)[j];
        reinterpret_cast<uint2*>(p)[j] = f4_to_h4(v);
    }
}

// ---------------- CSR scan/scatter ----------------
__global__ void scan1(const int* __restrict__ cnt, int* __restrict__ excl,
                      int* __restrict__ bsum) {
    __shared__ int sh[512];
    int i = blockIdx.x * 512 + threadIdx.x;
    int v = (i < NN) ? cnt[i] : 0;
    sh[threadIdx.x] = v;
    __syncthreads();
    #pragma unroll
    for (int off = 1; off < 512; off <<= 1) {
        int t = (threadIdx.x >= off) ? sh[threadIdx.x - off] : 0;
        __syncthreads();
        sh[threadIdx.x] += t;
        __syncthreads();
    }
    if (i < NN) excl[i] = sh[threadIdx.x] - v;
    if (threadIdx.x == 511) bsum[blockIdx.x] = sh[511];
}

__global__ void scan2(int* __restrict__ bsum, int nb) {
    __shared__ int sh[128];
    int v = (threadIdx.x < nb) ? bsum[threadIdx.x] : 0;
    sh[threadIdx.x] = v;
    __syncthreads();
    #pragma unroll
    for (int off = 1; off < 128; off <<= 1) {
        int t = (threadIdx.x >= off) ? sh[threadIdx.x - off] : 0;
        __syncthreads();
        sh[threadIdx.x] += t;
        __syncthreads();
    }
    if (threadIdx.x < nb) bsum[threadIdx.x] = sh[threadIdx.x] - v;
}

__global__ void scan3(int* __restrict__ excl, const int* __restrict__ bsum,
                      int* __restrict__ cursor) {
    int i = blockIdx.x * 512 + threadIdx.x;
    if (i < NN) {
        int v = excl[i] + bsum[blockIdx.x];
        excl[i] = v;
        cursor[i] = v;
    }
}

__global__ void scatter_kernel(const int* __restrict__ src, const int* __restrict__ dst,
                               int* __restrict__ cursor, int* __restrict__ esrc) {
    int e = blockIdx.x * blockDim.x + threadIdx.x;
    if (e >= EE) return;
    int pos = atomicAdd(&cursor[dst[e]], 1);
    esrc[pos] = src[e];
}

// ---------------- WMMA pure-fp16 GEMM core ----------------
// C = A @ B + bias.  EPI: 1 = fp16 store (+optional gelu), 2 = fused resid+LN.
template <int KTOT, int BN, bool GELU, int EPI>
__device__ __forceinline__ void gemm_core(
    const hf* __restrict__ A_g, int lda,
    const hf* __restrict__ B_g, int ldb,
    const float* __restrict__ bias,
    hf* __restrict__ Cf16,
    int ldc, int ccol0, int m0,
    const float* __restrict__ resid, const float* __restrict__ lng,
    const float* __restrict__ lnb, float* __restrict__ outp)
{
    constexpr int LDB = BN + 8;
    constexpr int B_ST = 32 * LDB;
    constexpr int WN = BN / 2;
    constexpr int NJ = BN / 32;

    extern __shared__ hf sm[];
    hf* AS[2] = { sm,            sm + A_ST };
    hf* BS[2] = { sm + 2 * A_ST, sm + 2 * A_ST + B_ST };
    float* bias_sm = (float*)(sm + 2 * A_ST + 2 * B_ST);

    const int tid = threadIdx.x;
    const int wid = tid >> 5;
    const int wm = wid >> 1;
    const int wn = wid & 1;

    constexpr int KC = KTOT / 32;

    auto load_stage = [&](int kc, int st) {
        #pragma unroll
        for (int i = tid; i < 512; i += 256) {
            int r = i >> 2, c8 = (i & 3) * 8;
            size_t go = (size_t)(m0 + r) * lda + kc * 32 + c8;
            cp16(AS[st] + r * LDA_SM + c8, A_g + go);
        }
        constexpr int BI = 32 * (BN / 8);
        #pragma unroll
        for (int i = tid; i < BI; i += 256) {
            int r = i / (BN / 8), c8 = (i % (BN / 8)) * 8;
            size_t go = (size_t)(kc * 32 + r) * ldb + ccol0 + c8;
            cp16(BS[st] + r * LDB + c8, B_g + go);
        }
        cp_commit();
    };

    load_stage(0, 0);

    for (int i = tid; i < 16 * BN; i += 256)
        bias_sm[i] = bias[ccol0 + (i & (BN - 1))];
    __syncthreads();

    wmma::fragment<wmma::accumulator, 16, 16, 16, float> acc[2][NJ];
    #pragma unroll
    for (int mi = 0; mi < 2; mi++)
        #pragma unroll
        for (int nj = 0; nj < NJ; nj++)
            wmma::load_matrix_sync(acc[mi][nj], bias_sm + wn * WN + nj * 16, BN, wmma::mem_row_major);

    #pragma unroll
    for (int kc = 0; kc < KC; kc++) {
        if (kc + 1 < KC) load_stage(kc + 1, (kc + 1) & 1);
        if (kc + 1 < KC) cp_wait<1>(); else cp_wait<0>();
        __syncthreads();

        const int st = kc & 1;
        #pragma unroll
        for (int kk = 0; kk < 2; kk++) {
            wmma::fragment<wmma::matrix_a, 16, 16, 16, hf, wmma::row_major> a[2];
            wmma::fragment<wmma::matrix_b, 16, 16, 16, hf, wmma::row_major> bfr[NJ];
            #pragma unroll
            for (int mi = 0; mi < 2; mi++)
                wmma::load_matrix_sync(a[mi], AS[st] + (wm * 32 + mi * 16) * LDA_SM + kk * 16, LDA_SM);
            #pragma unroll
            for (int nj = 0; nj < NJ; nj++)
                wmma::load_matrix_sync(bfr[nj], BS[st] + (kk * 16) * LDB + wn * WN + nj * 16, LDB);
            #pragma unroll
            for (int mi = 0; mi < 2; mi++)
                #pragma unroll
                for (int nj = 0; nj < NJ; nj++)
                    wmma::mma_sync(acc[mi][nj], a[mi], bfr[nj], acc[mi][nj]);
        }
        __syncthreads();
    }

    if (GELU) {
        #pragma unroll
        for (int mi = 0; mi < 2; mi++)
            #pragma unroll
            for (int nj = 0; nj < NJ; nj++)
                #pragma unroll
                for (int i = 0; i < acc[mi][nj].num_elements; i++) {
                    float x = acc[mi][nj].x[i];
                    acc[mi][nj].x[i] = 0.5f * x * (1.0f + erff(x * 0.70710678118654752f));
                }
    }

    if (EPI == 1) {
        constexpr int SS = WN + 4;
        float* stage = (float*)sm + wid * (32 * SS);
        #pragma unroll
        for (int mi = 0; mi < 2; mi++)
            #pragma unroll
            for (int nj = 0; nj < NJ; nj++)
                wmma::store_matrix_sync(stage + mi * 16 * SS + nj * 16, acc[mi][nj], SS, wmma::mem_row_major);
        __syncwarp();
        int lane = tid & 31;
        constexpr int QN = WN / 4;
        #pragma unroll
        for (int it = 0; it < QN; it++) {
            int j = it * 32 + lane;
            int r = j / QN, c4 = j % QN;
            float4 v = *reinterpret_cast<const float4*>(stage + r * SS + c4 * 4);
            size_t go = (size_t)(m0 + wm * 32 + r) * ldc + ccol0 + wn * WN + c4 * 4;
            *reinterpret_cast<uint2*>(Cf16 + go) = f4_to_h4(v);
        }
    } else {
        // EPI==2 (BN=128): fused residual + LayerNorm on complete rows.
        float* stageF = (float*)sm;   // 128 x 132 fp32 = 67584 B
        #pragma unroll
        for (int mi = 0; mi < 2; mi++)
            #pragma unroll
            for (int nj = 0; nj < NJ; nj++)
                wmma::store_matrix_sync(stageF + (wm * 32 + mi * 16) * 132 + wn * WN + nj * 16,
                                        acc[mi][nj], 132, wmma::mem_row_major);
        __syncthreads();
        int lane = tid & 31;
        float4 gg = reinterpret_cast<const float4*>(lng)[lane];
        float4 bb = reinterpret_cast<const float4*>(lnb)[lane];
        #pragma unroll
        for (int rr = 0; rr < 16; rr++) {
            int r = wid * 16 + rr;
            int row = m0 + r;
            if (row >= NN) continue;
            float4 v = *reinterpret_cast<const float4*>(stageF + r * 132 + lane * 4);
            float4 rv = reinterpret_cast<const float4*>(resid)[(size_t)row * 32 + lane];
            v.x += rv.x; v.y += rv.y; v.z += rv.z; v.w += rv.w;

            float s1 = v.x + v.y + v.z + v.w;
            float s2 = v.x * v.x + v.y * v.y + v.z * v.z + v.w * v.w;
            #pragma unroll
            for (int off = 16; off > 0; off >>= 1) {
                s1 += __shfl_xor_sync(0xffffffffu, s1, off);
                s2 += __shfl_xor_sync(0xffffffffu, s2, off);
            }
            float mu = s1 * (1.0f / HID);
            float var = s2 * (1.0f / HID) - mu * mu;
            float rstd = rsqrtf(var + LN_EPS);

            float4 o;
            o.x = (v.x - mu) * rstd * gg.x + bb.x;
            o.y = (v.y - mu) * rstd * gg.y + bb.y;
            o.z = (v.z - mu) * rstd * gg.z + bb.z;
            o.w = (v.w - mu) * rstd * gg.w + bb.w;
            reinterpret_cast<float4*>(outp)[(size_t)row * 32 + lane] = o;
        }
    }
}

__global__ __launch_bounds__(256, 3) void gemm_srcdst(
    const hf* __restrict__ h_f16,
    const hf* __restrict__ Ws, const float* __restrict__ bsrc,
    const hf* __restrict__ Wd, const float* __restrict__ bdst,
    hf* __restrict__ fs, hf* __restrict__ fd)
{
    int m0 = blockIdx.x * 128;
    int y = blockIdx.y;
    int col0 = (y & 1) * 64;
    if (y < 2)
        gemm_core<128, 64, false, 1>(h_f16, 128, Ws, 128, bsrc,
                                     fs, 128, col0, m0,
                                     nullptr, nullptr, nullptr, nullptr);
    else
        gemm_core<128, 64, false, 1>(h_f16, 128, Wd, 128, bdst,
                                     fd, 128, col0, m0,
                                     nullptr, nullptr, nullptr, nullptr);
}

__global__ __launch_bounds__(256, 3) void gemm_ffn1(
    const hf* __restrict__ h1_f16,
    const hf* __restrict__ W1, const float* __restrict__ bf1,
    hf* __restrict__ t_f16)
{
    gemm_core<128, 64, true, 1>(h1_f16, 128, W1, 256, bf1,
                                t_f16, 256, blockIdx.y * 64, blockIdx.x * 128,
                                nullptr, nullptr, nullptr, nullptr);
}

__global__ __launch_bounds__(256, 3) void gemm_ffn2_ln(
    const hf* __restrict__ t_f16,
    const hf* __restrict__ W2, const float* __restrict__ bf2,
    const float* __restrict__ h1, const float* __restrict__ g2,
    const float* __restrict__ be2, float* __restrict__ out)
{
    gemm_core<256, 128, false, 2>(t_f16, 256, W2, 128, bf2,
                                  nullptr, 128, 0, blockIdx.x * 128,
                                  h1, g2, be2, out);
}

// ---------------- edge logit helper ----------------
__device__ __forceinline__ float edge_logit(float4 vs, float4 vd, float4 va) {
    float x, sum = 0.0f;
    x = vs.x + vd.x; x = (x > 0.f) ? x : NEG_SLOPE * x; sum += x * va.x;
    x = vs.y + vd.y; x = (x > 0.f) ? x : NEG_SLOPE * x; sum += x * va.y;
    x = vs.z + vd.z; x = (x > 0.f) ? x : NEG_SLOPE * x; sum += x * va.z;
    x = vs.w + vd.w; x = (x > 0.f) ? x : NEG_SLOPE * x; sum += x * va.w;
    sum += __shfl_xor_sync(0xffffffffu, sum, 4);
    sum += __shfl_xor_sync(0xffffffffu, sum, 2);
    sum += __shfl_xor_sync(0xffffffffu, sum, 1);
    return sum;
}

// ---------------- fused edge aggregation + LN1 (fp16 gathers, fp32 math) ----
__global__ __launch_bounds__(256) void edge_agg_ln(
    const hf* __restrict__ fs, const hf* __restrict__ fd,
    const int* __restrict__ eoff, const int* __restrict__ ecnt,
    const int* __restrict__ esrc, const float* __restrict__ attn,
    const float* __restrict__ resid,
    const float* __restrict__ g, const float* __restrict__ b,
    float* __restrict__ out, hf* __restrict__ out_f16)
{
    int d = blockIdx.x * 8 + (threadIdx.x >> 5);
    if (d >= NN) return;
    int lane = threadIdx.x & 31;

    const uint2* fsp = reinterpret_cast<const uint2*>(fs);
    float4 va = reinterpret_cast<const float4*>(attn)[lane];
    float4 vd = h4_to_f4(reinterpret_cast<const uint2*>(fd)[(size_t)d * 32 + lane]);

    int i = eoff[d];
    int end = i + ecnt[d];

    float4 acc = make_float4(0.f, 0.f, 0.f, 0.f);
    float den = 0.0f;

    for (; i + 3 < end; i += 4) {
        int s0 = __ldg(esrc + i);
        int s1 = __ldg(esrc + i + 1);
        int s2 = __ldg(esrc + i + 2);
        int s3 = __ldg(esrc + i + 3);
        float4 v0 = h4_to_f4(fsp[(size_t)s0 * 32 + lane]);
        float4 v1 = h4_to_f4(fsp[(size_t)s1 * 32 + lane]);
        float4 v2 = h4_to_f4(fsp[(size_t)s2 * 32 + lane]);
        float4 v3 = h4_to_f4(fsp[(size_t)s3 * 32 + lane]);
        float a0 = __expf(edge_logit(v0, vd, va));
        float a1 = __expf(edge_logit(v1, vd, va));
        float a2 = __expf(edge_logit(v2, vd, va));
        float a3 = __expf(edge_logit(v3, vd, va));
        acc.x += v0.x * a0 + v1.x * a1 + v2.x * a2 + v3.x * a3;
        acc.y += v0.y * a0 + v1.y * a1 + v2.y * a2 + v3.y * a3;
        acc.z += v0.z * a0 + v1.z * a1 + v2.z * a2 + v3.z * a3;
        acc.w += v0.w * a0 + v1.w * a1 + v2.w * a2 + v3.w * a3;
        den += a0 + a1 + a2 + a3;
    }
    for (; i < end; i++) {
        int s = __ldg(esrc + i);
        float4 vs = h4_to_f4(fsp[(size_t)s * 32 + lane]);
        float a = __expf(edge_logit(vs, vd, va));
        acc.x += vs.x * a; acc.y += vs.y * a;
        acc.z += vs.z * a; acc.w += vs.w * a;
        den += a;
    }

    den = (den == 0.0f) ? 1.0f : den;
    float inv = 1.0f / den;
    float4 rv = reinterpret_cast<const float4*>(resid)[(size_t)d * 32 + lane];
    float4 v;
    v.x = acc.x * inv + rv.x; v.y = acc.y * inv + rv.y;
    v.z = acc.z * inv + rv.z; v.w = acc.w * inv + rv.w;

    float s1 = v.x + v.y + v.z + v.w;
    float s2 = v.x * v.x + v.y * v.y + v.z * v.z + v.w * v.w;
    #pragma unroll
    for (int off = 16; off > 0; off >>= 1) {
        s1 += __shfl_xor_sync(0xffffffffu, s1, off);
        s2 += __shfl_xor_sync(0xffffffffu, s2, off);
    }
    float mu = s1 * (1.0f / HID);
    float var = s2 * (1.0f / HID) - mu * mu;
    float rstd = rsqrtf(var + LN_EPS);

    float4 gg = reinterpret_cast<const float4*>(g)[lane];
    float4 bb = reinterpret_cast<const float4*>(b)[lane];
    float4 o;
    o.x = (v.x - mu) * rstd * gg.x + bb.x;
    o.y = (v.y - mu) * rstd * gg.y + bb.y;
    o.z = (v.z - mu) * rstd * gg.z + bb.z;
    o.w = (v.w - mu) * rstd * gg.w + bb.w;
    reinterpret_cast<float4*>(out)[(size_t)d * 32 + lane] = o;
    reinterpret_cast<uint2*>(out_f16)[(size_t)d * 32 + lane] = f4_to_h4(o);
}

// ---------------- launcher ----------------
extern "C" void kernel_launch(void* const* d_in, const int* in_sizes, int n_in,
                              void* d_out, int out_size)
{
    const float* h    = (const float*)d_in[0];
    const int*   src  = (const int*)  d_in[1];
    const int*   dst  = (const int*)  d_in[2];
    const float* Wsrc = (const float*)d_in[3];
    const float* bsrc = (const float*)d_in[4];
    const float* Wdst = (const float*)d_in[5];
    const float* bdst = (const float*)d_in[6];
    const float* attn = (const float*)d_in[7];
    const float* W1   = (const float*)d_in[8];
    const float* bf1  = (const float*)d_in[9];
    const float* W2   = (const float*)d_in[10];
    const float* bf2  = (const float*)d_in[11];
    const float* g1   = (const float*)d_in[12];
    const float* be1  = (const float*)d_in[13];
    const float* g2   = (const float*)d_in[14];
    const float* be2  = (const float*)d_in[15];
    float* out = (float*)d_out;

    float *h1;
    int *ecnt, *eoff, *cursor, *bsum, *esrc;
    hf *fs, *fd, *h_f16, *h1_f16, *t_f16, *Ws, *Wd, *W1h, *W2h;
    cudaGetSymbolAddress((void**)&h1,    g_h1);
    cudaGetSymbolAddress((void**)&ecnt,  g_ecnt);
    cudaGetSymbolAddress((void**)&eoff,  g_eoff);
    cudaGetSymbolAddress((void**)&cursor,g_cursor);
    cudaGetSymbolAddress((void**)&bsum,  g_bsum);
    cudaGetSymbolAddress((void**)&esrc,  g_esrc);
    cudaGetSymbolAddress((void**)&fs,    g_fs);
    cudaGetSymbolAddress((void**)&fd,    g_fd);
    cudaGetSymbolAddress((void**)&h_f16, g_h_f16);
    cudaGetSymbolAddress((void**)&h1_f16,g_h1_f16);
    cudaGetSymbolAddress((void**)&t_f16, g_t_f16);
    cudaGetSymbolAddress((void**)&Ws,    g_Ws);
    cudaGetSymbolAddress((void**)&Wd,    g_Wd);
    cudaGetSymbolAddress((void**)&W1h,   g_W1);
    cudaGetSymbolAddress((void**)&W2h,   g_W2);

    const int SM64 = SMB(64);    // 37888
    cudaFuncSetAttribute(gemm_srcdst,  cudaFuncAttributeMaxDynamicSharedMemorySize, SM64);
    cudaFuncSetAttribute(gemm_ffn1,    cudaFuncAttributeMaxDynamicSharedMemorySize, SM64);
    cudaFuncSetAttribute(gemm_ffn2_ln, cudaFuncAttributeMaxDynamicSharedMemorySize, SM_FFN2);

    static cudaStream_t s_side = nullptr;
    static cudaEvent_t ev_fork = nullptr, ev_join = nullptr;
    if (s_side == nullptr) {
        cudaStreamCreateWithFlags(&s_side, cudaStreamNonBlocking);
        cudaEventCreateWithFlags(&ev_fork, cudaEventDisableTiming);
        cudaEventCreateWithFlags(&ev_join, cudaEventDisableTiming);
    }

    const int GXM = NPAD / 128;   // 391
    const int NB = (NN + 511) / 512;

    cudaMemsetAsync(ecnt, 0, NN * sizeof(int));
    prep_kernel<<<PREP_TOTAL_B, 256>>>(dst, ecnt, h, h_f16,
                                       Wsrc, Wdst, W1, W2,
                                       Ws, Wd, W1h, W2h, h1_f16);

    // fork: CSR chain concurrent with gemm_srcdst
    cudaEventRecord(ev_fork, 0);
    cudaStreamWaitEvent(s_side, ev_fork, 0);
    scan1<<<NB, 512, 0, s_side>>>(ecnt, eoff, bsum);
    scan2<<<1, 128, 0, s_side>>>(bsum, NB);
    scan3<<<NB, 512, 0, s_side>>>(eoff, bsum, cursor);
    scatter_kernel<<<(EE + 255) / 256, 256, 0, s_side>>>(src, dst, cursor, esrc);
    cudaEventRecord(ev_join, s_side);

    gemm_srcdst<<<dim3(GXM, 4), 256, SM64>>>(h_f16, Ws, bsrc, Wd, bdst, fs, fd);

    cudaStreamWaitEvent(0, ev_join, 0);

    edge_agg_ln<<<(NN + 7) / 8, 256>>>(fs, fd, eoff, ecnt, esrc, attn,
                                       h, g1, be1, h1, h1_f16);

    gemm_ffn1<<<dim3(GXM, 4), 256, SM64>>>(h1_f16, W1h, bf1, t_f16);
    gemm_ffn2_ln<<<dim3(GXM, 1), 256, SM_FFN2>>>(t_f16, W2h, bf2, h1, g2, be2, out);
}

// round 14
// speedup vs baseline: 3.2711x; 1.0753x over previous
#include <cuda_runtime.h>
#include <cuda_fp16.h>
#include <mma.h>
#include <math.h>

using namespace nvcuda;
typedef __half hf;

// ---------------- problem constants ----------------
#define NN 50000
#define NPAD 50048            // 391 * 128
#define EE 600000
#define HID 128
#define NEG_SLOPE 0.2f
#define LN_EPS 1e-5f

// GEMM: BM=128, BN=128, BK=64, 2-stage cp.async, warp tile 32x64 (ratio 1.33)
#define LDA_SM 72             // 64 + 8 halves
#define LDB_SM 136            // 128 + 8 halves
#define A_ST (128 * LDA_SM)   // 9216 halves per stage
#define B_ST (64 * LDB_SM)    // 8704 halves per stage
#define SM_GEMM ((2 * A_ST + 2 * B_ST) * 2 + 16 * 128 * 4)   // 71680 + 8192 = 79872

// prep kernel block partition
#define PREP_HIST_B ((EE + 255) / 256)
#define PREP_SPH_B  ((NPAD * 32 + 255) / 256)
#define PREP_SPW_B  ((24576 + (NPAD - NN) * 32 + 255) / 256)
#define PREP_TOTAL_B (PREP_HIST_B + PREP_SPH_B + PREP_SPW_B)

// ---------------- scratch ----------------
__device__ float g_h1[NPAD * HID];
// CSR scratch
__device__ int g_ecnt[NN];
__device__ int g_eoff[NN];
__device__ int g_cursor[NN];
__device__ int g_bsum[128];
__device__ int g_esrc[EE];
// fp16 tensors
__device__ hf g_fs[NPAD * HID];
__device__ hf g_fd[NPAD * HID];
__device__ hf g_h_f16[NPAD * HID];
__device__ hf g_h1_f16[NPAD * HID];
__device__ hf g_t_f16[NPAD * 2 * HID];
__device__ hf g_Ws[HID * HID];
__device__ hf g_Wd[HID * HID];
__device__ hf g_W1[HID * 2 * HID];
__device__ hf g_W2[2 * HID * HID];

// ---------------- cp.async helpers ----------------
__device__ __forceinline__ void cp16(void* smem, const void* gmem) {
    unsigned saddr = (unsigned)__cvta_generic_to_shared(smem);
    asm volatile("cp.async.cg.shared.global [%0], [%1], 16;" :: "r"(saddr), "l"(gmem));
}
__device__ __forceinline__ void cp_commit() {
    asm volatile("cp.async.commit_group;" ::: "memory");
}
template <int N>
__device__ __forceinline__ void cp_wait() {
    asm volatile("cp.async.wait_group %0;" :: "n"(N) : "memory");
}

// ---------------- conversion helpers ----------------
__device__ __forceinline__ uint2 f4_to_h4(float4 v) {
    __half2 p0 = __floats2half2_rn(v.x, v.y);
    __half2 p1 = __floats2half2_rn(v.z, v.w);
    uint2 u;
    u.x = *reinterpret_cast<unsigned*>(&p0);
    u.y = *reinterpret_cast<unsigned*>(&p1);
    return u;
}
__device__ __forceinline__ float4 h4_to_f4(uint2 u) {
    __half2 p0 = *reinterpret_cast<__half2*>(&u.x);
    __half2 p1 = *reinterpret_cast<__half2*>(&u.y);
    float2 a = __half22float2(p0);
    float2 b = __half22float2(p1);
    return make_float4(a.x, a.y, b.x, b.y);
}

// ---------------- merged prep ----------------
__global__ void prep_kernel(
    const int* __restrict__ dst, int* __restrict__ cnt,
    const float* __restrict__ h, hf* __restrict__ h_f16,
    const float* __restrict__ Ws, const float* __restrict__ Wd,
    const float* __restrict__ W1, const float* __restrict__ W2,
    hf* __restrict__ Wsh, hf* __restrict__ Wdh,
    hf* __restrict__ W1h, hf* __restrict__ W2h,
    hf* __restrict__ h1_f16)
{
    int b = blockIdx.x;
    if (b < PREP_HIST_B) {
        int e = b * 256 + threadIdx.x;
        if (e < EE) atomicAdd(&cnt[dst[e]], 1);
        return;
    }
    b -= PREP_HIST_B;
    if (b < PREP_SPH_B) {
        int i = b * 256 + threadIdx.x;
        if (i >= NPAD * 32) return;
        int row = i >> 5;
        float4 v = make_float4(0.f, 0.f, 0.f, 0.f);
        if (row < NN) v = reinterpret_cast<const float4*>(h)[i];
        reinterpret_cast<uint2*>(h_f16)[i] = f4_to_h4(v);
        return;
    }
    b -= PREP_SPH_B;
    {
        int i = b * 256 + threadIdx.x;
        if (i >= 24576 + (NPAD - NN) * 32) return;
        if (i >= 24576) {
            int j = i - 24576;
            reinterpret_cast<uint2*>(h1_f16 + (size_t)NN * HID)[j] = make_uint2(0u, 0u);
            return;
        }
        const float* s; hf* p; int j = i;
        if (j < 4096)        { s = Ws; p = Wsh; }
        else if (j < 8192)   { j -= 4096;  s = Wd; p = Wdh; }
        else if (j < 16384)  { j -= 8192;  s = W1; p = W1h; }
        else                 { j -= 16384; s = W2; p = W2h; }
        float4 v = reinterpret_cast<const float4*>(s)[j];
        reinterpret_cast<uint2*>(p)[j] = f4_to_h4(v);
    }
}

// ---------------- CSR scan/scatter ----------------
__global__ void scan1(const int* __restrict__ cnt, int* __restrict__ excl,
                      int* __restrict__ bsum) {
    __shared__ int sh[512];
    int i = blockIdx.x * 512 + threadIdx.x;
    int v = (i < NN) ? cnt[i] : 0;
    sh[threadIdx.x] = v;
    __syncthreads();
    #pragma unroll
    for (int off = 1; off < 512; off <<= 1) {
        int t = (threadIdx.x >= off) ? sh[threadIdx.x - off] : 0;
        __syncthreads();
        sh[threadIdx.x] += t;
        __syncthreads();
    }
    if (i < NN) excl[i] = sh[threadIdx.x] - v;
    if (threadIdx.x == 511) bsum[blockIdx.x] = sh[511];
}

__global__ void scan2(int* __restrict__ bsum, int nb) {
    __shared__ int sh[128];
    int v = (threadIdx.x < nb) ? bsum[threadIdx.x] : 0;
    sh[threadIdx.x] = v;
    __syncthreads();
    #pragma unroll
    for (int off = 1; off < 128; off <<= 1) {
        int t = (threadIdx.x >= off) ? sh[threadIdx.x - off] : 0;
        __syncthreads();
        sh[threadIdx.x] += t;
        __syncthreads();
    }
    if (threadIdx.x < nb) bsum[threadIdx.x] = sh[threadIdx.x] - v;
}

__global__ void scan3(int* __restrict__ excl, const int* __restrict__ bsum,
                      int* __restrict__ cursor) {
    int i = blockIdx.x * 512 + threadIdx.x;
    if (i < NN) {
        int v = excl[i] + bsum[blockIdx.x];
        excl[i] = v;
        cursor[i] = v;
    }
}

__global__ void scatter_kernel(const int* __restrict__ src, const int* __restrict__ dst,
                               int* __restrict__ cursor, int* __restrict__ esrc) {
    int e = blockIdx.x * blockDim.x + threadIdx.x;
    if (e >= EE) return;
    int pos = atomicAdd(&cursor[dst[e]], 1);
    esrc[pos] = src[e];
}

// ---------------- WMMA pure-fp16 GEMM core: 128x128 tile, BK=64 ----------------
// 8 warps as 4(m) x 2(n); warp tile 32 rows x 64 cols -> acc[2][4].
// EPI: 1 = fp16 store (+optional gelu), 2 = fused residual+LayerNorm.
template <int KTOT, bool GELU, int EPI>
__device__ __forceinline__ void gemm_core(
    const hf* __restrict__ A_g, int lda,
    const hf* __restrict__ B_g, int ldb,
    const float* __restrict__ bias,
    hf* __restrict__ Cf16,
    int ldc, int ccol0, int m0,
    const float* __restrict__ resid, const float* __restrict__ lng,
    const float* __restrict__ lnb, float* __restrict__ outp)
{
    extern __shared__ hf sm[];
    hf* AS[2] = { sm,            sm + A_ST };
    hf* BS[2] = { sm + 2 * A_ST, sm + 2 * A_ST + B_ST };
    float* bias_sm = (float*)(sm + 2 * A_ST + 2 * B_ST);   // [16][128]

    const int tid = threadIdx.x;
    const int wid = tid >> 5;
    const int wm = wid & 3;           // 0..3 -> 32 rows each
    const int wn = wid >> 2;          // 0..1 -> 64 cols each

    constexpr int KC = KTOT / 64;

    auto load_stage = [&](int kc, int st) {
        #pragma unroll
        for (int i = tid; i < 1024; i += 256) {    // A: 128 x 64 halves
            int r = i >> 3, c8 = (i & 7) * 8;
            size_t go = (size_t)(m0 + r) * lda + kc * 64 + c8;
            cp16(AS[st] + r * LDA_SM + c8, A_g + go);
        }
        #pragma unroll
        for (int i = tid; i < 1024; i += 256) {    // B: 64 x 128 halves
            int r = i >> 4, c8 = (i & 15) * 8;
            size_t go = (size_t)(kc * 64 + r) * ldb + ccol0 + c8;
            cp16(BS[st] + r * LDB_SM + c8, B_g + go);
        }
        cp_commit();
    };

    load_stage(0, 0);

    for (int i = tid; i < 16 * 128; i += 256)
        bias_sm[i] = bias[ccol0 + (i & 127)];
    __syncthreads();

    wmma::fragment<wmma::accumulator, 16, 16, 16, float> acc[2][4];
    #pragma unroll
    for (int mi = 0; mi < 2; mi++)
        #pragma unroll
        for (int nj = 0; nj < 4; nj++)
            wmma::load_matrix_sync(acc[mi][nj], bias_sm + wn * 64 + nj * 16, 128, wmma::mem_row_major);

    #pragma unroll
    for (int kc = 0; kc < KC; kc++) {
        if (kc + 1 < KC) load_stage(kc + 1, (kc + 1) & 1);
        if (kc + 1 < KC) cp_wait<1>(); else cp_wait<0>();
        __syncthreads();

        const int st = kc & 1;
        #pragma unroll
        for (int kk = 0; kk < 4; kk++) {
            wmma::fragment<wmma::matrix_a, 16, 16, 16, hf, wmma::row_major> a[2];
            wmma::fragment<wmma::matrix_b, 16, 16, 16, hf, wmma::row_major> bfr[4];
            #pragma unroll
            for (int mi = 0; mi < 2; mi++)
                wmma::load_matrix_sync(a[mi], AS[st] + (wm * 32 + mi * 16) * LDA_SM + kk * 16, LDA_SM);
            #pragma unroll
            for (int nj = 0; nj < 4; nj++)
                wmma::load_matrix_sync(bfr[nj], BS[st] + (kk * 16) * LDB_SM + wn * 64 + nj * 16, LDB_SM);
            #pragma unroll
            for (int mi = 0; mi < 2; mi++)
                #pragma unroll
                for (int nj = 0; nj < 4; nj++)
                    wmma::mma_sync(acc[mi][nj], a[mi], bfr[nj], acc[mi][nj]);
        }
        __syncthreads();
    }

    if (GELU) {
        #pragma unroll
        for (int mi = 0; mi < 2; mi++)
            #pragma unroll
            for (int nj = 0; nj < 4; nj++)
                #pragma unroll
                for (int i = 0; i < acc[mi][nj].num_elements; i++) {
                    float x = acc[mi][nj].x[i];
                    acc[mi][nj].x[i] = 0.5f * x * (1.0f + erff(x * 0.70710678118654752f));
                }
    }

    if (EPI == 1) {
        // per-warp staging: 32 x 68 fp32 = 8704 B x 8 warps = 69632 <= 71680
        float* stage = (float*)sm + wid * (32 * 68);
        #pragma unroll
        for (int mi = 0; mi < 2; mi++)
            #pragma unroll
            for (int nj = 0; nj < 4; nj++)
                wmma::store_matrix_sync(stage + mi * 16 * 68 + nj * 16, acc[mi][nj], 68, wmma::mem_row_major);
        __syncwarp();
        int lane = tid & 31;
        #pragma unroll
        for (int it = 0; it < 16; it++) {
            int j = it * 32 + lane;         // 512 items: 32 rows x 16 quads
            int r = j >> 4, c4 = j & 15;
            float4 v = *reinterpret_cast<const float4*>(stage + r * 68 + c4 * 4);
            size_t go = (size_t)(m0 + wm * 32 + r) * ldc + ccol0 + wn * 64 + c4 * 4;
            *reinterpret_cast<uint2*>(Cf16 + go) = f4_to_h4(v);
        }
    } else {
        // EPI==2: fused residual + LayerNorm on complete 128-wide rows
        float* stageF = (float*)sm;   // 128 x 132 fp32 = 67584 <= 71680
        #pragma unroll
        for (int mi = 0; mi < 2; mi++)
            #pragma unroll
            for (int nj = 0; nj < 4; nj++)
                wmma::store_matrix_sync(stageF + (wm * 32 + mi * 16) * 132 + wn * 64 + nj * 16,
                                        acc[mi][nj], 132, wmma::mem_row_major);
        __syncthreads();
        int lane = tid & 31;
        float4 gg = reinterpret_cast<const float4*>(lng)[lane];
        float4 bb = reinterpret_cast<const float4*>(lnb)[lane];
        #pragma unroll
        for (int rr = 0; rr < 16; rr++) {
            int r = wid * 16 + rr;
            int row = m0 + r;
            if (row >= NN) continue;
            float4 v = *reinterpret_cast<const float4*>(stageF + r * 132 + lane * 4);
            float4 rv = reinterpret_cast<const float4*>(resid)[(size_t)row * 32 + lane];
            v.x += rv.x; v.y += rv.y; v.z += rv.z; v.w += rv.w;

            float s1 = v.x + v.y + v.z + v.w;
            float s2 = v.x * v.x + v.y * v.y + v.z * v.z + v.w * v.w;
            #pragma unroll
            for (int off = 16; off > 0; off >>= 1) {
                s1 += __shfl_xor_sync(0xffffffffu, s1, off);
                s2 += __shfl_xor_sync(0xffffffffu, s2, off);
            }
            float mu = s1 * (1.0f / HID);
            float var = s2 * (1.0f / HID) - mu * mu;
            float rstd = rsqrtf(var + LN_EPS);

            float4 o;
            o.x = (v.x - mu) * rstd * gg.x + bb.x;
            o.y = (v.y - mu) * rstd * gg.y + bb.y;
            o.z = (v.z - mu) * rstd * gg.z + bb.z;
            o.w = (v.w - mu) * rstd * gg.w + bb.w;
            reinterpret_cast<float4*>(outp)[(size_t)row * 32 + lane] = o;
        }
    }
}

__global__ __launch_bounds__(256, 2) void gemm_srcdst(
    const hf* __restrict__ h_f16,
    const hf* __restrict__ Ws, const float* __restrict__ bsrc,
    const hf* __restrict__ Wd, const float* __restrict__ bdst,
    hf* __restrict__ fs, hf* __restrict__ fd)
{
    int m0 = blockIdx.x * 128;
    if (blockIdx.y == 0)
        gemm_core<128, false, 1>(h_f16, 128, Ws, 128, bsrc, fs, 128, 0, m0,
                                 nullptr, nullptr, nullptr, nullptr);
    else
        gemm_core<128, false, 1>(h_f16, 128, Wd, 128, bdst, fd, 128, 0, m0,
                                 nullptr, nullptr, nullptr, nullptr);
}

__global__ __launch_bounds__(256, 2) void gemm_ffn1(
    const hf* __restrict__ h1_f16,
    const hf* __restrict__ W1, const float* __restrict__ bf1,
    hf* __restrict__ t_f16)
{
    gemm_core<128, true, 1>(h1_f16, 128, W1, 256, bf1,
                            t_f16, 256, blockIdx.y * 128, blockIdx.x * 128,
                            nullptr, nullptr, nullptr, nullptr);
}

__global__ __launch_bounds__(256, 2) void gemm_ffn2_ln(
    const hf* __restrict__ t_f16,
    const hf* __restrict__ W2, const float* __restrict__ bf2,
    const float* __restrict__ h1, const float* __restrict__ g2,
    const float* __restrict__ be2, float* __restrict__ out)
{
    gemm_core<256, false, 2>(t_f16, 256, W2, 128, bf2,
                             nullptr, 128, 0, blockIdx.x * 128,
                             h1, g2, be2, out);
}

// ---------------- edge logit helper ----------------
__device__ __forceinline__ float edge_logit(float4 vs, float4 vd, float4 va) {
    float x, sum = 0.0f;
    x = vs.x + vd.x; x = (x > 0.f) ? x : NEG_SLOPE * x; sum += x * va.x;
    x = vs.y + vd.y; x = (x > 0.f) ? x : NEG_SLOPE * x; sum += x * va.y;
    x = vs.z + vd.z; x = (x > 0.f) ? x : NEG_SLOPE * x; sum += x * va.z;
    x = vs.w + vd.w; x = (x > 0.f) ? x : NEG_SLOPE * x; sum += x * va.w;
    sum += __shfl_xor_sync(0xffffffffu, sum, 4);
    sum += __shfl_xor_sync(0xffffffffu, sum, 2);
    sum += __shfl_xor_sync(0xffffffffu, sum, 1);
    return sum;
}

// ---------------- fused edge aggregation + LN1 (fp16 gathers, fp32 math) ----
__global__ __launch_bounds__(256) void edge_agg_ln(
    const hf* __restrict__ fs, const hf* __restrict__ fd,
    const int* __restrict__ eoff, const int* __restrict__ ecnt,
    const int* __restrict__ esrc, const float* __restrict__ attn,
    const float* __restrict__ resid,
    const float* __restrict__ g, const float* __restrict__ b,
    float* __restrict__ out, hf* __restrict__ out_f16)
{
    int d = blockIdx.x * 8 + (threadIdx.x >> 5);
    if (d >= NN) return;
    int lane = threadIdx.x & 31;

    const uint2* fsp = reinterpret_cast<const uint2*>(fs);
    float4 va = reinterpret_cast<const float4*>(attn)[lane];
    float4 vd = h4_to_f4(reinterpret_cast<const uint2*>(fd)[(size_t)d * 32 + lane]);

    int i = eoff[d];
    int end = i + ecnt[d];

    float4 acc = make_float4(0.f, 0.f, 0.f, 0.f);
    float den = 0.0f;

    for (; i + 3 < end; i += 4) {
        int s0 = __ldg(esrc + i);
        int s1 = __ldg(esrc + i + 1);
        int s2 = __ldg(esrc + i + 2);
        int s3 = __ldg(esrc + i + 3);
        float4 v0 = h4_to_f4(fsp[(size_t)s0 * 32 + lane]);
        float4 v1 = h4_to_f4(fsp[(size_t)s1 * 32 + lane]);
        float4 v2 = h4_to_f4(fsp[(size_t)s2 * 32 + lane]);
        float4 v3 = h4_to_f4(fsp[(size_t)s3 * 32 + lane]);
        float a0 = __expf(edge_logit(v0, vd, va));
        float a1 = __expf(edge_logit(v1, vd, va));
        float a2 = __expf(edge_logit(v2, vd, va));
        float a3 = __expf(edge_logit(v3, vd, va));
        acc.x += v0.x * a0 + v1.x * a1 + v2.x * a2 + v3.x * a3;
        acc.y += v0.y * a0 + v1.y * a1 + v2.y * a2 + v3.y * a3;
        acc.z += v0.z * a0 + v1.z * a1 + v2.z * a2 + v3.z * a3;
        acc.w += v0.w * a0 + v1.w * a1 + v2.w * a2 + v3.w * a3;
        den += a0 + a1 + a2 + a3;
    }
    for (; i < end; i++) {
        int s = __ldg(esrc + i);
        float4 vs = h4_to_f4(fsp[(size_t)s * 32 + lane]);
        float a = __expf(edge_logit(vs, vd, va));
        acc.x += vs.x * a; acc.y += vs.y * a;
        acc.z += vs.z * a; acc.w += vs.w * a;
        den += a;
    }

    den = (den == 0.0f) ? 1.0f : den;
    float inv = 1.0f / den;
    float4 rv = reinterpret_cast<const float4*>(resid)[(size_t)d * 32 + lane];
    float4 v;
    v.x = acc.x * inv + rv.x; v.y = acc.y * inv + rv.y;
    v.z = acc.z * inv + rv.z; v.w = acc.w * inv + rv.w;

    float s1 = v.x + v.y + v.z + v.w;
    float s2 = v.x * v.x + v.y * v.y + v.z * v.z + v.w * v.w;
    #pragma unroll
    for (int off = 16; off > 0; off >>= 1) {
        s1 += __shfl_xor_sync(0xffffffffu, s1, off);
        s2 += __shfl_xor_sync(0xffffffffu, s2, off);
    }
    float mu = s1 * (1.0f / HID);
    float var = s2 * (1.0f / HID) - mu * mu;
    float rstd = rsqrtf(var + LN_EPS);

    float4 gg = reinterpret_cast<const float4*>(g)[lane];
    float4 bb = reinterpret_cast<const float4*>(b)[lane];
    float4 o;
    o.x = (v.x - mu) * rstd * gg.x + bb.x;
    o.y = (v.y - mu) * rstd * gg.y + bb.y;
    o.z = (v.z - mu) * rstd * gg.z + bb.z;
    o.w = (v.w - mu) * rstd * gg.w + bb.w;
    reinterpret_cast<float4*>(out)[(size_t)d * 32 + lane] = o;
    reinterpret_cast<uint2*>(out_f16)[(size_t)d * 32 + lane] = f4_to_h4(o);
}

// ---------------- launcher ----------------
extern "C" void kernel_launch(void* const* d_in, const int* in_sizes, int n_in,
                              void* d_out, int out_size)
{
    const float* h    = (const float*)d_in[0];
    const int*   src  = (const int*)  d_in[1];
    const int*   dst  = (const int*)  d_in[2];
    const float* Wsrc = (const float*)d_in[3];
    const float* bsrc = (const float*)d_in[4];
    const float* Wdst = (const float*)d_in[5];
    const float* bdst = (const float*)d_in[6];
    const float* attn = (const float*)d_in[7];
    const float* W1   = (const float*)d_in[8];
    const float* bf1  = (const float*)d_in[9];
    const float* W2   = (const float*)d_in[10];
    const float* bf2  = (const float*)d_in[11];
    const float* g1   = (const float*)d_in[12];
    const float* be1  = (const float*)d_in[13];
    const float* g2   = (const float*)d_in[14];
    const float* be2  = (const float*)d_in[15];
    float* out = (float*)d_out;

    float *h1;
    int *ecnt, *eoff, *cursor, *bsum, *esrc;
    hf *fs, *fd, *h_f16, *h1_f16, *t_f16, *Ws, *Wd, *W1h, *W2h;
    cudaGetSymbolAddress((void**)&h1,    g_h1);
    cudaGetSymbolAddress((void**)&ecnt,  g_ecnt);
    cudaGetSymbolAddress((void**)&eoff,  g_eoff);
    cudaGetSymbolAddress((void**)&cursor,g_cursor);
    cudaGetSymbolAddress((void**)&bsum,  g_bsum);
    cudaGetSymbolAddress((void**)&esrc,  g_esrc);
    cudaGetSymbolAddress((void**)&fs,    g_fs);
    cudaGetSymbolAddress((void**)&fd,    g_fd);
    cudaGetSymbolAddress((void**)&h_f16, g_h_f16);
    cudaGetSymbolAddress((void**)&h1_f16,g_h1_f16);
    cudaGetSymbolAddress((void**)&t_f16, g_t_f16);
    cudaGetSymbolAddress((void**)&Ws,    g_Ws);
    cudaGetSymbolAddress((void**)&Wd,    g_Wd);
    cudaGetSymbolAddress((void**)&W1h,   g_W1);
    cudaGetSymbolAddress((void**)&W2h,   g_W2);

    cudaFuncSetAttribute(gemm_srcdst,  cudaFuncAttributeMaxDynamicSharedMemorySize, SM_GEMM);
    cudaFuncSetAttribute(gemm_ffn1,    cudaFuncAttributeMaxDynamicSharedMemorySize, SM_GEMM);
    cudaFuncSetAttribute(gemm_ffn2_ln, cudaFuncAttributeMaxDynamicSharedMemorySize, SM_GEMM);

    static cudaStream_t s_side = nullptr;
    static cudaEvent_t ev_fork = nullptr, ev_join = nullptr;
    if (s_side == nullptr) {
        cudaStreamCreateWithFlags(&s_side, cudaStreamNonBlocking);
        cudaEventCreateWithFlags(&ev_fork, cudaEventDisableTiming);
        cudaEventCreateWithFlags(&ev_join, cudaEventDisableTiming);
    }

    const int GXM = NPAD / 128;   // 391
    const int NB = (NN + 511) / 512;

    cudaMemsetAsync(ecnt, 0, NN * sizeof(int));
    prep_kernel<<<PREP_TOTAL_B, 256>>>(dst, ecnt, h, h_f16,
                                       Wsrc, Wdst, W1, W2,
                                       Ws, Wd, W1h, W2h, h1_f16);

    // fork: CSR chain concurrent with gemm_srcdst
    cudaEventRecord(ev_fork, 0);
    cudaStreamWaitEvent(s_side, ev_fork, 0);
    scan1<<<NB, 512, 0, s_side>>>(ecnt, eoff, bsum);
    scan2<<<1, 128, 0, s_side>>>(bsum, NB);
    scan3<<<NB, 512, 0, s_side>>>(eoff, bsum, cursor);
    scatter_kernel<<<(EE + 255) / 256, 256, 0, s_side>>>(src, dst, cursor, esrc);
    cudaEventRecord(ev_join, s_side);

    gemm_srcdst<<<dim3(GXM, 2), 256, SM_GEMM>>>(h_f16, Ws, bsrc, Wd, bdst, fs, fd);

    cudaStreamWaitEvent(0, ev_join, 0);

    edge_agg_ln<<<(NN + 7) / 8, 256>>>(fs, fd, eoff, ecnt, esrc, attn,
                                       h, g1, be1, h1, h1_f16);

    gemm_ffn1<<<dim3(GXM, 2), 256, SM_GEMM>>>(h1_f16, W1h, bf1, t_f16);
    gemm_ffn2_ln<<<dim3(GXM, 1), 256, SM_GEMM>>>(t_f16, W2h, bf2, h1, g2, be2, out);
}